// round 2
// baseline (speedup 1.0000x reference)
#include <cuda_runtime.h>

#define N_NODES 50000
#define N_EDGES 300000
#define BN_EPS 1e-5f

// ---------------- scratch (__device__ globals; no runtime alloc) ----------------
__device__ float    g_xl1[N_NODES * 256];
__device__ float    g_xr1[N_NODES * 256];
__device__ float    g_x4 [N_NODES * 1024];   // [mu_xl | mu_xr | ls_xl | ls_xr]
__device__ float    g_agg1[N_NODES * 256];   // conv1 aggregate, then x1 (post BN+ReLU)
__device__ float    g_agg_mu[N_NODES * 256];
__device__ float    g_agg_ls[N_NODES * 256];
__device__ float    g_alpha[N_EDGES * 2];
__device__ float    g_av   [N_EDGES * 2];
__device__ unsigned g_m1 [N_NODES * 2];
__device__ unsigned g_mmu[N_NODES * 2];
__device__ unsigned g_mls[N_NODES * 2];
__device__ float    g_den1 [N_NODES * 2];
__device__ float    g_denmu[N_NODES * 2];
__device__ float    g_denls[N_NODES * 2];
__device__ float    g_bn0[12];    // sum[5], sumsq[5]
__device__ float    g_bn1[512];   // sum[256], sumsq[256] -> then scale[256], shift[256]

// ---------------- helpers ----------------
__device__ __forceinline__ unsigned enc_f(float f) {
    unsigned u = __float_as_uint(f);
    return (u & 0x80000000u) ? ~u : (u | 0x80000000u);
}
__device__ __forceinline__ float dec_f(unsigned u) {
    unsigned v = (u & 0x80000000u) ? (u & 0x7fffffffu) : ~u;
    return __uint_as_float(v);
}
__device__ __forceinline__ void red_add_v4(float* p, float4 v) {
    asm volatile("red.global.add.v4.f32 [%0], {%1,%2,%3,%4};"
                 :: "l"(p), "f"(v.x), "f"(v.y), "f"(v.z), "f"(v.w) : "memory");
}

// ---------------- init: zero all accumulators ----------------
__global__ void k_init() {
    long long i = (long long)blockIdx.x * blockDim.x + threadIdx.x;
    long long stride = (long long)gridDim.x * blockDim.x;
    for (long long t = i; t < (long long)N_NODES * 256; t += stride) {
        g_agg1[t] = 0.f; g_agg_mu[t] = 0.f; g_agg_ls[t] = 0.f;
    }
    for (long long t = i; t < N_NODES * 2; t += stride) {
        g_m1[t] = 0u; g_mmu[t] = 0u; g_mls[t] = 0u;
        g_den1[t] = 0.f; g_denmu[t] = 0.f; g_denls[t] = 0.f;
    }
    for (long long t = i; t < 512; t += stride) g_bn1[t] = 0.f;
    if (i < 12) g_bn0[i] = 0.f;
}

// ---------------- BN0 statistics (5 channels) ----------------
__global__ void k_bn0_reduce(const float* __restrict__ h) {
    float s[5] = {0, 0, 0, 0, 0}, q[5] = {0, 0, 0, 0, 0};
    int stride = gridDim.x * blockDim.x;
    for (int r = blockIdx.x * blockDim.x + threadIdx.x; r < N_NODES; r += stride) {
#pragma unroll
        for (int c = 0; c < 5; c++) { float v = h[r * 5 + c]; s[c] += v; q[c] += v * v; }
    }
#pragma unroll
    for (int off = 16; off; off >>= 1) {
#pragma unroll
        for (int c = 0; c < 5; c++) {
            s[c] += __shfl_xor_sync(0xffffffffu, s[c], off);
            q[c] += __shfl_xor_sync(0xffffffffu, q[c], off);
        }
    }
    if ((threadIdx.x & 31) == 0) {
#pragma unroll
        for (int c = 0; c < 5; c++) {
            atomicAdd(&g_bn0[c], s[c]);
            atomicAdd(&g_bn0[5 + c], q[c]);
        }
    }
}

// ---------------- BN0 apply + conv1 linears (in=5 -> 256, 256) ----------------
__global__ void k_lin5(const float* __restrict__ h,
                       const float* __restrict__ bn_g, const float* __restrict__ bn_b,
                       const float* __restrict__ Wl, const float* __restrict__ bl,
                       const float* __restrict__ Wr, const float* __restrict__ br) {
    __shared__ float sWl[5 * 256], sWr[5 * 256];
    __shared__ float sc[5], sh[5];
    int tid = threadIdx.x;
    for (int i = tid; i < 5 * 256; i += blockDim.x) { sWl[i] = Wl[i]; sWr[i] = Wr[i]; }
    if (tid < 5) {
        float mean = g_bn0[tid] * (1.f / N_NODES);
        float var  = g_bn0[5 + tid] * (1.f / N_NODES) - mean * mean;
        float scale = rsqrtf(var + BN_EPS) * bn_g[tid];
        sc[tid] = scale; sh[tid] = bn_b[tid] - mean * scale;
    }
    __syncthreads();
    int j = tid;  // output column 0..255
    float blj = bl[j], brj = br[j];
    int n0 = blockIdx.x * 32;
    int n1 = min(n0 + 32, N_NODES);
    for (int n = n0; n < n1; n++) {
        float al = blj, ar = brj;
#pragma unroll
        for (int k = 0; k < 5; k++) {
            float x = h[n * 5 + k] * sc[k] + sh[k];
            al += x * sWl[k * 256 + j];
            ar += x * sWr[k * 256 + j];
        }
        g_xl1[(long long)n * 256 + j] = al;
        g_xr1[(long long)n * 256 + j] = ar;
    }
}

// ---------------- per-edge attention logits + segment max (warp per edge) --------
__global__ void k_alpha(const float* __restrict__ xl, int ldl,
                        const float* __restrict__ xr, int ldr,
                        const float* __restrict__ We, const float* __restrict__ att,
                        const float* __restrict__ ew,
                        const int* __restrict__ src, const int* __restrict__ dst,
                        unsigned* __restrict__ m) {
    int e = (blockIdx.x * blockDim.x + threadIdx.x) >> 5;
    if (e >= N_EDGES) return;
    int lane = threadIdx.x & 31;
    long long s = src[e], d = dst[e];
    float w = ew[e];
    const float* pl = xl + s * ldl;
    const float* pr = xr + d * ldr;
    float p0 = 0.f, p1 = 0.f;
#pragma unroll
    for (int i = 0; i < 8; i++) {
        int c = lane + 32 * i;
        float v = pl[c] + pr[c] + w * We[c];
        v = v > 0.f ? v : 0.2f * v;            // leaky_relu(0.2)
        float t = v * att[c];                  // att[h*128+c]
        if (i < 4) p0 += t; else p1 += t;
    }
#pragma unroll
    for (int off = 16; off; off >>= 1) {
        p0 += __shfl_xor_sync(0xffffffffu, p0, off);
        p1 += __shfl_xor_sync(0xffffffffu, p1, off);
    }
    if (lane == 0) {
        g_alpha[(long long)e * 2]     = p0;
        g_alpha[(long long)e * 2 + 1] = p1;
        atomicMax(&m[d * 2],     enc_f(p0));
        atomicMax(&m[d * 2 + 1], enc_f(p1));
    }
}

// ---------------- exp(alpha - max) + segment denominator ----------------
__global__ void k_expden(const int* __restrict__ dst,
                         const unsigned* __restrict__ m, float* __restrict__ den) {
    int e = blockIdx.x * blockDim.x + threadIdx.x;
    if (e >= N_EDGES) return;
    long long d = dst[e];
    float a0 = __expf(g_alpha[(long long)e * 2]     - dec_f(m[d * 2]));
    float a1 = __expf(g_alpha[(long long)e * 2 + 1] - dec_f(m[d * 2 + 1]));
    g_av[(long long)e * 2]     = a0;
    g_av[(long long)e * 2 + 1] = a1;
    atomicAdd(&den[d * 2],     a0);
    atomicAdd(&den[d * 2 + 1], a1);
}

// ---------------- weighted aggregate scatter (warp per edge, v4 red) -------------
__global__ void k_agg(const float* __restrict__ xl, int ldl,
                      const int* __restrict__ src, const int* __restrict__ dst,
                      const float* __restrict__ den, float* __restrict__ agg) {
    int e = (blockIdx.x * blockDim.x + threadIdx.x) >> 5;
    if (e >= N_EDGES) return;
    int lane = threadIdx.x & 31;
    long long s = src[e], d = dst[e];
    float c0 = g_av[(long long)e * 2]     / (den[d * 2]     + 1e-16f);
    float c1 = g_av[(long long)e * 2 + 1] / (den[d * 2 + 1] + 1e-16f);
    const float4* pl = (const float4*)(xl + s * ldl);
    float4 v0 = pl[lane];        // head 0: c = 4*lane .. 4*lane+3
    float4 v1 = pl[lane + 32];   // head 1
    float* o = agg + d * 256;
    float4 r0 = make_float4(v0.x * c0, v0.y * c0, v0.z * c0, v0.w * c0);
    float4 r1 = make_float4(v1.x * c1, v1.y * c1, v1.z * c1, v1.w * c1);
    red_add_v4(o + 4 * lane, r0);
    red_add_v4(o + 128 + 4 * lane, r1);
}

// ---------------- BN1 statistics over (agg1 + conv1 bias) ----------------
__global__ void k_bn1_reduce(const float* __restrict__ bias) {
    int c = threadIdx.x;
    float b = bias[c];
    float s = 0.f, q = 0.f;
    for (int r = blockIdx.x; r < N_NODES; r += gridDim.x) {
        float v = g_agg1[(long long)r * 256 + c] + b;
        s += v; q += v * v;
    }
    atomicAdd(&g_bn1[c], s);
    atomicAdd(&g_bn1[256 + c], q);
}

// turn sums into per-channel affine (scale A, shift C) so apply is a pure FMA
__global__ void k_bn1_finalize(const float* __restrict__ bias,
                               const float* __restrict__ g, const float* __restrict__ b) {
    int c = threadIdx.x;
    float mean = g_bn1[c] * (1.f / N_NODES);
    float var  = g_bn1[256 + c] * (1.f / N_NODES) - mean * mean;
    float A = rsqrtf(var + BN_EPS) * g[c];
    float C = (bias[c] - mean) * A + b[c];
    g_bn1[c] = A;
    g_bn1[256 + c] = C;
}

__global__ void k_bn1_apply() {
    long long i = (long long)blockIdx.x * blockDim.x + threadIdx.x;
    if (i >= (long long)N_NODES * 256) return;
    int c = (int)(i & 255);
    float v = g_agg1[i] * g_bn1[c] + g_bn1[256 + c];
    g_agg1[i] = v > 0.f ? v : 0.f;   // ReLU -> this IS x1
}

// ---------------- fused GEMM: x1[N,256] @ [mu_Wl|mu_Wr|ls_Wl|ls_Wr] -> [N,1024] --
// 128x64 block tile, 8x4 per-thread tile, BK=16, 256 threads
__global__ void k_gemm(const float* __restrict__ A,
                       const float* __restrict__ W0, const float* __restrict__ W1,
                       const float* __restrict__ W2, const float* __restrict__ W3,
                       const float* __restrict__ b0, const float* __restrict__ b1,
                       const float* __restrict__ b2, const float* __restrict__ b3,
                       float* __restrict__ C) {
    __shared__ float As[16][128];
    __shared__ float Bs[16][64];
    int tid = threadIdx.x;
    int bx = blockIdx.x;              // 0..15 (column tiles of 64)
    int by = blockIdx.y;              // row tiles of 128
    int grp = bx >> 2;                // which weight matrix
    const float* W = (grp == 0) ? W0 : (grp == 1) ? W1 : (grp == 2) ? W2 : W3;
    const float* bb = (grp == 0) ? b0 : (grp == 1) ? b1 : (grp == 2) ? b2 : b3;
    int jloc = (bx & 3) * 64;         // column offset within W (0..192)
    int rowBase = by * 128;
    int ty = tid >> 4, tx = tid & 15;

    float acc[8][4];
#pragma unroll
    for (int i = 0; i < 8; i++)
#pragma unroll
        for (int j = 0; j < 4; j++) acc[i][j] = 0.f;

    for (int k0 = 0; k0 < 256; k0 += 16) {
        // load A tile: 128 rows x 16 cols = 512 float4; 2 per thread
#pragma unroll
        for (int l = 0; l < 2; l++) {
            int p = tid + l * 256;
            int row = p >> 2, q = p & 3;
            int r = rowBase + row;
            float4 v = make_float4(0.f, 0.f, 0.f, 0.f);
            if (r < N_NODES)
                v = *(const float4*)(A + (long long)r * 256 + k0 + 4 * q);
            As[4 * q + 0][row] = v.x;
            As[4 * q + 1][row] = v.y;
            As[4 * q + 2][row] = v.z;
            As[4 * q + 3][row] = v.w;
        }
        // load B tile: 16 rows x 64 cols = 256 float4; 1 per thread
        {
            int k = tid >> 4, jq = tid & 15;
            float4 v = *(const float4*)(W + (long long)(k0 + k) * 256 + jloc + 4 * jq);
            *(float4*)&Bs[k][4 * jq] = v;
        }
        __syncthreads();
#pragma unroll
        for (int kk = 0; kk < 16; kk++) {
            float a[8], b[4];
#pragma unroll
            for (int i = 0; i < 8; i++) a[i] = As[kk][ty * 8 + i];
#pragma unroll
            for (int j = 0; j < 4; j++) b[j] = Bs[kk][tx * 4 + j];
#pragma unroll
            for (int i = 0; i < 8; i++)
#pragma unroll
                for (int j = 0; j < 4; j++) acc[i][j] += a[i] * b[j];
        }
        __syncthreads();
    }
    int colBase = bx * 64 + tx * 4;
    float4 bias4 = make_float4(bb[jloc + tx * 4 + 0], bb[jloc + tx * 4 + 1],
                               bb[jloc + tx * 4 + 2], bb[jloc + tx * 4 + 3]);
#pragma unroll
    for (int i = 0; i < 8; i++) {
        int r = rowBase + ty * 8 + i;
        if (r < N_NODES) {
            float4 v = make_float4(acc[i][0] + bias4.x, acc[i][1] + bias4.y,
                                   acc[i][2] + bias4.z, acc[i][3] + bias4.w);
            *(float4*)(C + (long long)r * 1024 + colBase) = v;
        }
    }
}

// ---------------- final: head mean + bias, write (mu, log_std) ----------------
__global__ void k_final(const float* __restrict__ mu_bias,
                        const float* __restrict__ ls_bias, float* __restrict__ out) {
    long long i = (long long)blockIdx.x * blockDim.x + threadIdx.x;
    if (i >= (long long)N_NODES * 128) return;
    long long n = i >> 7;
    int c = (int)(i & 127);
    out[i] = 0.5f * (g_agg_mu[n * 256 + c] + g_agg_mu[n * 256 + 128 + c]) + mu_bias[c];
    out[(long long)N_NODES * 128 + i] =
        0.5f * (g_agg_ls[n * 256 + c] + g_agg_ls[n * 256 + 128 + c]) + ls_bias[c];
}

// ---------------- launch ----------------
extern "C" void kernel_launch(void* const* d_in, const int* in_sizes, int n_in,
                              void* d_out, int out_size) {
    const float*     h        = (const float*)d_in[0];
    const int*       ei       = (const int*)d_in[1];      // int32! (JAX x64 disabled)
    const float*     ew       = (const float*)d_in[2];
    const float*     bn0_g    = (const float*)d_in[3];
    const float*     bn0_b    = (const float*)d_in[4];
    const float*     bn1_g    = (const float*)d_in[5];
    const float*     bn1_b    = (const float*)d_in[6];
    const float*     c1_Wl    = (const float*)d_in[7];
    const float*     c1_bl    = (const float*)d_in[8];
    const float*     c1_Wr    = (const float*)d_in[9];
    const float*     c1_br    = (const float*)d_in[10];
    const float*     c1_We    = (const float*)d_in[11];
    const float*     c1_att   = (const float*)d_in[12];
    const float*     c1_bias  = (const float*)d_in[13];
    const float*     mu_Wl    = (const float*)d_in[14];
    const float*     mu_bl    = (const float*)d_in[15];
    const float*     mu_Wr    = (const float*)d_in[16];
    const float*     mu_br    = (const float*)d_in[17];
    const float*     mu_We    = (const float*)d_in[18];
    const float*     mu_att   = (const float*)d_in[19];
    const float*     mu_bias  = (const float*)d_in[20];
    const float*     ls_Wl    = (const float*)d_in[21];
    const float*     ls_bl    = (const float*)d_in[22];
    const float*     ls_Wr    = (const float*)d_in[23];
    const float*     ls_br    = (const float*)d_in[24];
    const float*     ls_We    = (const float*)d_in[25];
    const float*     ls_att   = (const float*)d_in[26];
    const float*     ls_bias  = (const float*)d_in[27];
    float* out = (float*)d_out;

    const int* src = ei;
    const int* dst = ei + N_EDGES;

    float *xl1, *xr1, *x4, *agg1, *agg_mu, *agg_ls;
    float *den1, *denmu, *denls;
    unsigned *m1, *mmu, *mls;
    cudaGetSymbolAddress((void**)&xl1, g_xl1);
    cudaGetSymbolAddress((void**)&xr1, g_xr1);
    cudaGetSymbolAddress((void**)&x4, g_x4);
    cudaGetSymbolAddress((void**)&agg1, g_agg1);
    cudaGetSymbolAddress((void**)&agg_mu, g_agg_mu);
    cudaGetSymbolAddress((void**)&agg_ls, g_agg_ls);
    cudaGetSymbolAddress((void**)&den1, g_den1);
    cudaGetSymbolAddress((void**)&denmu, g_denmu);
    cudaGetSymbolAddress((void**)&denls, g_denls);
    cudaGetSymbolAddress((void**)&m1, g_m1);
    cudaGetSymbolAddress((void**)&mmu, g_mmu);
    cudaGetSymbolAddress((void**)&mls, g_mls);

    const int TB = 256;
    int edgeWarpBlocks = (N_EDGES * 32 + TB - 1) / TB;     // warp per edge
    int edgeBlocks     = (N_EDGES + TB - 1) / TB;

    k_init<<<1024, TB>>>();
    k_bn0_reduce<<<64, TB>>>(h);
    k_lin5<<<(N_NODES + 31) / 32, TB>>>(h, bn0_g, bn0_b, c1_Wl, c1_bl, c1_Wr, c1_br);

    // conv1 (concat=True)
    k_alpha<<<edgeWarpBlocks, TB>>>(xl1, 256, xr1, 256, c1_We, c1_att, ew, src, dst, m1);
    k_expden<<<edgeBlocks, TB>>>(dst, m1, den1);
    k_agg<<<edgeWarpBlocks, TB>>>(xl1, 256, src, dst, den1, agg1);

    // BN1 + ReLU -> x1 (in place in g_agg1)
    k_bn1_reduce<<<512, TB>>>(c1_bias);
    k_bn1_finalize<<<1, TB>>>(c1_bias, bn1_g, bn1_b);
    k_bn1_apply<<<(N_NODES * 256 + TB - 1) / TB, TB>>>();

    // fused linears for mu & log_std: x1 @ [mu_Wl|mu_Wr|ls_Wl|ls_Wr] -> g_x4
    dim3 gg(16, (N_NODES + 127) / 128);
    k_gemm<<<gg, TB>>>(agg1, mu_Wl, mu_Wr, ls_Wl, ls_Wr,
                       mu_bl, mu_br, ls_bl, ls_br, x4);

    // mu conv (concat=False -> mean of heads in k_final)
    k_alpha<<<edgeWarpBlocks, TB>>>(x4, 1024, x4 + 256, 1024, mu_We, mu_att, ew, src, dst, mmu);
    k_expden<<<edgeBlocks, TB>>>(dst, mmu, denmu);
    k_agg<<<edgeWarpBlocks, TB>>>(x4, 1024, src, dst, denmu, agg_mu);

    // log_std conv
    k_alpha<<<edgeWarpBlocks, TB>>>(x4 + 512, 1024, x4 + 768, 1024, ls_We, ls_att, ew, src, dst, mls);
    k_expden<<<edgeBlocks, TB>>>(dst, mls, denls);
    k_agg<<<edgeWarpBlocks, TB>>>(x4 + 512, 1024, src, dst, denls, agg_ls);

    k_final<<<(N_NODES * 128 + TB - 1) / TB, TB>>>(mu_bias, ls_bias, out);
}

// round 3
// speedup vs baseline: 1.1432x; 1.1432x over previous
#include <cuda_runtime.h>

#define NN 50000
#define NE 300000
#define BN_EPS 1e-5f

// ---------------- scratch (__device__ globals) ----------------
__device__ float g_xl1[NN * 256];
__device__ float g_xr1[NN * 256];
__device__ float g_x4 [NN * 1024];   // 4 contiguous blocks of [NN,256]: mu_xl|mu_xr|ls_xl|ls_xr
__device__ float g_agg1[NN * 256];   // conv1 out (+bias), pre-BN
__device__ float g_as  [NE * 4];     // per-edge alpha scratch (CSR order)
__device__ int   g_cnt [NN];
__device__ int   g_rowptr[NN + 1];
__device__ int   g_cursor[NN];
__device__ int   g_srcs[NE];         // src sorted by dst
__device__ float g_ews [NE];         // edge weight sorted by dst
__device__ float g_bn0[12];
__device__ float g_bn1[512];         // sums -> then (A scale, C shift)

// ---------------- helpers ----------------
__device__ __forceinline__ float wsum(float v) {
#pragma unroll
    for (int o = 16; o; o >>= 1) v += __shfl_xor_sync(0xffffffffu, v, o);
    return v;
}
#define NEG_INF __int_as_float(0xff800000)

__device__ __forceinline__ unsigned long long packdup(float f) {
    unsigned long long r;
    asm("mov.b64 %0, {%1, %1};" : "=l"(r) : "r"(__float_as_uint(f)));
    return r;
}
__device__ __forceinline__ void fma2(unsigned long long& acc,
                                     unsigned long long a, unsigned long long b) {
    asm("fma.rn.f32x2 %0, %1, %2, %0;" : "+l"(acc) : "l"(a), "l"(b));
}
__device__ __forceinline__ float2 unpk(unsigned long long v) {
    unsigned lo, hi;
    asm("mov.b64 {%0, %1}, %2;" : "=r"(lo), "=r"(hi) : "l"(v));
    return make_float2(__uint_as_float(lo), __uint_as_float(hi));
}

// ---------------- init ----------------
__global__ void k_init() {
    int i = blockIdx.x * blockDim.x + threadIdx.x;
    int stride = gridDim.x * blockDim.x;
    for (int t = i; t < NN; t += stride) g_cnt[t] = 0;
    for (int t = i; t < 512; t += stride) g_bn1[t] = 0.f;
    if (i < 12) g_bn0[i] = 0.f;
}

// ---------------- BN0 statistics (5 channels) ----------------
__global__ void k_bn0_reduce(const float* __restrict__ h) {
    float s[5] = {0, 0, 0, 0, 0}, q[5] = {0, 0, 0, 0, 0};
    int stride = gridDim.x * blockDim.x;
    for (int r = blockIdx.x * blockDim.x + threadIdx.x; r < NN; r += stride) {
#pragma unroll
        for (int c = 0; c < 5; c++) { float v = h[r * 5 + c]; s[c] += v; q[c] += v * v; }
    }
#pragma unroll
    for (int off = 16; off; off >>= 1) {
#pragma unroll
        for (int c = 0; c < 5; c++) {
            s[c] += __shfl_xor_sync(0xffffffffu, s[c], off);
            q[c] += __shfl_xor_sync(0xffffffffu, q[c], off);
        }
    }
    if ((threadIdx.x & 31) == 0) {
#pragma unroll
        for (int c = 0; c < 5; c++) {
            atomicAdd(&g_bn0[c], s[c]);
            atomicAdd(&g_bn0[5 + c], q[c]);
        }
    }
}

// ---------------- BN0 apply + conv1 linears (in=5 -> 256,256) ----------------
__global__ void k_lin5(const float* __restrict__ h,
                       const float* __restrict__ bn_g, const float* __restrict__ bn_b,
                       const float* __restrict__ Wl, const float* __restrict__ bl,
                       const float* __restrict__ Wr, const float* __restrict__ br) {
    __shared__ float sWl[5 * 256], sWr[5 * 256];
    __shared__ float sc[5], sh[5];
    int tid = threadIdx.x;
    for (int i = tid; i < 5 * 256; i += blockDim.x) { sWl[i] = Wl[i]; sWr[i] = Wr[i]; }
    if (tid < 5) {
        float mean = g_bn0[tid] * (1.f / NN);
        float var  = g_bn0[5 + tid] * (1.f / NN) - mean * mean;
        float scale = rsqrtf(var + BN_EPS) * bn_g[tid];
        sc[tid] = scale; sh[tid] = bn_b[tid] - mean * scale;
    }
    __syncthreads();
    int j = tid;
    float blj = bl[j], brj = br[j];
    int n0 = blockIdx.x * 32, n1 = min(n0 + 32, NN);
    for (int n = n0; n < n1; n++) {
        float al = blj, ar = brj;
#pragma unroll
        for (int k = 0; k < 5; k++) {
            float x = h[n * 5 + k] * sc[k] + sh[k];
            al += x * sWl[k * 256 + j];
            ar += x * sWr[k * 256 + j];
        }
        g_xl1[(long long)n * 256 + j] = al;
        g_xr1[(long long)n * 256 + j] = ar;
    }
}

// ---------------- CSR build ----------------
__global__ void k_hist(const int* __restrict__ dst) {
    int e = blockIdx.x * blockDim.x + threadIdx.x;
    if (e < NE) atomicAdd(&g_cnt[dst[e]], 1);
}

__global__ void k_scan() {   // single block, 1024 threads
    __shared__ int ssum[1024];
    int t = threadIdx.x;
    const int CH = (NN + 1023) / 1024;   // 49
    int base = t * CH;
    int s = 0;
    for (int i = 0; i < CH; i++) { int n = base + i; if (n < NN) s += g_cnt[n]; }
    ssum[t] = s;
    __syncthreads();
    for (int off = 1; off < 1024; off <<= 1) {
        int v = (t >= off) ? ssum[t - off] : 0;
        __syncthreads();
        ssum[t] += v;
        __syncthreads();
    }
    int run = ssum[t] - s;   // exclusive prefix
    for (int i = 0; i < CH; i++) {
        int n = base + i;
        if (n < NN) { g_rowptr[n] = run; g_cursor[n] = run; run += g_cnt[n]; }
    }
    if (t == 0) g_rowptr[NN] = NE;
}

__global__ void k_scatter(const int* __restrict__ src, const int* __restrict__ dst,
                          const float* __restrict__ ew) {
    int e = blockIdx.x * blockDim.x + threadIdx.x;
    if (e < NE) {
        int p = atomicAdd(&g_cursor[dst[e]], 1);
        g_srcs[p] = src[e];
        g_ews[p]  = ew[e];
    }
}

// ---------------- conv1: warp-per-node fused softmax + aggregate ----------------
__global__ void k_node1(const float* __restrict__ We, const float* __restrict__ att,
                        const float* __restrict__ bias) {
    int n = (blockIdx.x * blockDim.x + threadIdx.x) >> 5;
    if (n >= NN) return;
    int lane = threadIdx.x & 31;
    int cb = lane * 8;                  // channels cb..cb+7; head = (lane>=16)
    int js = g_rowptr[n], je = g_rowptr[n + 1];
    const float4* pxr = (const float4*)&g_xr1[(long long)n * 256 + cb];
    float4 xrA = pxr[0], xrB = pxr[1];
    float4 weA = *(const float4*)&We[cb],  weB = *(const float4*)&We[cb + 4];
    float4 atA = *(const float4*)&att[cb], atB = *(const float4*)&att[cb + 4];
    float m0 = NEG_INF, m1 = NEG_INF;
    for (int j = js; j < je; j++) {
        int s = g_srcs[j]; float w = g_ews[j];
        const float4* px = (const float4*)&g_xl1[(long long)s * 256 + cb];
        float4 xa = px[0], xb = px[1];
        float t = 0.f, v;
        v = xa.x + xrA.x + w * weA.x; v = v > 0.f ? v : 0.2f * v; t += v * atA.x;
        v = xa.y + xrA.y + w * weA.y; v = v > 0.f ? v : 0.2f * v; t += v * atA.y;
        v = xa.z + xrA.z + w * weA.z; v = v > 0.f ? v : 0.2f * v; t += v * atA.z;
        v = xa.w + xrA.w + w * weA.w; v = v > 0.f ? v : 0.2f * v; t += v * atA.w;
        v = xb.x + xrB.x + w * weB.x; v = v > 0.f ? v : 0.2f * v; t += v * atB.x;
        v = xb.y + xrB.y + w * weB.y; v = v > 0.f ? v : 0.2f * v; t += v * atB.y;
        v = xb.z + xrB.z + w * weB.z; v = v > 0.f ? v : 0.2f * v; t += v * atB.z;
        v = xb.w + xrB.w + w * weB.w; v = v > 0.f ? v : 0.2f * v; t += v * atB.w;
        float p0 = wsum(lane < 16 ? t : 0.f);
        float p1 = wsum(lane < 16 ? 0.f : t);
        if (lane == 0) { g_as[2 * j] = p0; g_as[2 * j + 1] = p1; }
        m0 = fmaxf(m0, p0); m1 = fmaxf(m1, p1);
    }
    __syncwarp();
    float d0 = 0.f, d1 = 0.f;
    for (int j = js + lane; j < je; j += 32) {
        float a0 = __expf(g_as[2 * j]     - m0);
        float a1 = __expf(g_as[2 * j + 1] - m1);
        g_as[2 * j] = a0; g_as[2 * j + 1] = a1;
        d0 += a0; d1 += a1;
    }
    d0 = wsum(d0); d1 = wsum(d1);
    __syncwarp();
    float i0 = 1.f / (d0 + 1e-16f), i1 = 1.f / (d1 + 1e-16f);
    float acc[8] = {0, 0, 0, 0, 0, 0, 0, 0};
    for (int j = js; j < je; j++) {
        int s = g_srcs[j];
        float wv = (lane < 16) ? g_as[2 * j] * i0 : g_as[2 * j + 1] * i1;
        const float4* px = (const float4*)&g_xl1[(long long)s * 256 + cb];
        float4 xa = px[0], xb = px[1];
        acc[0] += wv * xa.x; acc[1] += wv * xa.y; acc[2] += wv * xa.z; acc[3] += wv * xa.w;
        acc[4] += wv * xb.x; acc[5] += wv * xb.y; acc[6] += wv * xb.z; acc[7] += wv * xb.w;
    }
    float4 bA = *(const float4*)&bias[cb], bB = *(const float4*)&bias[cb + 4];
    float4 o0 = make_float4(acc[0] + bA.x, acc[1] + bA.y, acc[2] + bA.z, acc[3] + bA.w);
    float4 o1 = make_float4(acc[4] + bB.x, acc[5] + bB.y, acc[6] + bB.z, acc[7] + bB.w);
    float4* po = (float4*)&g_agg1[(long long)n * 256 + cb];
    po[0] = o0; po[1] = o1;
}

// ---------------- BN1 statistics + finalize ----------------
__global__ void k_bn1_reduce() {
    int c = threadIdx.x;
    float s = 0.f, q = 0.f;
    for (int r = blockIdx.x; r < NN; r += gridDim.x) {
        float v = g_agg1[(long long)r * 256 + c];
        s += v; q += v * v;
    }
    atomicAdd(&g_bn1[c], s);
    atomicAdd(&g_bn1[256 + c], q);
}

__global__ void k_bn1_finalize(const float* __restrict__ g, const float* __restrict__ b) {
    int c = threadIdx.x;
    float mean = g_bn1[c] * (1.f / NN);
    float var  = g_bn1[256 + c] * (1.f / NN) - mean * mean;
    float A = rsqrtf(var + BN_EPS) * g[c];
    float C = b[c] - mean * A;
    g_bn1[c] = A;
    g_bn1[256 + c] = C;
}

// ---------------- fused GEMM (f32x2): relu(bn(agg1)) @ [4 x W(256x256)] ----------
// 128x128 block tile, 256 threads, 8x8 per thread via packed fp32 pairs
__global__ void __launch_bounds__(256) k_gemm(
        const float* __restrict__ A,
        const float* __restrict__ W0, const float* __restrict__ W1,
        const float* __restrict__ W2, const float* __restrict__ W3,
        const float* __restrict__ b0, const float* __restrict__ b1,
        const float* __restrict__ b2, const float* __restrict__ b3,
        const float* __restrict__ bnA, const float* __restrict__ bnC,
        float* __restrict__ Cout) {
    __shared__ float As[16][128];
    __shared__ float Bs[16][128];
    int tid = threadIdx.x;
    int bx = blockIdx.x;              // 0..7 -> 4 weights x 2 col halves
    int by = blockIdx.y;
    int grp = bx >> 1;
    const float* W  = (grp == 0) ? W0 : (grp == 1) ? W1 : (grp == 2) ? W2 : W3;
    const float* bb = (grp == 0) ? b0 : (grp == 1) ? b1 : (grp == 2) ? b2 : b3;
    int jloc = (bx & 1) * 128;
    int rowBase = by * 128;
    int ty = tid >> 4, tx = tid & 15;

    unsigned long long acc[8][4];
#pragma unroll
    for (int i = 0; i < 8; i++)
#pragma unroll
        for (int j = 0; j < 4; j++) acc[i][j] = 0ull;

    for (int k0 = 0; k0 < 256; k0 += 16) {
        // A tile: 128x16, bn+relu applied on load
#pragma unroll
        for (int l = 0; l < 2; l++) {
            int p = tid + l * 256;
            int row = p >> 2, q = p & 3;
            int r = rowBase + row;
            int ccol = k0 + 4 * q;
            float4 v = make_float4(0.f, 0.f, 0.f, 0.f);
            if (r < NN) v = *(const float4*)(A + (long long)r * 256 + ccol);
            float4 sA = *(const float4*)(bnA + ccol);
            float4 sC = *(const float4*)(bnC + ccol);
            As[4 * q + 0][row] = fmaxf(v.x * sA.x + sC.x, 0.f);
            As[4 * q + 1][row] = fmaxf(v.y * sA.y + sC.y, 0.f);
            As[4 * q + 2][row] = fmaxf(v.z * sA.z + sC.z, 0.f);
            As[4 * q + 3][row] = fmaxf(v.w * sA.w + sC.w, 0.f);
        }
        // B tile: 16x128
#pragma unroll
        for (int l = 0; l < 2; l++) {
            int p = tid + l * 256;
            int k = p >> 5, jq = p & 31;
            *(float4*)&Bs[k][4 * jq] = *(const float4*)(W + (long long)(k0 + k) * 256 + jloc + 4 * jq);
        }
        __syncthreads();
#pragma unroll
        for (int kk = 0; kk < 16; kk++) {
            const float4* ap = (const float4*)&As[kk][ty * 8];
            float4 a0 = ap[0], a1 = ap[1];
            unsigned long long a2[8];
            a2[0] = packdup(a0.x); a2[1] = packdup(a0.y);
            a2[2] = packdup(a0.z); a2[3] = packdup(a0.w);
            a2[4] = packdup(a1.x); a2[5] = packdup(a1.y);
            a2[6] = packdup(a1.z); a2[7] = packdup(a1.w);
            const ulonglong2* bp = (const ulonglong2*)&Bs[kk][tx * 8];
            ulonglong2 bA = bp[0], bB = bp[1];
            unsigned long long b2[4] = {bA.x, bA.y, bB.x, bB.y};
#pragma unroll
            for (int i = 0; i < 8; i++)
#pragma unroll
                for (int j = 0; j < 4; j++) fma2(acc[i][j], a2[i], b2[j]);
        }
        __syncthreads();
    }
    // epilogue: out block = Cout + grp*NN*256, cols jloc + tx*8 .. +7
    float* outp = Cout + (long long)grp * NN * 256;
    int col = jloc + tx * 8;
    float bias8[8];
#pragma unroll
    for (int j = 0; j < 8; j++) bias8[j] = bb[col + j];
#pragma unroll
    for (int i = 0; i < 8; i++) {
        int r = rowBase + ty * 8 + i;
        if (r < NN) {
            float2 p0 = unpk(acc[i][0]), p1 = unpk(acc[i][1]);
            float2 p2 = unpk(acc[i][2]), p3 = unpk(acc[i][3]);
            float4 o0 = make_float4(p0.x + bias8[0], p0.y + bias8[1],
                                    p1.x + bias8[2], p1.y + bias8[3]);
            float4 o1 = make_float4(p2.x + bias8[4], p2.y + bias8[5],
                                    p3.x + bias8[6], p3.y + bias8[7]);
            float4* po = (float4*)(outp + (long long)r * 256 + col);
            po[0] = o0; po[1] = o1;
        }
    }
}

// ---------------- mu + log_std: warp-per-node fused dual conv ----------------
__global__ void k_node2(const float* __restrict__ muxl, const float* __restrict__ muxr,
                        const float* __restrict__ lsxl, const float* __restrict__ lsxr,
                        const float* __restrict__ Wem, const float* __restrict__ atm_,
                        const float* __restrict__ Wel, const float* __restrict__ atl_,
                        const float* __restrict__ bm, const float* __restrict__ bl_,
                        float* __restrict__ out) {
    int n = (blockIdx.x * blockDim.x + threadIdx.x) >> 5;
    if (n >= NN) return;
    int lane = threadIdx.x & 31;
    int cb = lane * 8;
    int js = g_rowptr[n], je = g_rowptr[n + 1];
    const float4* pm = (const float4*)&muxr[(long long)n * 256 + cb];
    const float4* pl = (const float4*)&lsxr[(long long)n * 256 + cb];
    float4 xmA = pm[0], xmB = pm[1];
    float4 xlA = pl[0], xlB = pl[1];
    float4 wmA = *(const float4*)&Wem[cb],  wmB = *(const float4*)&Wem[cb + 4];
    float4 amA = *(const float4*)&atm_[cb], amB = *(const float4*)&atm_[cb + 4];
    float4 wlA = *(const float4*)&Wel[cb],  wlB = *(const float4*)&Wel[cb + 4];
    float4 alA = *(const float4*)&atl_[cb], alB = *(const float4*)&atl_[cb + 4];
    float mm0 = NEG_INF, mm1 = NEG_INF, ml0 = NEG_INF, ml1 = NEG_INF;
    for (int j = js; j < je; j++) {
        int s = g_srcs[j]; float w = g_ews[j];
        const float4* pxm = (const float4*)&muxl[(long long)s * 256 + cb];
        const float4* pxl = (const float4*)&lsxl[(long long)s * 256 + cb];
        float4 ma = pxm[0], mb = pxm[1];
        float4 la = pxl[0], lb = pxl[1];
        float tm = 0.f, tl = 0.f, v;
        v = ma.x + xmA.x + w * wmA.x; v = v > 0.f ? v : 0.2f * v; tm += v * amA.x;
        v = ma.y + xmA.y + w * wmA.y; v = v > 0.f ? v : 0.2f * v; tm += v * amA.y;
        v = ma.z + xmA.z + w * wmA.z; v = v > 0.f ? v : 0.2f * v; tm += v * amA.z;
        v = ma.w + xmA.w + w * wmA.w; v = v > 0.f ? v : 0.2f * v; tm += v * amA.w;
        v = mb.x + xmB.x + w * wmB.x; v = v > 0.f ? v : 0.2f * v; tm += v * amB.x;
        v = mb.y + xmB.y + w * wmB.y; v = v > 0.f ? v : 0.2f * v; tm += v * amB.y;
        v = mb.z + xmB.z + w * wmB.z; v = v > 0.f ? v : 0.2f * v; tm += v * amB.z;
        v = mb.w + xmB.w + w * wmB.w; v = v > 0.f ? v : 0.2f * v; tm += v * amB.w;
        v = la.x + xlA.x + w * wlA.x; v = v > 0.f ? v : 0.2f * v; tl += v * alA.x;
        v = la.y + xlA.y + w * wlA.y; v = v > 0.f ? v : 0.2f * v; tl += v * alA.y;
        v = la.z + xlA.z + w * wlA.z; v = v > 0.f ? v : 0.2f * v; tl += v * alA.z;
        v = la.w + xlA.w + w * wlA.w; v = v > 0.f ? v : 0.2f * v; tl += v * alA.w;
        v = lb.x + xlB.x + w * wlB.x; v = v > 0.f ? v : 0.2f * v; tl += v * alB.x;
        v = lb.y + xlB.y + w * wlB.y; v = v > 0.f ? v : 0.2f * v; tl += v * alB.y;
        v = lb.z + xlB.z + w * wlB.z; v = v > 0.f ? v : 0.2f * v; tl += v * alB.z;
        v = lb.w + xlB.w + w * wlB.w; v = v > 0.f ? v : 0.2f * v; tl += v * alB.w;
        float pm0 = wsum(lane < 16 ? tm : 0.f);
        float pm1 = wsum(lane < 16 ? 0.f : tm);
        float pl0 = wsum(lane < 16 ? tl : 0.f);
        float pl1 = wsum(lane < 16 ? 0.f : tl);
        if (lane == 0) {
            g_as[4 * j + 0] = pm0; g_as[4 * j + 1] = pm1;
            g_as[4 * j + 2] = pl0; g_as[4 * j + 3] = pl1;
        }
        mm0 = fmaxf(mm0, pm0); mm1 = fmaxf(mm1, pm1);
        ml0 = fmaxf(ml0, pl0); ml1 = fmaxf(ml1, pl1);
    }
    __syncwarp();
    float dm0 = 0.f, dm1 = 0.f, dl0 = 0.f, dl1 = 0.f;
    for (int j = js + lane; j < je; j += 32) {
        float a0 = __expf(g_as[4 * j + 0] - mm0);
        float a1 = __expf(g_as[4 * j + 1] - mm1);
        float a2 = __expf(g_as[4 * j + 2] - ml0);
        float a3 = __expf(g_as[4 * j + 3] - ml1);
        g_as[4 * j + 0] = a0; g_as[4 * j + 1] = a1;
        g_as[4 * j + 2] = a2; g_as[4 * j + 3] = a3;
        dm0 += a0; dm1 += a1; dl0 += a2; dl1 += a3;
    }
    dm0 = wsum(dm0); dm1 = wsum(dm1); dl0 = wsum(dl0); dl1 = wsum(dl1);
    __syncwarp();
    float im0 = 1.f / (dm0 + 1e-16f), im1 = 1.f / (dm1 + 1e-16f);
    float il0 = 1.f / (dl0 + 1e-16f), il1 = 1.f / (dl1 + 1e-16f);
    float accm[8] = {0, 0, 0, 0, 0, 0, 0, 0};
    float accl[8] = {0, 0, 0, 0, 0, 0, 0, 0};
    for (int j = js; j < je; j++) {
        int s = g_srcs[j];
        float wm = (lane < 16) ? g_as[4 * j + 0] * im0 : g_as[4 * j + 1] * im1;
        float wl = (lane < 16) ? g_as[4 * j + 2] * il0 : g_as[4 * j + 3] * il1;
        const float4* pxm = (const float4*)&muxl[(long long)s * 256 + cb];
        const float4* pxl = (const float4*)&lsxl[(long long)s * 256 + cb];
        float4 ma = pxm[0], mb = pxm[1];
        float4 la = pxl[0], lb = pxl[1];
        accm[0] += wm * ma.x; accm[1] += wm * ma.y; accm[2] += wm * ma.z; accm[3] += wm * ma.w;
        accm[4] += wm * mb.x; accm[5] += wm * mb.y; accm[6] += wm * mb.z; accm[7] += wm * mb.w;
        accl[0] += wl * la.x; accl[1] += wl * la.y; accl[2] += wl * la.z; accl[3] += wl * la.w;
        accl[4] += wl * lb.x; accl[5] += wl * lb.y; accl[6] += wl * lb.z; accl[7] += wl * lb.w;
    }
    // mean over heads: lane<16 holds head0 ch (cb..cb+7), partner lane+16 holds ch+128
    float rm[8], rl[8];
#pragma unroll
    for (int k = 0; k < 8; k++) {
        float pm_ = __shfl_xor_sync(0xffffffffu, accm[k], 16);
        float pl_ = __shfl_xor_sync(0xffffffffu, accl[k], 16);
        rm[k] = 0.5f * (accm[k] + pm_);
        rl[k] = 0.5f * (accl[k] + pl_);
    }
    if (lane < 16) {
        float4 bmA = *(const float4*)&bm[cb],  bmB = *(const float4*)&bm[cb + 4];
        float4 blA = *(const float4*)&bl_[cb], blB = *(const float4*)&bl_[cb + 4];
        float4* po = (float4*)&out[(long long)n * 128 + cb];
        po[0] = make_float4(rm[0] + bmA.x, rm[1] + bmA.y, rm[2] + bmA.z, rm[3] + bmA.w);
        po[1] = make_float4(rm[4] + bmB.x, rm[5] + bmB.y, rm[6] + bmB.z, rm[7] + bmB.w);
        float4* pq = (float4*)&out[(long long)NN * 128 + (long long)n * 128 + cb];
        pq[0] = make_float4(rl[0] + blA.x, rl[1] + blA.y, rl[2] + blA.z, rl[3] + blA.w);
        pq[1] = make_float4(rl[4] + blB.x, rl[5] + blB.y, rl[6] + blB.z, rl[7] + blB.w);
    }
}

// ---------------- launch ----------------
extern "C" void kernel_launch(void* const* d_in, const int* in_sizes, int n_in,
                              void* d_out, int out_size) {
    const float* h       = (const float*)d_in[0];
    const int*   ei      = (const int*)d_in[1];
    const float* ew      = (const float*)d_in[2];
    const float* bn0_g   = (const float*)d_in[3];
    const float* bn0_b   = (const float*)d_in[4];
    const float* bn1_g   = (const float*)d_in[5];
    const float* bn1_b   = (const float*)d_in[6];
    const float* c1_Wl   = (const float*)d_in[7];
    const float* c1_bl   = (const float*)d_in[8];
    const float* c1_Wr   = (const float*)d_in[9];
    const float* c1_br   = (const float*)d_in[10];
    const float* c1_We   = (const float*)d_in[11];
    const float* c1_att  = (const float*)d_in[12];
    const float* c1_bias = (const float*)d_in[13];
    const float* mu_Wl   = (const float*)d_in[14];
    const float* mu_bl   = (const float*)d_in[15];
    const float* mu_Wr   = (const float*)d_in[16];
    const float* mu_br   = (const float*)d_in[17];
    const float* mu_We   = (const float*)d_in[18];
    const float* mu_att  = (const float*)d_in[19];
    const float* mu_bias = (const float*)d_in[20];
    const float* ls_Wl   = (const float*)d_in[21];
    const float* ls_bl   = (const float*)d_in[22];
    const float* ls_Wr   = (const float*)d_in[23];
    const float* ls_br   = (const float*)d_in[24];
    const float* ls_We   = (const float*)d_in[25];
    const float* ls_att  = (const float*)d_in[26];
    const float* ls_bias = (const float*)d_in[27];
    float* out = (float*)d_out;

    const int* src = ei;
    const int* dst = ei + NE;

    float *x4, *agg1, *bn1;
    cudaGetSymbolAddress((void**)&x4, g_x4);
    cudaGetSymbolAddress((void**)&agg1, g_agg1);
    cudaGetSymbolAddress((void**)&bn1, g_bn1);

    const int TB = 256;
    int eb = (NE + TB - 1) / TB;
    int nodeWarpBlocks = (NN * 32 + TB - 1) / TB;

    k_init<<<128, TB>>>();
    k_bn0_reduce<<<64, TB>>>(h);
    k_lin5<<<(NN + 31) / 32, TB>>>(h, bn0_g, bn0_b, c1_Wl, c1_bl, c1_Wr, c1_br);

    // CSR build (dst-grouped)
    k_hist<<<eb, TB>>>(dst);
    k_scan<<<1, 1024>>>();
    k_scatter<<<eb, TB>>>(src, dst, ew);

    // conv1 fused softmax-aggregate
    float *xl1, *xr1;
    cudaGetSymbolAddress((void**)&xl1, g_xl1);
    cudaGetSymbolAddress((void**)&xr1, g_xr1);
    (void)xl1; (void)xr1;
    k_node1<<<nodeWarpBlocks, TB>>>(c1_We, c1_att, c1_bias);

    // BN1 stats (apply fused into GEMM A-load)
    k_bn1_reduce<<<512, TB>>>();
    k_bn1_finalize<<<1, TB>>>(bn1_g, bn1_b);

    // fused GEMM -> 4 blocks [NN,256]: mu_xl | mu_xr | ls_xl | ls_xr
    dim3 gg(8, (NN + 127) / 128);
    k_gemm<<<gg, TB>>>(agg1, mu_Wl, mu_Wr, ls_Wl, ls_Wr,
                       mu_bl, mu_br, ls_bl, ls_br,
                       bn1, bn1 + 256, x4);

    // mu + log_std fused dual conv -> out
    k_node2<<<nodeWarpBlocks, TB>>>(x4, x4 + (long long)NN * 256,
                                    x4 + 2ll * NN * 256, x4 + 3ll * NN * 256,
                                    mu_We, mu_att, ls_We, ls_att,
                                    mu_bias, ls_bias, out);
}

// round 4
// speedup vs baseline: 1.1832x; 1.0350x over previous
#include <cuda_runtime.h>

#define NN 50000
#define NE 300000
#define BN_EPS 1e-5f
#define NEG_INF __int_as_float(0xff800000)

// ---------------- scratch (__device__ globals) ----------------
__device__ float g_xl1[NN * 256];
__device__ float g_xr1[NN * 256];
__device__ float g_x4 [NN * 1024];   // 4 blocks [NN,256]: mu_xl | mu_xr | ls_xl | ls_xr
__device__ float g_agg1[NN * 256];   // conv1 out (+bias), pre-BN
__device__ int   g_cnt [NN];
__device__ int   g_rowptr[NN + 1];
__device__ int   g_cursor[NN];
__device__ int   g_srcs[NE];
__device__ float g_ews [NE];
__device__ int   g_bsum[64];
__device__ int   g_boff[64];
__device__ float g_bn0[12];
__device__ float g_bn1[512];         // sums -> (A scale, C shift)

// ---------------- helpers ----------------
__device__ __forceinline__ float wsum(float v) {
#pragma unroll
    for (int o = 16; o; o >>= 1) v += __shfl_xor_sync(0xffffffffu, v, o);
    return v;
}
__device__ __forceinline__ unsigned long long packdup(float f) {
    unsigned long long r;
    asm("mov.b64 %0, {%1, %1};" : "=l"(r) : "r"(__float_as_uint(f)));
    return r;
}
__device__ __forceinline__ void fma2(unsigned long long& acc,
                                     unsigned long long a, unsigned long long b) {
    asm("fma.rn.f32x2 %0, %1, %2, %0;" : "+l"(acc) : "l"(a), "l"(b));
}
__device__ __forceinline__ float2 unpk(unsigned long long v) {
    unsigned lo, hi;
    asm("mov.b64 {%0, %1}, %2;" : "=r"(lo), "=r"(hi) : "l"(v));
    return make_float2(__uint_as_float(lo), __uint_as_float(hi));
}

// ---------------- init ----------------
__global__ void k_init() {
    int i = blockIdx.x * blockDim.x + threadIdx.x;
    int stride = gridDim.x * blockDim.x;
    for (int t = i; t < NN; t += stride) g_cnt[t] = 0;
    for (int t = i; t < 512; t += stride) g_bn1[t] = 0.f;
    if (i < 12) g_bn0[i] = 0.f;
}

// ---------------- BN0 statistics ----------------
__global__ void k_bn0_reduce(const float* __restrict__ h) {
    float s[5] = {0, 0, 0, 0, 0}, q[5] = {0, 0, 0, 0, 0};
    int stride = gridDim.x * blockDim.x;
    for (int r = blockIdx.x * blockDim.x + threadIdx.x; r < NN; r += stride) {
#pragma unroll
        for (int c = 0; c < 5; c++) { float v = h[r * 5 + c]; s[c] += v; q[c] += v * v; }
    }
#pragma unroll
    for (int off = 16; off; off >>= 1) {
#pragma unroll
        for (int c = 0; c < 5; c++) {
            s[c] += __shfl_xor_sync(0xffffffffu, s[c], off);
            q[c] += __shfl_xor_sync(0xffffffffu, q[c], off);
        }
    }
    if ((threadIdx.x & 31) == 0) {
#pragma unroll
        for (int c = 0; c < 5; c++) {
            atomicAdd(&g_bn0[c], s[c]);
            atomicAdd(&g_bn0[5 + c], q[c]);
        }
    }
}

// ---------------- hist ----------------
__global__ void k_hist(const int* __restrict__ dst) {
    int e = blockIdx.x * blockDim.x + threadIdx.x;
    if (e < NE) atomicAdd(&g_cnt[dst[e]], 1);
}

// ---------------- BN0 apply + conv1 linears ----------------
__global__ void k_lin5(const float* __restrict__ h,
                       const float* __restrict__ bn_g, const float* __restrict__ bn_b,
                       const float* __restrict__ Wl, const float* __restrict__ bl,
                       const float* __restrict__ Wr, const float* __restrict__ br) {
    __shared__ float sWl[5 * 256], sWr[5 * 256];
    __shared__ float sc[5], sh[5];
    int tid = threadIdx.x;
    for (int i = tid; i < 5 * 256; i += blockDim.x) { sWl[i] = Wl[i]; sWr[i] = Wr[i]; }
    if (tid < 5) {
        float mean = g_bn0[tid] * (1.f / NN);
        float var  = g_bn0[5 + tid] * (1.f / NN) - mean * mean;
        float scale = rsqrtf(var + BN_EPS) * bn_g[tid];
        sc[tid] = scale; sh[tid] = bn_b[tid] - mean * scale;
    }
    __syncthreads();
    int j = tid;
    float blj = bl[j], brj = br[j];
    int n0 = blockIdx.x * 32, n1 = min(n0 + 32, NN);
    for (int n = n0; n < n1; n++) {
        float al = blj, ar = brj;
#pragma unroll
        for (int k = 0; k < 5; k++) {
            float x = h[n * 5 + k] * sc[k] + sh[k];
            al += x * sWl[k * 256 + j];
            ar += x * sWr[k * 256 + j];
        }
        g_xl1[(long long)n * 256 + j] = al;
        g_xr1[(long long)n * 256 + j] = ar;
    }
}

// ---------------- CSR scan (3 kernels, coalesced) ----------------
__global__ void k_scan1() {    // 49 blocks x 1024: per-block sum
    __shared__ int sm[1024];
    int t = threadIdx.x;
    int n = blockIdx.x * 1024 + t;
    sm[t] = (n < NN) ? g_cnt[n] : 0;
    __syncthreads();
    for (int off = 512; off; off >>= 1) {
        if (t < off) sm[t] += sm[t + off];
        __syncthreads();
    }
    if (t == 0) g_bsum[blockIdx.x] = sm[0];
}

__global__ void k_scan2(int nblocks) {   // 1 block, 64 threads: scan block sums
    __shared__ int sm[64];
    int t = threadIdx.x;
    int v = (t < nblocks) ? g_bsum[t] : 0;
    sm[t] = v;
    __syncthreads();
    for (int off = 1; off < 64; off <<= 1) {
        int u = (t >= off) ? sm[t - off] : 0;
        __syncthreads();
        sm[t] += u;
        __syncthreads();
    }
    g_boff[t] = sm[t] - v;   // exclusive
    if (t == 0) g_rowptr[NN] = NE;
}

__global__ void k_scan3() {    // 49 blocks x 1024: scan within block + offset
    __shared__ int sm[1024];
    int t = threadIdx.x;
    int n = blockIdx.x * 1024 + t;
    int v = (n < NN) ? g_cnt[n] : 0;
    sm[t] = v;
    __syncthreads();
    for (int off = 1; off < 1024; off <<= 1) {
        int u = (t >= off) ? sm[t - off] : 0;
        __syncthreads();
        sm[t] += u;
        __syncthreads();
    }
    if (n < NN) {
        int excl = g_boff[blockIdx.x] + sm[t] - v;
        g_rowptr[n] = excl;
        g_cursor[n] = excl;
    }
}

__global__ void k_scatter(const int* __restrict__ src, const int* __restrict__ dst,
                          const float* __restrict__ ew) {
    int e = blockIdx.x * blockDim.x + threadIdx.x;
    if (e < NE) {
        int p = atomicAdd(&g_cursor[dst[e]], 1);
        g_srcs[p] = src[e];
        g_ews[p]  = ew[e];
    }
}

// ---------------- conv1: warp-per-node ONLINE softmax + aggregate ----------------
__global__ void k_node1(const float* __restrict__ We, const float* __restrict__ att,
                        const float* __restrict__ bias) {
    int n = (blockIdx.x * blockDim.x + threadIdx.x) >> 5;
    if (n >= NN) return;
    int lane = threadIdx.x & 31;
    int cb = lane * 8;                  // channels cb..cb+7; head = (lane>=16)
    int js = g_rowptr[n], je = g_rowptr[n + 1];
    const float4* pxr = (const float4*)&g_xr1[(long long)n * 256 + cb];
    float4 xrA = pxr[0], xrB = pxr[1];
    float4 weA = *(const float4*)&We[cb],  weB = *(const float4*)&We[cb + 4];
    float4 atA = *(const float4*)&att[cb], atB = *(const float4*)&att[cb + 4];
    float m = NEG_INF, den = 0.f;
    float acc[8] = {0, 0, 0, 0, 0, 0, 0, 0};
    for (int j = js; j < je; j++) {
        int s = g_srcs[j]; float w = g_ews[j];
        const float4* px = (const float4*)&g_xl1[(long long)s * 256 + cb];
        float4 xa = px[0], xb = px[1];
        float t = 0.f, v;
        v = xa.x + xrA.x + w * weA.x; v = v > 0.f ? v : 0.2f * v; t += v * atA.x;
        v = xa.y + xrA.y + w * weA.y; v = v > 0.f ? v : 0.2f * v; t += v * atA.y;
        v = xa.z + xrA.z + w * weA.z; v = v > 0.f ? v : 0.2f * v; t += v * atA.z;
        v = xa.w + xrA.w + w * weA.w; v = v > 0.f ? v : 0.2f * v; t += v * atA.w;
        v = xb.x + xrB.x + w * weB.x; v = v > 0.f ? v : 0.2f * v; t += v * atB.x;
        v = xb.y + xrB.y + w * weB.y; v = v > 0.f ? v : 0.2f * v; t += v * atB.y;
        v = xb.z + xrB.z + w * weB.z; v = v > 0.f ? v : 0.2f * v; t += v * atB.z;
        v = xb.w + xrB.w + w * weB.w; v = v > 0.f ? v : 0.2f * v; t += v * atB.w;
        float p0 = wsum(lane < 16 ? t : 0.f);
        float p1 = wsum(lane < 16 ? 0.f : t);
        float ph = (lane < 16) ? p0 : p1;
        float nm = fmaxf(m, ph);
        float sc = __expf(m - nm);      // m=-inf first iter -> 0
        float wg = __expf(ph - nm);
        m = nm;
        den = den * sc + wg;
        acc[0] = acc[0] * sc + wg * xa.x; acc[1] = acc[1] * sc + wg * xa.y;
        acc[2] = acc[2] * sc + wg * xa.z; acc[3] = acc[3] * sc + wg * xa.w;
        acc[4] = acc[4] * sc + wg * xb.x; acc[5] = acc[5] * sc + wg * xb.y;
        acc[6] = acc[6] * sc + wg * xb.z; acc[7] = acc[7] * sc + wg * xb.w;
    }
    float inv = 1.f / (den + 1e-16f);
    float4 bA = *(const float4*)&bias[cb], bB = *(const float4*)&bias[cb + 4];
    float4* po = (float4*)&g_agg1[(long long)n * 256 + cb];
    po[0] = make_float4(acc[0] * inv + bA.x, acc[1] * inv + bA.y,
                        acc[2] * inv + bA.z, acc[3] * inv + bA.w);
    po[1] = make_float4(acc[4] * inv + bB.x, acc[5] * inv + bB.y,
                        acc[6] * inv + bB.z, acc[7] * inv + bB.w);
}

// ---------------- BN1 statistics + finalize ----------------
__global__ void k_bn1_reduce() {
    int c = threadIdx.x;
    float s = 0.f, q = 0.f;
    for (int r = blockIdx.x; r < NN; r += gridDim.x) {
        float v = g_agg1[(long long)r * 256 + c];
        s += v; q += v * v;
    }
    atomicAdd(&g_bn1[c], s);
    atomicAdd(&g_bn1[256 + c], q);
}

__global__ void k_bn1_finalize(const float* __restrict__ g, const float* __restrict__ b) {
    int c = threadIdx.x;
    float mean = g_bn1[c] * (1.f / NN);
    float var  = g_bn1[256 + c] * (1.f / NN) - mean * mean;
    float A = rsqrtf(var + BN_EPS) * g[c];
    float C = b[c] - mean * A;
    g_bn1[c] = A;
    g_bn1[256 + c] = C;
}

// ---------------- fused GEMM (f32x2, dup-A smem): relu(bn(agg1)) @ 4xW ----------
__global__ void __launch_bounds__(256) k_gemm(
        const float* __restrict__ A,
        const float* __restrict__ W0, const float* __restrict__ W1,
        const float* __restrict__ W2, const float* __restrict__ W3,
        const float* __restrict__ b0, const float* __restrict__ b1,
        const float* __restrict__ b2, const float* __restrict__ b3,
        const float* __restrict__ bnA, const float* __restrict__ bnC,
        float* __restrict__ Cout) {
    __shared__ unsigned long long As2[16][128];   // duplicated pairs (a,a)
    __shared__ float Bs[16][128];
    int tid = threadIdx.x;
    int bx = blockIdx.x;              // 0..7 -> 4 weights x 2 col halves
    int by = blockIdx.y;
    int grp = bx >> 1;
    const float* W  = (grp == 0) ? W0 : (grp == 1) ? W1 : (grp == 2) ? W2 : W3;
    const float* bb = (grp == 0) ? b0 : (grp == 1) ? b1 : (grp == 2) ? b2 : b3;
    int jloc = (bx & 1) * 128;
    int rowBase = by * 128;
    int ty = tid >> 4, tx = tid & 15;

    unsigned long long acc[8][4];
#pragma unroll
    for (int i = 0; i < 8; i++)
#pragma unroll
        for (int j = 0; j < 4; j++) acc[i][j] = 0ull;

    for (int k0 = 0; k0 < 256; k0 += 16) {
#pragma unroll
        for (int l = 0; l < 2; l++) {
            int p = tid + l * 256;
            int row = p >> 2, q = p & 3;
            int r = rowBase + row;
            int ccol = k0 + 4 * q;
            float4 v = make_float4(0.f, 0.f, 0.f, 0.f);
            if (r < NN) v = *(const float4*)(A + (long long)r * 256 + ccol);
            float4 sA = *(const float4*)(bnA + ccol);
            float4 sC = *(const float4*)(bnC + ccol);
            As2[4 * q + 0][row] = packdup(fmaxf(v.x * sA.x + sC.x, 0.f));
            As2[4 * q + 1][row] = packdup(fmaxf(v.y * sA.y + sC.y, 0.f));
            As2[4 * q + 2][row] = packdup(fmaxf(v.z * sA.z + sC.z, 0.f));
            As2[4 * q + 3][row] = packdup(fmaxf(v.w * sA.w + sC.w, 0.f));
        }
#pragma unroll
        for (int l = 0; l < 2; l++) {
            int p = tid + l * 256;
            int k = p >> 5, jq = p & 31;
            *(float4*)&Bs[k][4 * jq] = *(const float4*)(W + (long long)(k0 + k) * 256 + jloc + 4 * jq);
        }
        __syncthreads();
#pragma unroll
        for (int kk = 0; kk < 16; kk++) {
            const ulonglong2* ap = (const ulonglong2*)&As2[kk][ty * 8];
            ulonglong2 aA = ap[0], aB = ap[1], aC = ap[2], aD = ap[3];
            unsigned long long a2[8] = {aA.x, aA.y, aB.x, aB.y, aC.x, aC.y, aD.x, aD.y};
            const ulonglong2* bp = (const ulonglong2*)&Bs[kk][tx * 8];
            ulonglong2 bA = bp[0], bB = bp[1];
            unsigned long long b2[4] = {bA.x, bA.y, bB.x, bB.y};
#pragma unroll
            for (int i = 0; i < 8; i++)
#pragma unroll
                for (int j = 0; j < 4; j++) fma2(acc[i][j], a2[i], b2[j]);
        }
        __syncthreads();
    }
    float* outp = Cout + (long long)grp * NN * 256;
    int col = jloc + tx * 8;
    float bias8[8];
#pragma unroll
    for (int j = 0; j < 8; j++) bias8[j] = bb[col + j];
#pragma unroll
    for (int i = 0; i < 8; i++) {
        int r = rowBase + ty * 8 + i;
        if (r < NN) {
            float2 p0 = unpk(acc[i][0]), p1 = unpk(acc[i][1]);
            float2 p2 = unpk(acc[i][2]), p3 = unpk(acc[i][3]);
            float4* po = (float4*)(outp + (long long)r * 256 + col);
            po[0] = make_float4(p0.x + bias8[0], p0.y + bias8[1],
                                p1.x + bias8[2], p1.y + bias8[3]);
            po[1] = make_float4(p2.x + bias8[4], p2.y + bias8[5],
                                p3.x + bias8[6], p3.y + bias8[7]);
        }
    }
}

// ---------------- mu/ls conv: warp-per-node ONLINE softmax, head-mean ------------
__global__ void k_node2h(const float* __restrict__ xl, const float* __restrict__ xr,
                         const float* __restrict__ We, const float* __restrict__ att,
                         const float* __restrict__ bias, float* __restrict__ out) {
    int n = (blockIdx.x * blockDim.x + threadIdx.x) >> 5;
    if (n >= NN) return;
    int lane = threadIdx.x & 31;
    int cb = lane * 8;
    int js = g_rowptr[n], je = g_rowptr[n + 1];
    const float4* pxr = (const float4*)&xr[(long long)n * 256 + cb];
    float4 xrA = pxr[0], xrB = pxr[1];
    float4 weA = *(const float4*)&We[cb],  weB = *(const float4*)&We[cb + 4];
    float4 atA = *(const float4*)&att[cb], atB = *(const float4*)&att[cb + 4];
    float m = NEG_INF, den = 0.f;
    float acc[8] = {0, 0, 0, 0, 0, 0, 0, 0};
    for (int j = js; j < je; j++) {
        int s = g_srcs[j]; float w = g_ews[j];
        const float4* px = (const float4*)&xl[(long long)s * 256 + cb];
        float4 xa = px[0], xb = px[1];
        float t = 0.f, v;
        v = xa.x + xrA.x + w * weA.x; v = v > 0.f ? v : 0.2f * v; t += v * atA.x;
        v = xa.y + xrA.y + w * weA.y; v = v > 0.f ? v : 0.2f * v; t += v * atA.y;
        v = xa.z + xrA.z + w * weA.z; v = v > 0.f ? v : 0.2f * v; t += v * atA.z;
        v = xa.w + xrA.w + w * weA.w; v = v > 0.f ? v : 0.2f * v; t += v * atA.w;
        v = xb.x + xrB.x + w * weB.x; v = v > 0.f ? v : 0.2f * v; t += v * atB.x;
        v = xb.y + xrB.y + w * weB.y; v = v > 0.f ? v : 0.2f * v; t += v * atB.y;
        v = xb.z + xrB.z + w * weB.z; v = v > 0.f ? v : 0.2f * v; t += v * atB.z;
        v = xb.w + xrB.w + w * weB.w; v = v > 0.f ? v : 0.2f * v; t += v * atB.w;
        float p0 = wsum(lane < 16 ? t : 0.f);
        float p1 = wsum(lane < 16 ? 0.f : t);
        float ph = (lane < 16) ? p0 : p1;
        float nm = fmaxf(m, ph);
        float sc = __expf(m - nm);
        float wg = __expf(ph - nm);
        m = nm;
        den = den * sc + wg;
        acc[0] = acc[0] * sc + wg * xa.x; acc[1] = acc[1] * sc + wg * xa.y;
        acc[2] = acc[2] * sc + wg * xa.z; acc[3] = acc[3] * sc + wg * xa.w;
        acc[4] = acc[4] * sc + wg * xb.x; acc[5] = acc[5] * sc + wg * xb.y;
        acc[6] = acc[6] * sc + wg * xb.z; acc[7] = acc[7] * sc + wg * xb.w;
    }
    float inv = 1.f / (den + 1e-16f);
    float r8[8];
#pragma unroll
    for (int k = 0; k < 8; k++) {
        float mine = acc[k] * inv;
        float peer = __shfl_xor_sync(0xffffffffu, mine, 16);
        r8[k] = 0.5f * (mine + peer);
    }
    if (lane < 16) {
        float4 bA = *(const float4*)&bias[cb], bB = *(const float4*)&bias[cb + 4];
        float4* po = (float4*)&out[(long long)n * 128 + cb];
        po[0] = make_float4(r8[0] + bA.x, r8[1] + bA.y, r8[2] + bA.z, r8[3] + bA.w);
        po[1] = make_float4(r8[4] + bB.x, r8[5] + bB.y, r8[6] + bB.z, r8[7] + bB.w);
    }
}

// ---------------- launch ----------------
extern "C" void kernel_launch(void* const* d_in, const int* in_sizes, int n_in,
                              void* d_out, int out_size) {
    const float* h       = (const float*)d_in[0];
    const int*   ei      = (const int*)d_in[1];
    const float* ew      = (const float*)d_in[2];
    const float* bn0_g   = (const float*)d_in[3];
    const float* bn0_b   = (const float*)d_in[4];
    const float* bn1_g   = (const float*)d_in[5];
    const float* bn1_b   = (const float*)d_in[6];
    const float* c1_Wl   = (const float*)d_in[7];
    const float* c1_bl   = (const float*)d_in[8];
    const float* c1_Wr   = (const float*)d_in[9];
    const float* c1_br   = (const float*)d_in[10];
    const float* c1_We   = (const float*)d_in[11];
    const float* c1_att  = (const float*)d_in[12];
    const float* c1_bias = (const float*)d_in[13];
    const float* mu_Wl   = (const float*)d_in[14];
    const float* mu_bl   = (const float*)d_in[15];
    const float* mu_Wr   = (const float*)d_in[16];
    const float* mu_br   = (const float*)d_in[17];
    const float* mu_We   = (const float*)d_in[18];
    const float* mu_att  = (const float*)d_in[19];
    const float* mu_bias = (const float*)d_in[20];
    const float* ls_Wl   = (const float*)d_in[21];
    const float* ls_bl   = (const float*)d_in[22];
    const float* ls_Wr   = (const float*)d_in[23];
    const float* ls_br   = (const float*)d_in[24];
    const float* ls_We   = (const float*)d_in[25];
    const float* ls_att  = (const float*)d_in[26];
    const float* ls_bias = (const float*)d_in[27];
    float* out = (float*)d_out;

    const int* src = ei;
    const int* dst = ei + NE;

    float *x4, *agg1, *bn1;
    cudaGetSymbolAddress((void**)&x4, g_x4);
    cudaGetSymbolAddress((void**)&agg1, g_agg1);
    cudaGetSymbolAddress((void**)&bn1, g_bn1);

    const int TB = 256;
    int eb = (NE + TB - 1) / TB;
    int nodeWarpBlocks = (NN * 32 + TB - 1) / TB;
    int scanBlocks = (NN + 1023) / 1024;   // 49

    k_init<<<128, TB>>>();                                       // 1
    k_bn0_reduce<<<64, TB>>>(h);                                 // 2
    k_hist<<<eb, TB>>>(dst);                                     // 3
    k_lin5<<<(NN + 31) / 32, TB>>>(h, bn0_g, bn0_b,              // 4 (ncu slot)
                                   c1_Wl, c1_bl, c1_Wr, c1_br);
    k_scan1<<<scanBlocks, 1024>>>();                             // 5
    k_scan2<<<1, 64>>>(scanBlocks);                              // 6
    k_scan3<<<scanBlocks, 1024>>>();                             // 7
    k_scatter<<<eb, TB>>>(src, dst, ew);                         // 8

    k_node1<<<nodeWarpBlocks, TB>>>(c1_We, c1_att, c1_bias);     // 9

    k_bn1_reduce<<<512, TB>>>();                                 // 10
    k_bn1_finalize<<<1, TB>>>(bn1_g, bn1_b);                     // 11

    dim3 gg(8, (NN + 127) / 128);
    k_gemm<<<gg, TB>>>(agg1, mu_Wl, mu_Wr, ls_Wl, ls_Wr,         // 12
                       mu_bl, mu_br, ls_bl, ls_br,
                       bn1, bn1 + 256, x4);

    k_node2h<<<nodeWarpBlocks, TB>>>(x4, x4 + (long long)NN * 256,          // 13: mu
                                     mu_We, mu_att, mu_bias, out);
    k_node2h<<<nodeWarpBlocks, TB>>>(x4 + 2ll * NN * 256, x4 + 3ll * NN * 256,  // 14: ls
                                     ls_We, ls_att, ls_bias,
                                     out + (long long)NN * 128);
}

// round 5
// speedup vs baseline: 1.3382x; 1.1310x over previous
#include <cuda_runtime.h>

#define NN 50000
#define NE 300000
#define BN_EPS 1e-5f
#define NEG_INF __int_as_float(0xff800000)

// ---------------- scratch (__device__ globals) ----------------
__device__ float g_xl1[NN * 256];
__device__ float g_xr1[NN * 256];
__device__ float g_x4 [NN * 1024];   // 4 blocks [NN,256]: mu_xl | mu_xr | ls_xl | ls_xr
__device__ float g_agg1[NN * 256];   // conv1 out (+bias), pre-BN
__device__ int   g_cnt [NN];
__device__ int   g_rowptr[NN + 1];
__device__ int   g_cursor[NN];
__device__ int   g_srcs[NE];
__device__ float g_ews [NE];
__device__ int   g_bsum[64];
__device__ int   g_boff[64];
__device__ float g_bn0[12];
__device__ float g_bn1[512];         // sums -> (A scale, C shift)

// ---------------- helpers ----------------
__device__ __forceinline__ float wsum(float v) {
#pragma unroll
    for (int o = 16; o; o >>= 1) v += __shfl_xor_sync(0xffffffffu, v, o);
    return v;
}
__device__ __forceinline__ unsigned long long packdup(float f) {
    unsigned long long r;
    asm("mov.b64 %0, {%1, %1};" : "=l"(r) : "r"(__float_as_uint(f)));
    return r;
}
__device__ __forceinline__ void fma2(unsigned long long& acc,
                                     unsigned long long a, unsigned long long b) {
    asm("fma.rn.f32x2 %0, %1, %2, %0;" : "+l"(acc) : "l"(a), "l"(b));
}
__device__ __forceinline__ float2 unpk(unsigned long long v) {
    unsigned lo, hi;
    asm("mov.b64 {%0, %1}, %2;" : "=r"(lo), "=r"(hi) : "l"(v));
    return make_float2(__uint_as_float(lo), __uint_as_float(hi));
}

// ---------------- init ----------------
__global__ void k_init() {
    int i = blockIdx.x * blockDim.x + threadIdx.x;
    int stride = gridDim.x * blockDim.x;
    for (int t = i; t < NN; t += stride) g_cnt[t] = 0;
    for (int t = i; t < 512; t += stride) g_bn1[t] = 0.f;
    if (i < 12) g_bn0[i] = 0.f;
}

// ---------------- BN0 statistics ----------------
__global__ void k_bn0_reduce(const float* __restrict__ h) {
    float s[5] = {0, 0, 0, 0, 0}, q[5] = {0, 0, 0, 0, 0};
    int stride = gridDim.x * blockDim.x;
    for (int r = blockIdx.x * blockDim.x + threadIdx.x; r < NN; r += stride) {
#pragma unroll
        for (int c = 0; c < 5; c++) { float v = h[r * 5 + c]; s[c] += v; q[c] += v * v; }
    }
#pragma unroll
    for (int off = 16; off; off >>= 1) {
#pragma unroll
        for (int c = 0; c < 5; c++) {
            s[c] += __shfl_xor_sync(0xffffffffu, s[c], off);
            q[c] += __shfl_xor_sync(0xffffffffu, q[c], off);
        }
    }
    if ((threadIdx.x & 31) == 0) {
#pragma unroll
        for (int c = 0; c < 5; c++) {
            atomicAdd(&g_bn0[c], s[c]);
            atomicAdd(&g_bn0[5 + c], q[c]);
        }
    }
}

// ---------------- hist ----------------
__global__ void k_hist(const int* __restrict__ dst) {
    int e = blockIdx.x * blockDim.x + threadIdx.x;
    if (e < NE) atomicAdd(&g_cnt[dst[e]], 1);
}

// ---------------- BN0 apply + conv1 linears ----------------
__global__ void k_lin5(const float* __restrict__ h,
                       const float* __restrict__ bn_g, const float* __restrict__ bn_b,
                       const float* __restrict__ Wl, const float* __restrict__ bl,
                       const float* __restrict__ Wr, const float* __restrict__ br) {
    __shared__ float sWl[5 * 256], sWr[5 * 256];
    __shared__ float sc[5], sh[5];
    int tid = threadIdx.x;
    for (int i = tid; i < 5 * 256; i += blockDim.x) { sWl[i] = Wl[i]; sWr[i] = Wr[i]; }
    if (tid < 5) {
        float mean = g_bn0[tid] * (1.f / NN);
        float var  = g_bn0[5 + tid] * (1.f / NN) - mean * mean;
        float scale = rsqrtf(var + BN_EPS) * bn_g[tid];
        sc[tid] = scale; sh[tid] = bn_b[tid] - mean * scale;
    }
    __syncthreads();
    int j = tid;
    float blj = bl[j], brj = br[j];
    int n0 = blockIdx.x * 32, n1 = min(n0 + 32, NN);
    for (int n = n0; n < n1; n++) {
        float al = blj, ar = brj;
#pragma unroll
        for (int k = 0; k < 5; k++) {
            float x = h[n * 5 + k] * sc[k] + sh[k];
            al += x * sWl[k * 256 + j];
            ar += x * sWr[k * 256 + j];
        }
        g_xl1[(long long)n * 256 + j] = al;
        g_xr1[(long long)n * 256 + j] = ar;
    }
}

// ---------------- CSR scan (3 kernels, coalesced) ----------------
__global__ void k_scan1() {
    __shared__ int sm[1024];
    int t = threadIdx.x;
    int n = blockIdx.x * 1024 + t;
    sm[t] = (n < NN) ? g_cnt[n] : 0;
    __syncthreads();
    for (int off = 512; off; off >>= 1) {
        if (t < off) sm[t] += sm[t + off];
        __syncthreads();
    }
    if (t == 0) g_bsum[blockIdx.x] = sm[0];
}

__global__ void k_scan2(int nblocks) {
    __shared__ int sm[64];
    int t = threadIdx.x;
    int v = (t < nblocks) ? g_bsum[t] : 0;
    sm[t] = v;
    __syncthreads();
    for (int off = 1; off < 64; off <<= 1) {
        int u = (t >= off) ? sm[t - off] : 0;
        __syncthreads();
        sm[t] += u;
        __syncthreads();
    }
    g_boff[t] = sm[t] - v;
    if (t == 0) g_rowptr[NN] = NE;
}

__global__ void k_scan3() {
    __shared__ int sm[1024];
    int t = threadIdx.x;
    int n = blockIdx.x * 1024 + t;
    int v = (n < NN) ? g_cnt[n] : 0;
    sm[t] = v;
    __syncthreads();
    for (int off = 1; off < 1024; off <<= 1) {
        int u = (t >= off) ? sm[t - off] : 0;
        __syncthreads();
        sm[t] += u;
        __syncthreads();
    }
    if (n < NN) {
        int excl = g_boff[blockIdx.x] + sm[t] - v;
        g_rowptr[n] = excl;
        g_cursor[n] = excl;
    }
}

__global__ void k_scatter(const int* __restrict__ src, const int* __restrict__ dst,
                          const float* __restrict__ ew) {
    int e = blockIdx.x * blockDim.x + threadIdx.x;
    if (e < NE) {
        int p = atomicAdd(&g_cursor[dst[e]], 1);
        g_srcs[p] = src[e];
        g_ews[p]  = ew[e];
    }
}

// ---------------- conv1: warp-per-node ONLINE softmax + aggregate ----------------
__global__ void k_node1(const float* __restrict__ We, const float* __restrict__ att,
                        const float* __restrict__ bias) {
    int n = (blockIdx.x * blockDim.x + threadIdx.x) >> 5;
    if (n >= NN) return;
    int lane = threadIdx.x & 31;
    int cb = lane * 8;
    int js = g_rowptr[n], je = g_rowptr[n + 1];
    const float4* pxr = (const float4*)&g_xr1[(long long)n * 256 + cb];
    float4 xrA = pxr[0], xrB = pxr[1];
    float4 weA = *(const float4*)&We[cb],  weB = *(const float4*)&We[cb + 4];
    float4 atA = *(const float4*)&att[cb], atB = *(const float4*)&att[cb + 4];
    float m = NEG_INF, den = 0.f;
    float acc[8] = {0, 0, 0, 0, 0, 0, 0, 0};
    for (int j = js; j < je; j++) {
        int s = g_srcs[j]; float w = g_ews[j];
        const float4* px = (const float4*)&g_xl1[(long long)s * 256 + cb];
        float4 xa = px[0], xb = px[1];
        float t = 0.f, v;
        v = xa.x + xrA.x + w * weA.x; v = v > 0.f ? v : 0.2f * v; t += v * atA.x;
        v = xa.y + xrA.y + w * weA.y; v = v > 0.f ? v : 0.2f * v; t += v * atA.y;
        v = xa.z + xrA.z + w * weA.z; v = v > 0.f ? v : 0.2f * v; t += v * atA.z;
        v = xa.w + xrA.w + w * weA.w; v = v > 0.f ? v : 0.2f * v; t += v * atA.w;
        v = xb.x + xrB.x + w * weB.x; v = v > 0.f ? v : 0.2f * v; t += v * atB.x;
        v = xb.y + xrB.y + w * weB.y; v = v > 0.f ? v : 0.2f * v; t += v * atB.y;
        v = xb.z + xrB.z + w * weB.z; v = v > 0.f ? v : 0.2f * v; t += v * atB.z;
        v = xb.w + xrB.w + w * weB.w; v = v > 0.f ? v : 0.2f * v; t += v * atB.w;
        float p0 = wsum(lane < 16 ? t : 0.f);
        float p1 = wsum(lane < 16 ? 0.f : t);
        float ph = (lane < 16) ? p0 : p1;
        float nm = fmaxf(m, ph);
        float sc = __expf(m - nm);
        float wg = __expf(ph - nm);
        m = nm;
        den = den * sc + wg;
        acc[0] = acc[0] * sc + wg * xa.x; acc[1] = acc[1] * sc + wg * xa.y;
        acc[2] = acc[2] * sc + wg * xa.z; acc[3] = acc[3] * sc + wg * xa.w;
        acc[4] = acc[4] * sc + wg * xb.x; acc[5] = acc[5] * sc + wg * xb.y;
        acc[6] = acc[6] * sc + wg * xb.z; acc[7] = acc[7] * sc + wg * xb.w;
    }
    float inv = 1.f / (den + 1e-16f);
    float4 bA = *(const float4*)&bias[cb], bB = *(const float4*)&bias[cb + 4];
    float4* po = (float4*)&g_agg1[(long long)n * 256 + cb];
    po[0] = make_float4(acc[0] * inv + bA.x, acc[1] * inv + bA.y,
                        acc[2] * inv + bA.z, acc[3] * inv + bA.w);
    po[1] = make_float4(acc[4] * inv + bB.x, acc[5] * inv + bB.y,
                        acc[6] * inv + bB.z, acc[7] * inv + bB.w);
}

// ---------------- BN1 statistics + finalize ----------------
__global__ void k_bn1_reduce() {
    int c = threadIdx.x;
    float s = 0.f, q = 0.f;
    for (int r = blockIdx.x; r < NN; r += gridDim.x) {
        float v = g_agg1[(long long)r * 256 + c];
        s += v; q += v * v;
    }
    atomicAdd(&g_bn1[c], s);
    atomicAdd(&g_bn1[256 + c], q);
}

__global__ void k_bn1_finalize(const float* __restrict__ g, const float* __restrict__ b) {
    int c = threadIdx.x;
    float mean = g_bn1[c] * (1.f / NN);
    float var  = g_bn1[256 + c] * (1.f / NN) - mean * mean;
    float A = rsqrtf(var + BN_EPS) * g[c];
    float C = b[c] - mean * A;
    g_bn1[c] = A;
    g_bn1[256 + c] = C;
}

// ---------------- fused GEMM (f32x2, R3 balanced inner loop) --------------------
// 128x128 block tile, 256 threads, 8x8 per thread: natural-A float smem +
// natural-B u64 pairs + 8 register packdups/kk -> 64 B/thread/kk (LDS==FMA).
__global__ void __launch_bounds__(256) k_gemm(
        const float* __restrict__ A,
        const float* __restrict__ W0, const float* __restrict__ W1,
        const float* __restrict__ W2, const float* __restrict__ W3,
        const float* __restrict__ b0, const float* __restrict__ b1,
        const float* __restrict__ b2, const float* __restrict__ b3,
        const float* __restrict__ bnA, const float* __restrict__ bnC,
        float* __restrict__ Cout) {
    __shared__ float As[16][128];
    __shared__ float Bs[16][128];
    int tid = threadIdx.x;
    int bx = blockIdx.x;              // 0..7 -> 4 weights x 2 col halves
    int by = blockIdx.y;
    int grp = bx >> 1;
    const float* W  = (grp == 0) ? W0 : (grp == 1) ? W1 : (grp == 2) ? W2 : W3;
    const float* bb = (grp == 0) ? b0 : (grp == 1) ? b1 : (grp == 2) ? b2 : b3;
    int jloc = (bx & 1) * 128;
    int rowBase = by * 128;
    int ty = tid >> 4, tx = tid & 15;

    unsigned long long acc[8][4];
#pragma unroll
    for (int i = 0; i < 8; i++)
#pragma unroll
        for (int j = 0; j < 4; j++) acc[i][j] = 0ull;

    for (int k0 = 0; k0 < 256; k0 += 16) {
        // A tile: 128x16, bn+relu applied on load
#pragma unroll
        for (int l = 0; l < 2; l++) {
            int p = tid + l * 256;
            int row = p >> 2, q = p & 3;
            int r = rowBase + row;
            int ccol = k0 + 4 * q;
            float4 v = make_float4(0.f, 0.f, 0.f, 0.f);
            if (r < NN) v = *(const float4*)(A + (long long)r * 256 + ccol);
            float4 sA = *(const float4*)(bnA + ccol);
            float4 sC = *(const float4*)(bnC + ccol);
            As[4 * q + 0][row] = fmaxf(v.x * sA.x + sC.x, 0.f);
            As[4 * q + 1][row] = fmaxf(v.y * sA.y + sC.y, 0.f);
            As[4 * q + 2][row] = fmaxf(v.z * sA.z + sC.z, 0.f);
            As[4 * q + 3][row] = fmaxf(v.w * sA.w + sC.w, 0.f);
        }
        // B tile: 16x128
#pragma unroll
        for (int l = 0; l < 2; l++) {
            int p = tid + l * 256;
            int k = p >> 5, jq = p & 31;
            *(float4*)&Bs[k][4 * jq] = *(const float4*)(W + (long long)(k0 + k) * 256 + jloc + 4 * jq);
        }
        __syncthreads();
#pragma unroll
        for (int kk = 0; kk < 16; kk++) {
            const float4* ap = (const float4*)&As[kk][ty * 8];
            float4 a0 = ap[0], a1 = ap[1];
            unsigned long long a2[8];
            a2[0] = packdup(a0.x); a2[1] = packdup(a0.y);
            a2[2] = packdup(a0.z); a2[3] = packdup(a0.w);
            a2[4] = packdup(a1.x); a2[5] = packdup(a1.y);
            a2[6] = packdup(a1.z); a2[7] = packdup(a1.w);
            const ulonglong2* bp = (const ulonglong2*)&Bs[kk][tx * 8];
            ulonglong2 bA = bp[0], bB = bp[1];
            unsigned long long b2[4] = {bA.x, bA.y, bB.x, bB.y};
#pragma unroll
            for (int i = 0; i < 8; i++)
#pragma unroll
                for (int j = 0; j < 4; j++) fma2(acc[i][j], a2[i], b2[j]);
        }
        __syncthreads();
    }
    float* outp = Cout + (long long)grp * NN * 256;
    int col = jloc + tx * 8;
    float bias8[8];
#pragma unroll
    for (int j = 0; j < 8; j++) bias8[j] = bb[col + j];
#pragma unroll
    for (int i = 0; i < 8; i++) {
        int r = rowBase + ty * 8 + i;
        if (r < NN) {
            float2 p0 = unpk(acc[i][0]), p1 = unpk(acc[i][1]);
            float2 p2 = unpk(acc[i][2]), p3 = unpk(acc[i][3]);
            float4* po = (float4*)(outp + (long long)r * 256 + col);
            po[0] = make_float4(p0.x + bias8[0], p0.y + bias8[1],
                                p1.x + bias8[2], p1.y + bias8[3]);
            po[1] = make_float4(p2.x + bias8[4], p2.y + bias8[5],
                                p3.x + bias8[6], p3.y + bias8[7]);
        }
    }
}

// ---------------- mu/ls conv: warp-per-node ONLINE softmax, head-mean ------------
__global__ void k_node2h(const float* __restrict__ xl, const float* __restrict__ xr,
                         const float* __restrict__ We, const float* __restrict__ att,
                         const float* __restrict__ bias, float* __restrict__ out) {
    int n = (blockIdx.x * blockDim.x + threadIdx.x) >> 5;
    if (n >= NN) return;
    int lane = threadIdx.x & 31;
    int cb = lane * 8;
    int js = g_rowptr[n], je = g_rowptr[n + 1];
    const float4* pxr = (const float4*)&xr[(long long)n * 256 + cb];
    float4 xrA = pxr[0], xrB = pxr[1];
    float4 weA = *(const float4*)&We[cb],  weB = *(const float4*)&We[cb + 4];
    float4 atA = *(const float4*)&att[cb], atB = *(const float4*)&att[cb + 4];
    float m = NEG_INF, den = 0.f;
    float acc[8] = {0, 0, 0, 0, 0, 0, 0, 0};
    for (int j = js; j < je; j++) {
        int s = g_srcs[j]; float w = g_ews[j];
        const float4* px = (const float4*)&xl[(long long)s * 256 + cb];
        float4 xa = px[0], xb = px[1];
        float t = 0.f, v;
        v = xa.x + xrA.x + w * weA.x; v = v > 0.f ? v : 0.2f * v; t += v * atA.x;
        v = xa.y + xrA.y + w * weA.y; v = v > 0.f ? v : 0.2f * v; t += v * atA.y;
        v = xa.z + xrA.z + w * weA.z; v = v > 0.f ? v : 0.2f * v; t += v * atA.z;
        v = xa.w + xrA.w + w * weA.w; v = v > 0.f ? v : 0.2f * v; t += v * atA.w;
        v = xb.x + xrB.x + w * weB.x; v = v > 0.f ? v : 0.2f * v; t += v * atB.x;
        v = xb.y + xrB.y + w * weB.y; v = v > 0.f ? v : 0.2f * v; t += v * atB.y;
        v = xb.z + xrB.z + w * weB.z; v = v > 0.f ? v : 0.2f * v; t += v * atB.z;
        v = xb.w + xrB.w + w * weB.w; v = v > 0.f ? v : 0.2f * v; t += v * atB.w;
        float p0 = wsum(lane < 16 ? t : 0.f);
        float p1 = wsum(lane < 16 ? 0.f : t);
        float ph = (lane < 16) ? p0 : p1;
        float nm = fmaxf(m, ph);
        float sc = __expf(m - nm);
        float wg = __expf(ph - nm);
        m = nm;
        den = den * sc + wg;
        acc[0] = acc[0] * sc + wg * xa.x; acc[1] = acc[1] * sc + wg * xa.y;
        acc[2] = acc[2] * sc + wg * xa.z; acc[3] = acc[3] * sc + wg * xa.w;
        acc[4] = acc[4] * sc + wg * xb.x; acc[5] = acc[5] * sc + wg * xb.y;
        acc[6] = acc[6] * sc + wg * xb.z; acc[7] = acc[7] * sc + wg * xb.w;
    }
    float inv = 1.f / (den + 1e-16f);
    float r8[8];
#pragma unroll
    for (int k = 0; k < 8; k++) {
        float mine = acc[k] * inv;
        float peer = __shfl_xor_sync(0xffffffffu, mine, 16);
        r8[k] = 0.5f * (mine + peer);
    }
    if (lane < 16) {
        float4 bA = *(const float4*)&bias[cb], bB = *(const float4*)&bias[cb + 4];
        float4* po = (float4*)&out[(long long)n * 128 + cb];
        po[0] = make_float4(r8[0] + bA.x, r8[1] + bA.y, r8[2] + bA.z, r8[3] + bA.w);
        po[1] = make_float4(r8[4] + bB.x, r8[5] + bB.y, r8[6] + bB.z, r8[7] + bB.w);
    }
}

// ---------------- launch ----------------
extern "C" void kernel_launch(void* const* d_in, const int* in_sizes, int n_in,
                              void* d_out, int out_size) {
    const float* h       = (const float*)d_in[0];
    const int*   ei      = (const int*)d_in[1];
    const float* ew      = (const float*)d_in[2];
    const float* bn0_g   = (const float*)d_in[3];
    const float* bn0_b   = (const float*)d_in[4];
    const float* bn1_g   = (const float*)d_in[5];
    const float* bn1_b   = (const float*)d_in[6];
    const float* c1_Wl   = (const float*)d_in[7];
    const float* c1_bl   = (const float*)d_in[8];
    const float* c1_Wr   = (const float*)d_in[9];
    const float* c1_br   = (const float*)d_in[10];
    const float* c1_We   = (const float*)d_in[11];
    const float* c1_att  = (const float*)d_in[12];
    const float* c1_bias = (const float*)d_in[13];
    const float* mu_Wl   = (const float*)d_in[14];
    const float* mu_bl   = (const float*)d_in[15];
    const float* mu_Wr   = (const float*)d_in[16];
    const float* mu_br   = (const float*)d_in[17];
    const float* mu_We   = (const float*)d_in[18];
    const float* mu_att  = (const float*)d_in[19];
    const float* mu_bias = (const float*)d_in[20];
    const float* ls_Wl   = (const float*)d_in[21];
    const float* ls_bl   = (const float*)d_in[22];
    const float* ls_Wr   = (const float*)d_in[23];
    const float* ls_br   = (const float*)d_in[24];
    const float* ls_We   = (const float*)d_in[25];
    const float* ls_att  = (const float*)d_in[26];
    const float* ls_bias = (const float*)d_in[27];
    float* out = (float*)d_out;

    const int* src = ei;
    const int* dst = ei + NE;

    float *x4, *agg1, *bn1;
    cudaGetSymbolAddress((void**)&x4, g_x4);
    cudaGetSymbolAddress((void**)&agg1, g_agg1);
    cudaGetSymbolAddress((void**)&bn1, g_bn1);

    const int TB = 256;
    int eb = (NE + TB - 1) / TB;
    int nodeWarpBlocks = (NN * 32 + TB - 1) / TB;
    int scanBlocks = (NN + 1023) / 1024;   // 49

    k_init<<<128, TB>>>();                                       // 1
    k_bn0_reduce<<<64, TB>>>(h);                                 // 2
    k_hist<<<eb, TB>>>(dst);                                     // 3
    k_lin5<<<(NN + 31) / 32, TB>>>(h, bn0_g, bn0_b,              // 4 (ncu slot)
                                   c1_Wl, c1_bl, c1_Wr, c1_br);
    k_scan1<<<scanBlocks, 1024>>>();                             // 5
    k_scan2<<<1, 64>>>(scanBlocks);                              // 6
    k_scan3<<<scanBlocks, 1024>>>();                             // 7
    k_scatter<<<eb, TB>>>(src, dst, ew);                         // 8

    k_node1<<<nodeWarpBlocks, TB>>>(c1_We, c1_att, c1_bias);     // 9

    k_bn1_reduce<<<512, TB>>>();                                 // 10
    k_bn1_finalize<<<1, TB>>>(bn1_g, bn1_b);                     // 11

    dim3 gg(8, (NN + 127) / 128);
    k_gemm<<<gg, TB>>>(agg1, mu_Wl, mu_Wr, ls_Wl, ls_Wr,         // 12
                       mu_bl, mu_br, ls_bl, ls_br,
                       bn1, bn1 + 256, x4);

    k_node2h<<<nodeWarpBlocks, TB>>>(x4, x4 + (long long)NN * 256,          // 13: mu
                                     mu_We, mu_att, mu_bias, out);
    k_node2h<<<nodeWarpBlocks, TB>>>(x4 + 2ll * NN * 256, x4 + 3ll * NN * 256,  // 14: ls
                                     ls_We, ls_att, ls_bias,
                                     out + (long long)NN * 128);
}

// round 7
// speedup vs baseline: 2.1075x; 1.5749x over previous
#include <cuda_runtime.h>
#include <cuda_bf16.h>
#include <cstdint>

#define NN 50000
#define NE 300000
#define BN_EPS 1e-5f
#define NEG_INF __int_as_float(0xff800000)
#define NBLK 391                       // ceil(NN/128)

// ---------------- scratch (__device__ globals) ----------------
__device__ float g_xl1[NN * 256];
__device__ float g_xr1[NN * 256];
__device__ float g_x4 [NN * 1024];   // 4 blocks [NN,256]: mu_xl | mu_xr | ls_xl | ls_xr
__device__ float g_agg1[NN * 256];   // conv1 out (+bias), pre-BN
__device__ int   g_cnt [NN];
__device__ int   g_rowptr[NN + 1];
__device__ int   g_cursor[NN];
__device__ int   g_srcs[NE];
__device__ float g_ews [NE];
__device__ int   g_bsum[64];
__device__ int   g_boff[64];
__device__ float g_bn0[12];
__device__ float g_bn1[512];         // sums -> (A scale, C shift)
// bf16 hi/lo operand planes for the mma.sync GEMM
__device__ unsigned short g_a_hi[NBLK * 128 * 256];   // relu(bn(x1)) hi
__device__ unsigned short g_a_lo[NBLK * 128 * 256];   // residual lo
__device__ unsigned short g_wt_hi[1024 * 256];        // W^T [n][k] hi
__device__ unsigned short g_wt_lo[1024 * 256];

// ---------------- generic helpers ----------------
__device__ __forceinline__ float wsum(float v) {
#pragma unroll
    for (int o = 16; o; o >>= 1) v += __shfl_xor_sync(0xffffffffu, v, o);
    return v;
}
__device__ __forceinline__ uint32_t s2u(const void* p) {
    uint32_t a;
    asm("{ .reg .u64 t; cvta.to.shared.u64 t, %1; cvt.u32.u64 %0, t; }" : "=r"(a) : "l"(p));
    return a;
}
// pack two floats to bf16x2 hi, produce bf16x2 lo residual
__device__ __forceinline__ uint32_t split2(float a, float b, uint32_t& lo) {
    __nv_bfloat16 ha = __float2bfloat16_rn(a), hb = __float2bfloat16_rn(b);
    float ra = a - __bfloat162float(ha), rb = b - __bfloat162float(hb);
    lo = (uint32_t)__bfloat16_as_ushort(__float2bfloat16_rn(ra)) |
         ((uint32_t)__bfloat16_as_ushort(__float2bfloat16_rn(rb)) << 16);
    return (uint32_t)__bfloat16_as_ushort(ha) |
           ((uint32_t)__bfloat16_as_ushort(hb) << 16);
}

#define LDSM4(r, a) \
    asm volatile("ldmatrix.sync.aligned.m8n8.x4.shared.b16 {%0,%1,%2,%3}, [%4];" \
        : "=r"((r)[0]), "=r"((r)[1]), "=r"((r)[2]), "=r"((r)[3]) : "r"(a))
#define MMA(c, a, b) \
    asm volatile("mma.sync.aligned.m16n8k16.row.col.f32.bf16.bf16.f32 " \
        "{%0,%1,%2,%3},{%4,%5,%6,%7},{%8,%9},{%0,%1,%2,%3};" \
        : "+f"((c)[0]), "+f"((c)[1]), "+f"((c)[2]), "+f"((c)[3]) \
        : "r"((a)[0]), "r"((a)[1]), "r"((a)[2]), "r"((a)[3]), "r"((b)[0]), "r"((b)[1]))

// ---------------- init ----------------
__global__ void k_init() {
    int i = blockIdx.x * blockDim.x + threadIdx.x;
    int stride = gridDim.x * blockDim.x;
    for (int t = i; t < NN; t += stride) g_cnt[t] = 0;
    for (int t = i; t < 512; t += stride) g_bn1[t] = 0.f;
    if (i < 12) g_bn0[i] = 0.f;
}

// ---------------- BN0 statistics ----------------
__global__ void k_bn0_reduce(const float* __restrict__ h) {
    float s[5] = {0, 0, 0, 0, 0}, q[5] = {0, 0, 0, 0, 0};
    int stride = gridDim.x * blockDim.x;
    for (int r = blockIdx.x * blockDim.x + threadIdx.x; r < NN; r += stride) {
#pragma unroll
        for (int c = 0; c < 5; c++) { float v = h[r * 5 + c]; s[c] += v; q[c] += v * v; }
    }
#pragma unroll
    for (int off = 16; off; off >>= 1) {
#pragma unroll
        for (int c = 0; c < 5; c++) {
            s[c] += __shfl_xor_sync(0xffffffffu, s[c], off);
            q[c] += __shfl_xor_sync(0xffffffffu, q[c], off);
        }
    }
    if ((threadIdx.x & 31) == 0) {
#pragma unroll
        for (int c = 0; c < 5; c++) {
            atomicAdd(&g_bn0[c], s[c]);
            atomicAdd(&g_bn0[5 + c], q[c]);
        }
    }
}

// ---------------- W prep: transpose to [n][k] bf16 hi/lo ----------------
__global__ void k_prepw(const float* __restrict__ w0, const float* __restrict__ w1,
                        const float* __restrict__ w2, const float* __restrict__ w3) {
    int idx = blockIdx.x * blockDim.x + threadIdx.x;   // 0..65535
    if (idx >= 1024 * 64) return;
    int q = idx >> 10;          // k quad: k = 4q..4q+3
    int j = idx & 1023;         // global n
    int g = j >> 8, jj = j & 255;
    const float* Wg = (g == 0) ? w0 : (g == 1) ? w1 : (g == 2) ? w2 : w3;
    float v0 = Wg[(4 * q + 0) * 256 + jj];
    float v1 = Wg[(4 * q + 1) * 256 + jj];
    float v2 = Wg[(4 * q + 2) * 256 + jj];
    float v3 = Wg[(4 * q + 3) * 256 + jj];
    uint32_t l0, l1;
    uint32_t h0 = split2(v0, v1, l0);
    uint32_t h1 = split2(v2, v3, l1);
    size_t o = (size_t)j * 256 + 4 * q;
    *(uint2*)&g_wt_hi[o] = make_uint2(h0, h1);
    *(uint2*)&g_wt_lo[o] = make_uint2(l0, l1);
}

// ---------------- BN0 apply + conv1 linears ----------------
__global__ void k_lin5(const float* __restrict__ h,
                       const float* __restrict__ bn_g, const float* __restrict__ bn_b,
                       const float* __restrict__ Wl, const float* __restrict__ bl,
                       const float* __restrict__ Wr, const float* __restrict__ br) {
    __shared__ float sWl[5 * 256], sWr[5 * 256];
    __shared__ float sc[5], sh[5];
    int tid = threadIdx.x;
    for (int i = tid; i < 5 * 256; i += blockDim.x) { sWl[i] = Wl[i]; sWr[i] = Wr[i]; }
    if (tid < 5) {
        float mean = g_bn0[tid] * (1.f / NN);
        float var  = g_bn0[5 + tid] * (1.f / NN) - mean * mean;
        float scale = rsqrtf(var + BN_EPS) * bn_g[tid];
        sc[tid] = scale; sh[tid] = bn_b[tid] - mean * scale;
    }
    __syncthreads();
    int j = tid;
    float blj = bl[j], brj = br[j];
    int n0 = blockIdx.x * 32, n1 = min(n0 + 32, NN);
    for (int n = n0; n < n1; n++) {
        float al = blj, ar = brj;
#pragma unroll
        for (int k = 0; k < 5; k++) {
            float x = h[n * 5 + k] * sc[k] + sh[k];
            al += x * sWl[k * 256 + j];
            ar += x * sWr[k * 256 + j];
        }
        g_xl1[(long long)n * 256 + j] = al;
        g_xr1[(long long)n * 256 + j] = ar;
    }
}

// ---------------- hist + CSR scan + scatter ----------------
__global__ void k_hist(const int* __restrict__ dst) {
    int e = blockIdx.x * blockDim.x + threadIdx.x;
    if (e < NE) atomicAdd(&g_cnt[dst[e]], 1);
}

__global__ void k_scan1() {
    __shared__ int sm[1024];
    int t = threadIdx.x;
    int n = blockIdx.x * 1024 + t;
    sm[t] = (n < NN) ? g_cnt[n] : 0;
    __syncthreads();
    for (int off = 512; off; off >>= 1) {
        if (t < off) sm[t] += sm[t + off];
        __syncthreads();
    }
    if (t == 0) g_bsum[blockIdx.x] = sm[0];
}

__global__ void k_scan2(int nblocks) {
    __shared__ int sm[64];
    int t = threadIdx.x;
    int v = (t < nblocks) ? g_bsum[t] : 0;
    sm[t] = v;
    __syncthreads();
    for (int off = 1; off < 64; off <<= 1) {
        int u = (t >= off) ? sm[t - off] : 0;
        __syncthreads();
        sm[t] += u;
        __syncthreads();
    }
    g_boff[t] = sm[t] - v;
    if (t == 0) g_rowptr[NN] = NE;
}

__global__ void k_scan3() {
    __shared__ int sm[1024];
    int t = threadIdx.x;
    int n = blockIdx.x * 1024 + t;
    int v = (n < NN) ? g_cnt[n] : 0;
    sm[t] = v;
    __syncthreads();
    for (int off = 1; off < 1024; off <<= 1) {
        int u = (t >= off) ? sm[t - off] : 0;
        __syncthreads();
        sm[t] += u;
        __syncthreads();
    }
    if (n < NN) {
        int excl = g_boff[blockIdx.x] + sm[t] - v;
        g_rowptr[n] = excl;
        g_cursor[n] = excl;
    }
}

__global__ void k_scatter(const int* __restrict__ src, const int* __restrict__ dst,
                          const float* __restrict__ ew) {
    int e = blockIdx.x * blockDim.x + threadIdx.x;
    if (e < NE) {
        int p = atomicAdd(&g_cursor[dst[e]], 1);
        g_srcs[p] = src[e];
        g_ews[p]  = ew[e];
    }
}

// ---------------- conv1: warp-per-node ONLINE softmax + aggregate ----------------
__global__ void k_node1(const float* __restrict__ We, const float* __restrict__ att,
                        const float* __restrict__ bias) {
    int n = (blockIdx.x * blockDim.x + threadIdx.x) >> 5;
    if (n >= NN) return;
    int lane = threadIdx.x & 31;
    int cb = lane * 8;
    int js = g_rowptr[n], je = g_rowptr[n + 1];
    const float4* pxr = (const float4*)&g_xr1[(long long)n * 256 + cb];
    float4 xrA = pxr[0], xrB = pxr[1];
    float4 weA = *(const float4*)&We[cb],  weB = *(const float4*)&We[cb + 4];
    float4 atA = *(const float4*)&att[cb], atB = *(const float4*)&att[cb + 4];
    float m = NEG_INF, den = 0.f;
    float acc[8] = {0, 0, 0, 0, 0, 0, 0, 0};
    for (int j = js; j < je; j++) {
        int s = g_srcs[j]; float w = g_ews[j];
        const float4* px = (const float4*)&g_xl1[(long long)s * 256 + cb];
        float4 xa = px[0], xb = px[1];
        float t = 0.f, v;
        v = xa.x + xrA.x + w * weA.x; v = v > 0.f ? v : 0.2f * v; t += v * atA.x;
        v = xa.y + xrA.y + w * weA.y; v = v > 0.f ? v : 0.2f * v; t += v * atA.y;
        v = xa.z + xrA.z + w * weA.z; v = v > 0.f ? v : 0.2f * v; t += v * atA.z;
        v = xa.w + xrA.w + w * weA.w; v = v > 0.f ? v : 0.2f * v; t += v * atA.w;
        v = xb.x + xrB.x + w * weB.x; v = v > 0.f ? v : 0.2f * v; t += v * atB.x;
        v = xb.y + xrB.y + w * weB.y; v = v > 0.f ? v : 0.2f * v; t += v * atB.y;
        v = xb.z + xrB.z + w * weB.z; v = v > 0.f ? v : 0.2f * v; t += v * atB.z;
        v = xb.w + xrB.w + w * weB.w; v = v > 0.f ? v : 0.2f * v; t += v * atB.w;
        float p0 = wsum(lane < 16 ? t : 0.f);
        float p1 = wsum(lane < 16 ? 0.f : t);
        float ph = (lane < 16) ? p0 : p1;
        float nm = fmaxf(m, ph);
        float sc = __expf(m - nm);
        float wg = __expf(ph - nm);
        m = nm;
        den = den * sc + wg;
        acc[0] = acc[0] * sc + wg * xa.x; acc[1] = acc[1] * sc + wg * xa.y;
        acc[2] = acc[2] * sc + wg * xa.z; acc[3] = acc[3] * sc + wg * xa.w;
        acc[4] = acc[4] * sc + wg * xb.x; acc[5] = acc[5] * sc + wg * xb.y;
        acc[6] = acc[6] * sc + wg * xb.z; acc[7] = acc[7] * sc + wg * xb.w;
    }
    float inv = 1.f / (den + 1e-16f);
    float4 bA = *(const float4*)&bias[cb], bB = *(const float4*)&bias[cb + 4];
    float4* po = (float4*)&g_agg1[(long long)n * 256 + cb];
    po[0] = make_float4(acc[0] * inv + bA.x, acc[1] * inv + bA.y,
                        acc[2] * inv + bA.z, acc[3] * inv + bA.w);
    po[1] = make_float4(acc[4] * inv + bB.x, acc[5] * inv + bB.y,
                        acc[6] * inv + bB.z, acc[7] * inv + bB.w);
}

// ---------------- BN1 statistics + finalize ----------------
__global__ void k_bn1_reduce() {
    int c = threadIdx.x;
    float s = 0.f, q = 0.f;
    for (int r = blockIdx.x; r < NN; r += gridDim.x) {
        float v = g_agg1[(long long)r * 256 + c];
        s += v; q += v * v;
    }
    atomicAdd(&g_bn1[c], s);
    atomicAdd(&g_bn1[256 + c], q);
}

__global__ void k_bn1_finalize(const float* __restrict__ g, const float* __restrict__ b) {
    int c = threadIdx.x;
    float mean = g_bn1[c] * (1.f / NN);
    float var  = g_bn1[256 + c] * (1.f / NN) - mean * mean;
    float A = rsqrtf(var + BN_EPS) * g[c];
    float C = b[c] - mean * A;
    g_bn1[c] = A;
    g_bn1[256 + c] = C;
}

// ---------------- A prep: BN+ReLU, bf16 hi/lo split (plain layout) --------------
__global__ void k_prepa() {
    int idx = blockIdx.x * blockDim.x + threadIdx.x;   // quad index
    if (idx >= NBLK * 128 * 64) return;
    int r = idx >> 6;
    int q4 = (idx & 63) * 4;
    uint32_t h0 = 0, h1 = 0, l0 = 0, l1 = 0;
    if (r < NN) {
        float4 x = *(const float4*)&g_agg1[(size_t)r * 256 + q4];
        float4 sA = *(const float4*)&g_bn1[q4];
        float4 sC = *(const float4*)&g_bn1[256 + q4];
        float v0 = fmaxf(x.x * sA.x + sC.x, 0.f);
        float v1 = fmaxf(x.y * sA.y + sC.y, 0.f);
        float v2 = fmaxf(x.z * sA.z + sC.z, 0.f);
        float v3 = fmaxf(x.w * sA.w + sC.w, 0.f);
        h0 = split2(v0, v1, l0);
        h1 = split2(v2, v3, l1);
    }
    size_t o = (size_t)r * 256 + q4;
    *(uint2*)&g_a_hi[o] = make_uint2(h0, h1);
    *(uint2*)&g_a_lo[o] = make_uint2(l0, l1);
}

// ---------------- mma.sync GEMM: C[128x128/CTA] = A(hi/lo) @ W^T(hi/lo) ---------
// 8 warps, warp tile 64x32, BK=32, smem rows padded to 40 bf16 (80B)
#define RS 40
__global__ void __launch_bounds__(256) k_gemm_mma(
        const float* __restrict__ b0, const float* __restrict__ b1,
        const float* __restrict__ b2, const float* __restrict__ b3,
        float* __restrict__ Cout) {
    __shared__ __align__(16) unsigned short sAh[128 * RS], sAl[128 * RS];
    __shared__ __align__(16) unsigned short sBh[128 * RS], sBl[128 * RS];
    int tid = threadIdx.x;
    int wid = tid >> 5, lane = tid & 31;
    int bx = blockIdx.x;              // 0..7 -> grp*2 + half
    int by = blockIdx.y;
    int grp = bx >> 1, half = bx & 1;
    const float* bb = (grp == 0) ? b0 : (grp == 1) ? b1 : (grp == 2) ? b2 : b3;
    int warp_m = wid & 1;             // 2 x 64 rows
    int warp_n = wid >> 1;            // 4 x 32 cols

    const unsigned short* gAh = g_a_hi + (size_t)by * 128 * 256;
    const unsigned short* gAl = g_a_lo + (size_t)by * 128 * 256;
    const unsigned short* gBh = g_wt_hi + (size_t)bx * 128 * 256;
    const unsigned short* gBl = g_wt_lo + (size_t)bx * 128 * 256;

    uint32_t aAh = s2u(sAh), aAl = s2u(sAl), aBh = s2u(sBh), aBl = s2u(sBl);
    // ldmatrix lane address components
    int arow = 64 * warp_m + (lane & 15);
    int akb  = (lane >> 4) << 3;
    int brow = 32 * warp_n + (lane & 7) + ((lane >> 4) << 3);
    int bkb  = ((lane >> 3) & 1) << 3;

    float acc[4][4][4];
#pragma unroll
    for (int mi = 0; mi < 4; mi++)
#pragma unroll
        for (int ni = 0; ni < 4; ni++)
#pragma unroll
            for (int r = 0; r < 4; r++) acc[mi][ni][r] = 0.f;

    for (int c = 0; c < 8; c++) {
        int k0 = c * 32;
        __syncthreads();
#pragma unroll
        for (int l = 0; l < 2; l++) {
            int p = tid + l * 256;
            int row = p >> 2, q = p & 3;
            size_t go = (size_t)row * 256 + k0 + 8 * q;
            int so = row * RS + 8 * q;
            *(uint4*)&sAh[so] = *(const uint4*)&gAh[go];
            *(uint4*)&sAl[so] = *(const uint4*)&gAl[go];
            *(uint4*)&sBh[so] = *(const uint4*)&gBh[go];
            *(uint4*)&sBl[so] = *(const uint4*)&gBl[go];
        }
        __syncthreads();
#pragma unroll
        for (int ks = 0; ks < 2; ks++) {
            int kk = ks * 16;
            uint32_t ah[4][4], al[4][4];
#pragma unroll
            for (int mi = 0; mi < 4; mi++) {
                uint32_t ad = aAh + (uint32_t)(((arow + 16 * mi) * RS + kk + akb) * 2);
                LDSM4(ah[mi], ad);
            }
            uint32_t bh[4][2];
#pragma unroll
            for (int nb = 0; nb < 2; nb++) {
                uint32_t r4[4];
                uint32_t ad = aBh + (uint32_t)(((brow + 16 * nb) * RS + kk + bkb) * 2);
                LDSM4(r4, ad);
                bh[2 * nb][0] = r4[0]; bh[2 * nb][1] = r4[1];
                bh[2 * nb + 1][0] = r4[2]; bh[2 * nb + 1][1] = r4[3];
            }
#pragma unroll
            for (int mi = 0; mi < 4; mi++)
#pragma unroll
                for (int ni = 0; ni < 4; ni++) MMA(acc[mi][ni], ah[mi], bh[ni]);
            uint32_t bl_[4][2];
#pragma unroll
            for (int nb = 0; nb < 2; nb++) {
                uint32_t r4[4];
                uint32_t ad = aBl + (uint32_t)(((brow + 16 * nb) * RS + kk + bkb) * 2);
                LDSM4(r4, ad);
                bl_[2 * nb][0] = r4[0]; bl_[2 * nb][1] = r4[1];
                bl_[2 * nb + 1][0] = r4[2]; bl_[2 * nb + 1][1] = r4[3];
            }
#pragma unroll
            for (int mi = 0; mi < 4; mi++)
#pragma unroll
                for (int ni = 0; ni < 4; ni++) MMA(acc[mi][ni], ah[mi], bl_[ni]);
#pragma unroll
            for (int mi = 0; mi < 4; mi++) {
                uint32_t ad = aAl + (uint32_t)(((arow + 16 * mi) * RS + kk + akb) * 2);
                LDSM4(al[mi], ad);
            }
#pragma unroll
            for (int mi = 0; mi < 4; mi++)
#pragma unroll
                for (int ni = 0; ni < 4; ni++) MMA(acc[mi][ni], al[mi], bh[ni]);
        }
    }

    // epilogue: fragment (row = l>>2 [+8], col = (l&3)*2)
    float* outp = Cout + (size_t)grp * NN * 256;
    int rbase = by * 128 + 64 * warp_m + (lane >> 2);
    int cfrag = (lane & 3) * 2;
#pragma unroll
    for (int ni = 0; ni < 4; ni++) {
        int col = 32 * warp_n + 8 * ni + cfrag;
        float bx0 = bb[half * 128 + col], bx1 = bb[half * 128 + col + 1];
#pragma unroll
        for (int mi = 0; mi < 4; mi++) {
            int r0 = rbase + 16 * mi;
            if (r0 < NN)
                *(float2*)&outp[(size_t)r0 * 256 + half * 128 + col] =
                    make_float2(acc[mi][ni][0] + bx0, acc[mi][ni][1] + bx1);
            if (r0 + 8 < NN)
                *(float2*)&outp[(size_t)(r0 + 8) * 256 + half * 128 + col] =
                    make_float2(acc[mi][ni][2] + bx0, acc[mi][ni][3] + bx1);
        }
    }
}

// ---------------- mu/ls conv: warp-per-node ONLINE softmax, head-mean ------------
__global__ void k_node2h(const float* __restrict__ xl, const float* __restrict__ xr,
                         const float* __restrict__ We, const float* __restrict__ att,
                         const float* __restrict__ bias, float* __restrict__ out) {
    int n = (blockIdx.x * blockDim.x + threadIdx.x) >> 5;
    if (n >= NN) return;
    int lane = threadIdx.x & 31;
    int cb = lane * 8;
    int js = g_rowptr[n], je = g_rowptr[n + 1];
    const float4* pxr = (const float4*)&xr[(long long)n * 256 + cb];
    float4 xrA = pxr[0], xrB = pxr[1];
    float4 weA = *(const float4*)&We[cb],  weB = *(const float4*)&We[cb + 4];
    float4 atA = *(const float4*)&att[cb], atB = *(const float4*)&att[cb + 4];
    float m = NEG_INF, den = 0.f;
    float acc[8] = {0, 0, 0, 0, 0, 0, 0, 0};
    for (int j = js; j < je; j++) {
        int s = g_srcs[j]; float w = g_ews[j];
        const float4* px = (const float4*)&xl[(long long)s * 256 + cb];
        float4 xa = px[0], xb = px[1];
        float t = 0.f, v;
        v = xa.x + xrA.x + w * weA.x; v = v > 0.f ? v : 0.2f * v; t += v * atA.x;
        v = xa.y + xrA.y + w * weA.y; v = v > 0.f ? v : 0.2f * v; t += v * atA.y;
        v = xa.z + xrA.z + w * weA.z; v = v > 0.f ? v : 0.2f * v; t += v * atA.z;
        v = xa.w + xrA.w + w * weA.w; v = v > 0.f ? v : 0.2f * v; t += v * atA.w;
        v = xb.x + xrB.x + w * weB.x; v = v > 0.f ? v : 0.2f * v; t += v * atB.x;
        v = xb.y + xrB.y + w * weB.y; v = v > 0.f ? v : 0.2f * v; t += v * atB.y;
        v = xb.z + xrB.z + w * weB.z; v = v > 0.f ? v : 0.2f * v; t += v * atB.z;
        v = xb.w + xrB.w + w * weB.w; v = v > 0.f ? v : 0.2f * v; t += v * atB.w;
        float p0 = wsum(lane < 16 ? t : 0.f);
        float p1 = wsum(lane < 16 ? 0.f : t);
        float ph = (lane < 16) ? p0 : p1;
        float nm = fmaxf(m, ph);
        float sc = __expf(m - nm);
        float wg = __expf(ph - nm);
        m = nm;
        den = den * sc + wg;
        acc[0] = acc[0] * sc + wg * xa.x; acc[1] = acc[1] * sc + wg * xa.y;
        acc[2] = acc[2] * sc + wg * xa.z; acc[3] = acc[3] * sc + wg * xa.w;
        acc[4] = acc[4] * sc + wg * xb.x; acc[5] = acc[5] * sc + wg * xb.y;
        acc[6] = acc[6] * sc + wg * xb.z; acc[7] = acc[7] * sc + wg * xb.w;
    }
    float inv = 1.f / (den + 1e-16f);
    float r8[8];
#pragma unroll
    for (int k = 0; k < 8; k++) {
        float mine = acc[k] * inv;
        float peer = __shfl_xor_sync(0xffffffffu, mine, 16);
        r8[k] = 0.5f * (mine + peer);
    }
    if (lane < 16) {
        float4 bA = *(const float4*)&bias[cb], bB = *(const float4*)&bias[cb + 4];
        float4* po = (float4*)&out[(long long)n * 128 + cb];
        po[0] = make_float4(r8[0] + bA.x, r8[1] + bA.y, r8[2] + bA.z, r8[3] + bA.w);
        po[1] = make_float4(r8[4] + bB.x, r8[5] + bB.y, r8[6] + bB.z, r8[7] + bB.w);
    }
}

// ---------------- launch ----------------
extern "C" void kernel_launch(void* const* d_in, const int* in_sizes, int n_in,
                              void* d_out, int out_size) {
    const float* h       = (const float*)d_in[0];
    const int*   ei      = (const int*)d_in[1];
    const float* ew      = (const float*)d_in[2];
    const float* bn0_g   = (const float*)d_in[3];
    const float* bn0_b   = (const float*)d_in[4];
    const float* bn1_g   = (const float*)d_in[5];
    const float* bn1_b   = (const float*)d_in[6];
    const float* c1_Wl   = (const float*)d_in[7];
    const float* c1_bl   = (const float*)d_in[8];
    const float* c1_Wr   = (const float*)d_in[9];
    const float* c1_br   = (const float*)d_in[10];
    const float* c1_We   = (const float*)d_in[11];
    const float* c1_att  = (const float*)d_in[12];
    const float* c1_bias = (const float*)d_in[13];
    const float* mu_Wl   = (const float*)d_in[14];
    const float* mu_bl   = (const float*)d_in[15];
    const float* mu_Wr   = (const float*)d_in[16];
    const float* mu_br   = (const float*)d_in[17];
    const float* mu_We   = (const float*)d_in[18];
    const float* mu_att  = (const float*)d_in[19];
    const float* mu_bias = (const float*)d_in[20];
    const float* ls_Wl   = (const float*)d_in[21];
    const float* ls_bl   = (const float*)d_in[22];
    const float* ls_Wr   = (const float*)d_in[23];
    const float* ls_br   = (const float*)d_in[24];
    const float* ls_We   = (const float*)d_in[25];
    const float* ls_att  = (const float*)d_in[26];
    const float* ls_bias = (const float*)d_in[27];
    float* out = (float*)d_out;

    const int* src = ei;
    const int* dst = ei + NE;

    float* x4;
    cudaGetSymbolAddress((void**)&x4, g_x4);

    const int TB = 256;
    int eb = (NE + TB - 1) / TB;
    int nodeWarpBlocks = (NN * 32 + TB - 1) / TB;
    int scanBlocks = (NN + 1023) / 1024;   // 49

    k_init<<<128, TB>>>();                                       // 1
    k_bn0_reduce<<<64, TB>>>(h);                                 // 2
    k_prepw<<<(1024 * 64 + TB - 1) / TB, TB>>>(mu_Wl, mu_Wr, ls_Wl, ls_Wr);  // 3
    k_lin5<<<(NN + 31) / 32, TB>>>(h, bn0_g, bn0_b,              // 4 (ncu slot)
                                   c1_Wl, c1_bl, c1_Wr, c1_br);
    k_hist<<<eb, TB>>>(dst);                                     // 5
    k_scan1<<<scanBlocks, 1024>>>();                             // 6
    k_scan2<<<1, 64>>>(scanBlocks);                              // 7
    k_scan3<<<scanBlocks, 1024>>>();                             // 8
    k_scatter<<<eb, TB>>>(src, dst, ew);                         // 9

    k_node1<<<nodeWarpBlocks, TB>>>(c1_We, c1_att, c1_bias);     // 10

    k_bn1_reduce<<<512, TB>>>();                                 // 11
    k_bn1_finalize<<<1, TB>>>(bn1_g, bn1_b);                     // 12

    k_prepa<<<(NBLK * 128 * 64 + TB - 1) / TB, TB>>>();          // 13

    dim3 gg(8, NBLK);
    k_gemm_mma<<<gg, 256>>>(mu_bl, mu_br, ls_bl, ls_br, x4);     // 14

    k_node2h<<<nodeWarpBlocks, TB>>>(x4, x4 + (long long)NN * 256,          // 15: mu
                                     mu_We, mu_att, mu_bias, out);
    k_node2h<<<nodeWarpBlocks, TB>>>(x4 + 2ll * NN * 256, x4 + 3ll * NN * 256,  // 16: ls
                                     ls_We, ls_att, ls_bias,
                                     out + (long long)NN * 128);
}

// round 8
// speedup vs baseline: 2.2271x; 1.0567x over previous
#include <cuda_runtime.h>
#include <cuda_bf16.h>
#include <cstdint>

#define NN 50000
#define NE 300000
#define BN_EPS 1e-5f
#define NEG_INF __int_as_float(0xff800000)
#define NBLK 391                       // ceil(NN/128)

// ---------------- scratch (__device__ globals) ----------------
__device__ float g_xl1[NN * 256];
__device__ float g_xr1[NN * 256];
__device__ float g_x4 [NN * 1024];   // 4 blocks [NN,256]: mu_xl | mu_xr | ls_xl | ls_xr
__device__ float g_agg1[NN * 256];   // conv1 out (+bias), pre-BN
__device__ int   g_cnt [NN];
__device__ int   g_rowptr[NN + 1];
__device__ int   g_cursor[NN];
__device__ int   g_srcs[NE];
__device__ float g_ews [NE];
__device__ int   g_bsum[64];
__device__ int   g_boff[64];
__device__ float g_bn0[12];
__device__ float g_bn1[512];         // sums -> (A scale, C shift)
// bf16 hi/lo operand planes for the mma.sync GEMM
__device__ unsigned short g_a_hi[NBLK * 128 * 256];   // relu(bn(x1)) hi
__device__ unsigned short g_a_lo[NBLK * 128 * 256];   // residual lo
__device__ unsigned short g_wt_hi[1024 * 256];        // W^T [n][k] hi
__device__ unsigned short g_wt_lo[1024 * 256];

// ---------------- generic helpers ----------------
__device__ __forceinline__ float wsum(float v) {
#pragma unroll
    for (int o = 16; o; o >>= 1) v += __shfl_xor_sync(0xffffffffu, v, o);
    return v;
}
__device__ __forceinline__ uint32_t s2u(const void* p) {
    uint32_t a;
    asm("{ .reg .u64 t; cvta.to.shared.u64 t, %1; cvt.u32.u64 %0, t; }" : "=r"(a) : "l"(p));
    return a;
}
// pack two floats to bf16x2 hi, produce bf16x2 lo residual
__device__ __forceinline__ uint32_t split2(float a, float b, uint32_t& lo) {
    __nv_bfloat16 ha = __float2bfloat16_rn(a), hb = __float2bfloat16_rn(b);
    float ra = a - __bfloat162float(ha), rb = b - __bfloat162float(hb);
    lo = (uint32_t)__bfloat16_as_ushort(__float2bfloat16_rn(ra)) |
         ((uint32_t)__bfloat16_as_ushort(__float2bfloat16_rn(rb)) << 16);
    return (uint32_t)__bfloat16_as_ushort(ha) |
           ((uint32_t)__bfloat16_as_ushort(hb) << 16);
}

#define LDSM4(r, a) \
    asm volatile("ldmatrix.sync.aligned.m8n8.x4.shared.b16 {%0,%1,%2,%3}, [%4];" \
        : "=r"((r)[0]), "=r"((r)[1]), "=r"((r)[2]), "=r"((r)[3]) : "r"(a))
#define MMA(c, a, b) \
    asm volatile("mma.sync.aligned.m16n8k16.row.col.f32.bf16.bf16.f32 " \
        "{%0,%1,%2,%3},{%4,%5,%6,%7},{%8,%9},{%0,%1,%2,%3};" \
        : "+f"((c)[0]), "+f"((c)[1]), "+f"((c)[2]), "+f"((c)[3]) \
        : "r"((a)[0]), "r"((a)[1]), "r"((a)[2]), "r"((a)[3]), "r"((b)[0]), "r"((b)[1]))
#define CP16(saddr, gptr) \
    asm volatile("cp.async.ca.shared.global [%0], [%1], 16;" :: "r"(saddr), "l"(gptr) : "memory")

// ---------------- init ----------------
__global__ void k_init() {
    int i = blockIdx.x * blockDim.x + threadIdx.x;
    int stride = gridDim.x * blockDim.x;
    for (int t = i; t < NN; t += stride) g_cnt[t] = 0;
    for (int t = i; t < 512; t += stride) g_bn1[t] = 0.f;
    if (i < 12) g_bn0[i] = 0.f;
}

// ---------------- BN0 statistics ----------------
__global__ void k_bn0_reduce(const float* __restrict__ h) {
    float s[5] = {0, 0, 0, 0, 0}, q[5] = {0, 0, 0, 0, 0};
    int stride = gridDim.x * blockDim.x;
    for (int r = blockIdx.x * blockDim.x + threadIdx.x; r < NN; r += stride) {
#pragma unroll
        for (int c = 0; c < 5; c++) { float v = h[r * 5 + c]; s[c] += v; q[c] += v * v; }
    }
#pragma unroll
    for (int off = 16; off; off >>= 1) {
#pragma unroll
        for (int c = 0; c < 5; c++) {
            s[c] += __shfl_xor_sync(0xffffffffu, s[c], off);
            q[c] += __shfl_xor_sync(0xffffffffu, q[c], off);
        }
    }
    if ((threadIdx.x & 31) == 0) {
#pragma unroll
        for (int c = 0; c < 5; c++) {
            atomicAdd(&g_bn0[c], s[c]);
            atomicAdd(&g_bn0[5 + c], q[c]);
        }
    }
}

// ---------------- W prep: transpose to [n][k] bf16 hi/lo ----------------
__global__ void k_prepw(const float* __restrict__ w0, const float* __restrict__ w1,
                        const float* __restrict__ w2, const float* __restrict__ w3) {
    int idx = blockIdx.x * blockDim.x + threadIdx.x;   // 0..65535
    if (idx >= 1024 * 64) return;
    int q = idx >> 10;          // k quad: k = 4q..4q+3
    int j = idx & 1023;         // global n
    int g = j >> 8, jj = j & 255;
    const float* Wg = (g == 0) ? w0 : (g == 1) ? w1 : (g == 2) ? w2 : w3;
    float v0 = Wg[(4 * q + 0) * 256 + jj];
    float v1 = Wg[(4 * q + 1) * 256 + jj];
    float v2 = Wg[(4 * q + 2) * 256 + jj];
    float v3 = Wg[(4 * q + 3) * 256 + jj];
    uint32_t l0, l1;
    uint32_t h0 = split2(v0, v1, l0);
    uint32_t h1 = split2(v2, v3, l1);
    size_t o = (size_t)j * 256 + 4 * q;
    *(uint2*)&g_wt_hi[o] = make_uint2(h0, h1);
    *(uint2*)&g_wt_lo[o] = make_uint2(l0, l1);
}

// ---------------- BN0 apply + conv1 linears ----------------
__global__ void k_lin5(const float* __restrict__ h,
                       const float* __restrict__ bn_g, const float* __restrict__ bn_b,
                       const float* __restrict__ Wl, const float* __restrict__ bl,
                       const float* __restrict__ Wr, const float* __restrict__ br) {
    __shared__ float sWl[5 * 256], sWr[5 * 256];
    __shared__ float sc[5], sh[5];
    int tid = threadIdx.x;
    for (int i = tid; i < 5 * 256; i += blockDim.x) { sWl[i] = Wl[i]; sWr[i] = Wr[i]; }
    if (tid < 5) {
        float mean = g_bn0[tid] * (1.f / NN);
        float var  = g_bn0[5 + tid] * (1.f / NN) - mean * mean;
        float scale = rsqrtf(var + BN_EPS) * bn_g[tid];
        sc[tid] = scale; sh[tid] = bn_b[tid] - mean * scale;
    }
    __syncthreads();
    int j = tid;
    float blj = bl[j], brj = br[j];
    int n0 = blockIdx.x * 32, n1 = min(n0 + 32, NN);
    for (int n = n0; n < n1; n++) {
        float al = blj, ar = brj;
#pragma unroll
        for (int k = 0; k < 5; k++) {
            float x = h[n * 5 + k] * sc[k] + sh[k];
            al += x * sWl[k * 256 + j];
            ar += x * sWr[k * 256 + j];
        }
        g_xl1[(long long)n * 256 + j] = al;
        g_xr1[(long long)n * 256 + j] = ar;
    }
}

// ---------------- hist + CSR scan + scatter ----------------
__global__ void k_hist(const int* __restrict__ dst) {
    int e = blockIdx.x * blockDim.x + threadIdx.x;
    if (e < NE) atomicAdd(&g_cnt[dst[e]], 1);
}

__global__ void k_scan1() {
    __shared__ int sm[1024];
    int t = threadIdx.x;
    int n = blockIdx.x * 1024 + t;
    sm[t] = (n < NN) ? g_cnt[n] : 0;
    __syncthreads();
    for (int off = 512; off; off >>= 1) {
        if (t < off) sm[t] += sm[t + off];
        __syncthreads();
    }
    if (t == 0) g_bsum[blockIdx.x] = sm[0];
}

__global__ void k_scan2(int nblocks) {
    __shared__ int sm[64];
    int t = threadIdx.x;
    int v = (t < nblocks) ? g_bsum[t] : 0;
    sm[t] = v;
    __syncthreads();
    for (int off = 1; off < 64; off <<= 1) {
        int u = (t >= off) ? sm[t - off] : 0;
        __syncthreads();
        sm[t] += u;
        __syncthreads();
    }
    g_boff[t] = sm[t] - v;
    if (t == 0) g_rowptr[NN] = NE;
}

__global__ void k_scan3() {
    __shared__ int sm[1024];
    int t = threadIdx.x;
    int n = blockIdx.x * 1024 + t;
    int v = (n < NN) ? g_cnt[n] : 0;
    sm[t] = v;
    __syncthreads();
    for (int off = 1; off < 1024; off <<= 1) {
        int u = (t >= off) ? sm[t - off] : 0;
        __syncthreads();
        sm[t] += u;
        __syncthreads();
    }
    if (n < NN) {
        int excl = g_boff[blockIdx.x] + sm[t] - v;
        g_rowptr[n] = excl;
        g_cursor[n] = excl;
    }
}

__global__ void k_scatter(const int* __restrict__ src, const int* __restrict__ dst,
                          const float* __restrict__ ew) {
    int e = blockIdx.x * blockDim.x + threadIdx.x;
    if (e < NE) {
        int p = atomicAdd(&g_cursor[dst[e]], 1);
        g_srcs[p] = src[e];
        g_ews[p]  = ew[e];
    }
}

// ---------------- conv1: warp-per-node ONLINE softmax + aggregate ----------------
__global__ void k_node1(const float* __restrict__ We, const float* __restrict__ att,
                        const float* __restrict__ bias) {
    int n = (blockIdx.x * blockDim.x + threadIdx.x) >> 5;
    if (n >= NN) return;
    int lane = threadIdx.x & 31;
    int cb = lane * 8;
    int js = g_rowptr[n], je = g_rowptr[n + 1];
    const float4* pxr = (const float4*)&g_xr1[(long long)n * 256 + cb];
    float4 xrA = pxr[0], xrB = pxr[1];
    float4 weA = *(const float4*)&We[cb],  weB = *(const float4*)&We[cb + 4];
    float4 atA = *(const float4*)&att[cb], atB = *(const float4*)&att[cb + 4];
    float m = NEG_INF, den = 0.f;
    float acc[8] = {0, 0, 0, 0, 0, 0, 0, 0};
    for (int j = js; j < je; j++) {
        int s = g_srcs[j]; float w = g_ews[j];
        const float4* px = (const float4*)&g_xl1[(long long)s * 256 + cb];
        float4 xa = px[0], xb = px[1];
        float t = 0.f, v;
        v = xa.x + xrA.x + w * weA.x; v = v > 0.f ? v : 0.2f * v; t += v * atA.x;
        v = xa.y + xrA.y + w * weA.y; v = v > 0.f ? v : 0.2f * v; t += v * atA.y;
        v = xa.z + xrA.z + w * weA.z; v = v > 0.f ? v : 0.2f * v; t += v * atA.z;
        v = xa.w + xrA.w + w * weA.w; v = v > 0.f ? v : 0.2f * v; t += v * atA.w;
        v = xb.x + xrB.x + w * weB.x; v = v > 0.f ? v : 0.2f * v; t += v * atB.x;
        v = xb.y + xrB.y + w * weB.y; v = v > 0.f ? v : 0.2f * v; t += v * atB.y;
        v = xb.z + xrB.z + w * weB.z; v = v > 0.f ? v : 0.2f * v; t += v * atB.z;
        v = xb.w + xrB.w + w * weB.w; v = v > 0.f ? v : 0.2f * v; t += v * atB.w;
        float p0 = wsum(lane < 16 ? t : 0.f);
        float p1 = wsum(lane < 16 ? 0.f : t);
        float ph = (lane < 16) ? p0 : p1;
        float nm = fmaxf(m, ph);
        float sc = __expf(m - nm);
        float wg = __expf(ph - nm);
        m = nm;
        den = den * sc + wg;
        acc[0] = acc[0] * sc + wg * xa.x; acc[1] = acc[1] * sc + wg * xa.y;
        acc[2] = acc[2] * sc + wg * xa.z; acc[3] = acc[3] * sc + wg * xa.w;
        acc[4] = acc[4] * sc + wg * xb.x; acc[5] = acc[5] * sc + wg * xb.y;
        acc[6] = acc[6] * sc + wg * xb.z; acc[7] = acc[7] * sc + wg * xb.w;
    }
    float inv = 1.f / (den + 1e-16f);
    float4 bA = *(const float4*)&bias[cb], bB = *(const float4*)&bias[cb + 4];
    float4* po = (float4*)&g_agg1[(long long)n * 256 + cb];
    po[0] = make_float4(acc[0] * inv + bA.x, acc[1] * inv + bA.y,
                        acc[2] * inv + bA.z, acc[3] * inv + bA.w);
    po[1] = make_float4(acc[4] * inv + bB.x, acc[5] * inv + bB.y,
                        acc[6] * inv + bB.z, acc[7] * inv + bB.w);
}

// ---------------- BN1 statistics + finalize ----------------
__global__ void k_bn1_reduce() {
    int c = threadIdx.x;
    float s = 0.f, q = 0.f;
    for (int r = blockIdx.x; r < NN; r += gridDim.x) {
        float v = g_agg1[(long long)r * 256 + c];
        s += v; q += v * v;
    }
    atomicAdd(&g_bn1[c], s);
    atomicAdd(&g_bn1[256 + c], q);
}

__global__ void k_bn1_finalize(const float* __restrict__ g, const float* __restrict__ b) {
    int c = threadIdx.x;
    float mean = g_bn1[c] * (1.f / NN);
    float var  = g_bn1[256 + c] * (1.f / NN) - mean * mean;
    float A = rsqrtf(var + BN_EPS) * g[c];
    float C = b[c] - mean * A;
    g_bn1[c] = A;
    g_bn1[256 + c] = C;
}

// ---------------- A prep: BN+ReLU, bf16 hi/lo split (plain layout) --------------
__global__ void k_prepa() {
    int idx = blockIdx.x * blockDim.x + threadIdx.x;   // quad index
    if (idx >= NBLK * 128 * 64) return;
    int r = idx >> 6;
    int q4 = (idx & 63) * 4;
    uint32_t h0 = 0, h1 = 0, l0 = 0, l1 = 0;
    if (r < NN) {
        float4 x = *(const float4*)&g_agg1[(size_t)r * 256 + q4];
        float4 sA = *(const float4*)&g_bn1[q4];
        float4 sC = *(const float4*)&g_bn1[256 + q4];
        float v0 = fmaxf(x.x * sA.x + sC.x, 0.f);
        float v1 = fmaxf(x.y * sA.y + sC.y, 0.f);
        float v2 = fmaxf(x.z * sA.z + sC.z, 0.f);
        float v3 = fmaxf(x.w * sA.w + sC.w, 0.f);
        h0 = split2(v0, v1, l0);
        h1 = split2(v2, v3, l1);
    }
    size_t o = (size_t)r * 256 + q4;
    *(uint2*)&g_a_hi[o] = make_uint2(h0, h1);
    *(uint2*)&g_a_lo[o] = make_uint2(l0, l1);
}

// ---------------- mma.sync GEMM with 2-stage cp.async pipeline -------------------
// 8 warps, warp tile 64x32, BK=32, smem rows padded to 40 bf16 (80B)
#define RS 40
#define PLN (128 * RS * 2)             // 10240 B per plane
__global__ void __launch_bounds__(256) k_gemm_mma(
        const float* __restrict__ b0, const float* __restrict__ b1,
        const float* __restrict__ b2, const float* __restrict__ b3,
        float* __restrict__ Cout) {
    extern __shared__ __align__(16) char dsm[];
    uint32_t sb = s2u(dsm);
    int tid = threadIdx.x;
    int wid = tid >> 5, lane = tid & 31;
    int bx = blockIdx.x;              // 0..7 -> grp*2 + half
    int by = blockIdx.y;
    int grp = bx >> 1, half = bx & 1;
    const float* bb = (grp == 0) ? b0 : (grp == 1) ? b1 : (grp == 2) ? b2 : b3;
    int warp_m = wid & 1;             // 2 x 64 rows
    int warp_n = wid >> 1;            // 4 x 32 cols

    const unsigned short* gAh = g_a_hi + (size_t)by * 128 * 256;
    const unsigned short* gAl = g_a_lo + (size_t)by * 128 * 256;
    const unsigned short* gBh = g_wt_hi + (size_t)bx * 128 * 256;
    const unsigned short* gBl = g_wt_lo + (size_t)bx * 128 * 256;

    // ldmatrix lane address components
    int arow = 64 * warp_m + (lane & 15);
    int akb  = (lane >> 4) << 3;
    int brow = 32 * warp_n + (lane & 7) + ((lane >> 4) << 3);
    int bkb  = ((lane >> 3) & 1) << 3;
    // cp.async granule for this thread
    int grow0 = tid >> 2, gq0 = (tid & 3) * 8;
    int grow1 = (tid + 256) >> 2, gq1 = ((tid + 256) & 3) * 8;

    float acc[4][4][4];
#pragma unroll
    for (int mi = 0; mi < 4; mi++)
#pragma unroll
        for (int ni = 0; ni < 4; ni++)
#pragma unroll
            for (int r = 0; r < 4; r++) acc[mi][ni][r] = 0.f;

    // pipeline issue helper (macro to keep immediates)
#define ISSUE(stage, cc) do { \
        int k0_ = (cc) * 32; \
        uint32_t base_ = sb + (stage) * 4 * PLN; \
        uint32_t d0_ = base_ + (uint32_t)(grow0 * RS + gq0) * 2; \
        uint32_t d1_ = base_ + (uint32_t)(grow1 * RS + gq1) * 2; \
        size_t s0_ = (size_t)grow0 * 256 + k0_ + gq0; \
        size_t s1_ = (size_t)grow1 * 256 + k0_ + gq1; \
        CP16(d0_,           gAh + s0_); CP16(d1_,           gAh + s1_); \
        CP16(d0_ + PLN,     gAl + s0_); CP16(d1_ + PLN,     gAl + s1_); \
        CP16(d0_ + 2 * PLN, gBh + s0_); CP16(d1_ + 2 * PLN, gBh + s1_); \
        CP16(d0_ + 3 * PLN, gBl + s0_); CP16(d1_ + 3 * PLN, gBl + s1_); \
        asm volatile("cp.async.commit_group;" ::: "memory"); \
    } while (0)

    ISSUE(0, 0);
    for (int c = 0; c < 8; c++) {
        if (c + 1 < 8) {
            ISSUE((c + 1) & 1, c + 1);
            asm volatile("cp.async.wait_group 1;" ::: "memory");
        } else {
            asm volatile("cp.async.wait_group 0;" ::: "memory");
        }
        __syncthreads();
        uint32_t aAh = sb + (c & 1) * 4 * PLN;
        uint32_t aAl = aAh + PLN, aBh = aAh + 2 * PLN, aBl = aAh + 3 * PLN;
#pragma unroll
        for (int ks = 0; ks < 2; ks++) {
            int kk = ks * 16;
            uint32_t ah[4][4], al[4][4];
#pragma unroll
            for (int mi = 0; mi < 4; mi++) {
                uint32_t ad = aAh + (uint32_t)(((arow + 16 * mi) * RS + kk + akb) * 2);
                LDSM4(ah[mi], ad);
            }
            uint32_t bh[4][2];
#pragma unroll
            for (int nb = 0; nb < 2; nb++) {
                uint32_t r4[4];
                uint32_t ad = aBh + (uint32_t)(((brow + 16 * nb) * RS + kk + bkb) * 2);
                LDSM4(r4, ad);
                bh[2 * nb][0] = r4[0]; bh[2 * nb][1] = r4[1];
                bh[2 * nb + 1][0] = r4[2]; bh[2 * nb + 1][1] = r4[3];
            }
#pragma unroll
            for (int mi = 0; mi < 4; mi++)
#pragma unroll
                for (int ni = 0; ni < 4; ni++) MMA(acc[mi][ni], ah[mi], bh[ni]);
            uint32_t bl_[4][2];
#pragma unroll
            for (int nb = 0; nb < 2; nb++) {
                uint32_t r4[4];
                uint32_t ad = aBl + (uint32_t)(((brow + 16 * nb) * RS + kk + bkb) * 2);
                LDSM4(r4, ad);
                bl_[2 * nb][0] = r4[0]; bl_[2 * nb][1] = r4[1];
                bl_[2 * nb + 1][0] = r4[2]; bl_[2 * nb + 1][1] = r4[3];
            }
#pragma unroll
            for (int mi = 0; mi < 4; mi++)
#pragma unroll
                for (int ni = 0; ni < 4; ni++) MMA(acc[mi][ni], ah[mi], bl_[ni]);
#pragma unroll
            for (int mi = 0; mi < 4; mi++) {
                uint32_t ad = aAl + (uint32_t)(((arow + 16 * mi) * RS + kk + akb) * 2);
                LDSM4(al[mi], ad);
            }
#pragma unroll
            for (int mi = 0; mi < 4; mi++)
#pragma unroll
                for (int ni = 0; ni < 4; ni++) MMA(acc[mi][ni], al[mi], bh[ni]);
        }
        __syncthreads();   // stage reuse barrier
    }

    // epilogue: fragment (row = l>>2 [+8], col = (l&3)*2)
    float* outp = Cout + (size_t)grp * NN * 256;
    int rbase = by * 128 + 64 * warp_m + (lane >> 2);
    int cfrag = (lane & 3) * 2;
#pragma unroll
    for (int ni = 0; ni < 4; ni++) {
        int col = 32 * warp_n + 8 * ni + cfrag;
        float bx0 = bb[half * 128 + col], bx1 = bb[half * 128 + col + 1];
#pragma unroll
        for (int mi = 0; mi < 4; mi++) {
            int r0 = rbase + 16 * mi;
            if (r0 < NN)
                *(float2*)&outp[(size_t)r0 * 256 + half * 128 + col] =
                    make_float2(acc[mi][ni][0] + bx0, acc[mi][ni][1] + bx1);
            if (r0 + 8 < NN)
                *(float2*)&outp[(size_t)(r0 + 8) * 256 + half * 128 + col] =
                    make_float2(acc[mi][ni][2] + bx0, acc[mi][ni][3] + bx1);
        }
    }
}

// ---------------- mu/ls conv: warp-per-node ONLINE softmax, head-mean ------------
__global__ void k_node2h(const float* __restrict__ xl, const float* __restrict__ xr,
                         const float* __restrict__ We, const float* __restrict__ att,
                         const float* __restrict__ bias, float* __restrict__ out) {
    int n = (blockIdx.x * blockDim.x + threadIdx.x) >> 5;
    if (n >= NN) return;
    int lane = threadIdx.x & 31;
    int cb = lane * 8;
    int js = g_rowptr[n], je = g_rowptr[n + 1];
    const float4* pxr = (const float4*)&xr[(long long)n * 256 + cb];
    float4 xrA = pxr[0], xrB = pxr[1];
    float4 weA = *(const float4*)&We[cb],  weB = *(const float4*)&We[cb + 4];
    float4 atA = *(const float4*)&att[cb], atB = *(const float4*)&att[cb + 4];
    float m = NEG_INF, den = 0.f;
    float acc[8] = {0, 0, 0, 0, 0, 0, 0, 0};
    for (int j = js; j < je; j++) {
        int s = g_srcs[j]; float w = g_ews[j];
        const float4* px = (const float4*)&xl[(long long)s * 256 + cb];
        float4 xa = px[0], xb = px[1];
        float t = 0.f, v;
        v = xa.x + xrA.x + w * weA.x; v = v > 0.f ? v : 0.2f * v; t += v * atA.x;
        v = xa.y + xrA.y + w * weA.y; v = v > 0.f ? v : 0.2f * v; t += v * atA.y;
        v = xa.z + xrA.z + w * weA.z; v = v > 0.f ? v : 0.2f * v; t += v * atA.z;
        v = xa.w + xrA.w + w * weA.w; v = v > 0.f ? v : 0.2f * v; t += v * atA.w;
        v = xb.x + xrB.x + w * weB.x; v = v > 0.f ? v : 0.2f * v; t += v * atB.x;
        v = xb.y + xrB.y + w * weB.y; v = v > 0.f ? v : 0.2f * v; t += v * atB.y;
        v = xb.z + xrB.z + w * weB.z; v = v > 0.f ? v : 0.2f * v; t += v * atB.z;
        v = xb.w + xrB.w + w * weB.w; v = v > 0.f ? v : 0.2f * v; t += v * atB.w;
        float p0 = wsum(lane < 16 ? t : 0.f);
        float p1 = wsum(lane < 16 ? 0.f : t);
        float ph = (lane < 16) ? p0 : p1;
        float nm = fmaxf(m, ph);
        float sc = __expf(m - nm);
        float wg = __expf(ph - nm);
        m = nm;
        den = den * sc + wg;
        acc[0] = acc[0] * sc + wg * xa.x; acc[1] = acc[1] * sc + wg * xa.y;
        acc[2] = acc[2] * sc + wg * xa.z; acc[3] = acc[3] * sc + wg * xa.w;
        acc[4] = acc[4] * sc + wg * xb.x; acc[5] = acc[5] * sc + wg * xb.y;
        acc[6] = acc[6] * sc + wg * xb.z; acc[7] = acc[7] * sc + wg * xb.w;
    }
    float inv = 1.f / (den + 1e-16f);
    float r8[8];
#pragma unroll
    for (int k = 0; k < 8; k++) {
        float mine = acc[k] * inv;
        float peer = __shfl_xor_sync(0xffffffffu, mine, 16);
        r8[k] = 0.5f * (mine + peer);
    }
    if (lane < 16) {
        float4 bA = *(const float4*)&bias[cb], bB = *(const float4*)&bias[cb + 4];
        float4* po = (float4*)&out[(long long)n * 128 + cb];
        po[0] = make_float4(r8[0] + bA.x, r8[1] + bA.y, r8[2] + bA.z, r8[3] + bA.w);
        po[1] = make_float4(r8[4] + bB.x, r8[5] + bB.y, r8[6] + bB.z, r8[7] + bB.w);
    }
}

// ---------------- launch ----------------
extern "C" void kernel_launch(void* const* d_in, const int* in_sizes, int n_in,
                              void* d_out, int out_size) {
    const float* h       = (const float*)d_in[0];
    const int*   ei      = (const int*)d_in[1];
    const float* ew      = (const float*)d_in[2];
    const float* bn0_g   = (const float*)d_in[3];
    const float* bn0_b   = (const float*)d_in[4];
    const float* bn1_g   = (const float*)d_in[5];
    const float* bn1_b   = (const float*)d_in[6];
    const float* c1_Wl   = (const float*)d_in[7];
    const float* c1_bl   = (const float*)d_in[8];
    const float* c1_Wr   = (const float*)d_in[9];
    const float* c1_br   = (const float*)d_in[10];
    const float* c1_We   = (const float*)d_in[11];
    const float* c1_att  = (const float*)d_in[12];
    const float* c1_bias = (const float*)d_in[13];
    const float* mu_Wl   = (const float*)d_in[14];
    const float* mu_bl   = (const float*)d_in[15];
    const float* mu_Wr   = (const float*)d_in[16];
    const float* mu_br   = (const float*)d_in[17];
    const float* mu_We   = (const float*)d_in[18];
    const float* mu_att  = (const float*)d_in[19];
    const float* mu_bias = (const float*)d_in[20];
    const float* ls_Wl   = (const float*)d_in[21];
    const float* ls_bl   = (const float*)d_in[22];
    const float* ls_Wr   = (const float*)d_in[23];
    const float* ls_br   = (const float*)d_in[24];
    const float* ls_We   = (const float*)d_in[25];
    const float* ls_att  = (const float*)d_in[26];
    const float* ls_bias = (const float*)d_in[27];
    float* out = (float*)d_out;

    const int* src = ei;
    const int* dst = ei + NE;

    float* x4;
    cudaGetSymbolAddress((void**)&x4, g_x4);

    const int TB = 256;
    int eb = (NE + TB - 1) / TB;
    int nodeWarpBlocks = (NN * 32 + TB - 1) / TB;
    int scanBlocks = (NN + 1023) / 1024;   // 49
    const int GEMM_SMEM = 8 * PLN;         // 81920 B

    cudaFuncSetAttribute(k_gemm_mma, cudaFuncAttributeMaxDynamicSharedMemorySize, GEMM_SMEM);

    k_init<<<128, TB>>>();                                       // 1
    k_bn0_reduce<<<64, TB>>>(h);                                 // 2
    k_prepw<<<(1024 * 64 + TB - 1) / TB, TB>>>(mu_Wl, mu_Wr, ls_Wl, ls_Wr);  // 3
    k_lin5<<<(NN + 31) / 32, TB>>>(h, bn0_g, bn0_b,              // 4 (ncu slot)
                                   c1_Wl, c1_bl, c1_Wr, c1_br);
    k_hist<<<eb, TB>>>(dst);                                     // 5
    k_scan1<<<scanBlocks, 1024>>>();                             // 6
    k_scan2<<<1, 64>>>(scanBlocks);                              // 7
    k_scan3<<<scanBlocks, 1024>>>();                             // 8
    k_scatter<<<eb, TB>>>(src, dst, ew);                         // 9

    k_node1<<<nodeWarpBlocks, TB>>>(c1_We, c1_att, c1_bias);     // 10

    k_bn1_reduce<<<512, TB>>>();                                 // 11
    k_bn1_finalize<<<1, TB>>>(bn1_g, bn1_b);                     // 12

    k_prepa<<<(NBLK * 128 * 64 + TB - 1) / TB, TB>>>();          // 13

    dim3 gg(8, NBLK);
    k_gemm_mma<<<gg, 256, GEMM_SMEM>>>(mu_bl, mu_br, ls_bl, ls_br, x4);  // 14

    k_node2h<<<nodeWarpBlocks, TB>>>(x4, x4 + (long long)NN * 256,          // 15: mu
                                     mu_We, mu_att, mu_bias, out);
    k_node2h<<<nodeWarpBlocks, TB>>>(x4 + 2ll * NN * 256, x4 + 3ll * NN * 256,  // 16: ls
                                     ls_We, ls_att, ls_bias,
                                     out + (long long)NN * 128);
}

// round 10
// speedup vs baseline: 2.4222x; 1.0876x over previous
#include <cuda_runtime.h>
#include <cuda_bf16.h>
#include <cstdint>

#define NN 50000
#define NE 300000
#define BN_EPS 1e-5f
#define NEG_INF __int_as_float(0xff800000)
#define NBLK 391                       // ceil(NN/128)

// ---------------- scratch (__device__ globals) ----------------
__device__ float g_xl1[NN * 256];
__device__ float g_xr1[NN * 256];
__device__ float g_x4 [NN * 1024];   // 4 blocks [NN,256]: mu_xl | mu_xr | ls_xl | ls_xr
__device__ float g_agg1[NN * 256];   // conv1 out (+bias), pre-BN
__device__ int   g_cnt [NN];
__device__ int   g_rowptr[NN + 1];
__device__ int   g_cursor[NN];
__device__ int   g_srcs[NE];
__device__ float g_ews [NE];
__device__ int   g_bsum[64];
__device__ int   g_boff[64];
__device__ float g_bn0[12];
__device__ float g_bn1[512];         // channel sums / sumsq
// bf16 hi/lo operand planes for the mma.sync GEMM
__device__ unsigned short g_a_hi[NBLK * 128 * 256];   // relu(bn(x1)) hi
__device__ unsigned short g_a_lo[NBLK * 128 * 256];   // residual lo
__device__ unsigned short g_wt_hi[1024 * 256];        // W^T [n][k] hi
__device__ unsigned short g_wt_lo[1024 * 256];

// ---------------- generic helpers ----------------
__device__ __forceinline__ float wsum(float v) {
#pragma unroll
    for (int o = 16; o; o >>= 1) v += __shfl_xor_sync(0xffffffffu, v, o);
    return v;
}
// butterfly over 16-lane halves: lanes 0-15 end with sum(lanes 0-15), 16-31 with sum(16-31)
__device__ __forceinline__ float hsum(float v) {
#pragma unroll
    for (int o = 8; o; o >>= 1) v += __shfl_xor_sync(0xffffffffu, v, o);
    return v;
}
__device__ __forceinline__ uint32_t s2u(const void* p) {
    uint32_t a;
    asm("{ .reg .u64 t; cvta.to.shared.u64 t, %1; cvt.u32.u64 %0, t; }" : "=r"(a) : "l"(p));
    return a;
}
// pack two floats to bf16x2 hi, produce bf16x2 lo residual
__device__ __forceinline__ uint32_t split2(float a, float b, uint32_t& lo) {
    __nv_bfloat16 ha = __float2bfloat16_rn(a), hb = __float2bfloat16_rn(b);
    float ra = a - __bfloat162float(ha), rb = b - __bfloat162float(hb);
    lo = (uint32_t)__bfloat16_as_ushort(__float2bfloat16_rn(ra)) |
         ((uint32_t)__bfloat16_as_ushort(__float2bfloat16_rn(rb)) << 16);
    return (uint32_t)__bfloat16_as_ushort(ha) |
           ((uint32_t)__bfloat16_as_ushort(hb) << 16);
}

// per-edge logit over this lane's 8 channels (inline fn: macro-hygiene-safe)
__device__ __forceinline__ float edge_logit(
        const float4& xa, const float4& xb, float ew,
        const float4& xrA, const float4& xrB,
        const float4& weA, const float4& weB,
        const float4& atA, const float4& atB) {
    float t = 0.f, v;
    v = xa.x + xrA.x + ew * weA.x; v = v > 0.f ? v : 0.2f * v; t += v * atA.x;
    v = xa.y + xrA.y + ew * weA.y; v = v > 0.f ? v : 0.2f * v; t += v * atA.y;
    v = xa.z + xrA.z + ew * weA.z; v = v > 0.f ? v : 0.2f * v; t += v * atA.z;
    v = xa.w + xrA.w + ew * weA.w; v = v > 0.f ? v : 0.2f * v; t += v * atA.w;
    v = xb.x + xrB.x + ew * weB.x; v = v > 0.f ? v : 0.2f * v; t += v * atB.x;
    v = xb.y + xrB.y + ew * weB.y; v = v > 0.f ? v : 0.2f * v; t += v * atB.y;
    v = xb.z + xrB.z + ew * weB.z; v = v > 0.f ? v : 0.2f * v; t += v * atB.z;
    v = xb.w + xrB.w + ew * weB.w; v = v > 0.f ? v : 0.2f * v; t += v * atB.w;
    return t;
}

#define LDSM4(r, a) \
    asm volatile("ldmatrix.sync.aligned.m8n8.x4.shared.b16 {%0,%1,%2,%3}, [%4];" \
        : "=r"((r)[0]), "=r"((r)[1]), "=r"((r)[2]), "=r"((r)[3]) : "r"(a))
#define MMA(c, a, b) \
    asm volatile("mma.sync.aligned.m16n8k16.row.col.f32.bf16.bf16.f32 " \
        "{%0,%1,%2,%3},{%4,%5,%6,%7},{%8,%9},{%0,%1,%2,%3};" \
        : "+f"((c)[0]), "+f"((c)[1]), "+f"((c)[2]), "+f"((c)[3]) \
        : "r"((a)[0]), "r"((a)[1]), "r"((a)[2]), "r"((a)[3]), "r"((b)[0]), "r"((b)[1]))
#define CP16(saddr, gptr) \
    asm volatile("cp.async.ca.shared.global [%0], [%1], 16;" :: "r"(saddr), "l"(gptr) : "memory")

// ---------------- init ----------------
__global__ void k_init() {
    int i = blockIdx.x * blockDim.x + threadIdx.x;
    int stride = gridDim.x * blockDim.x;
    for (int t = i; t < NN; t += stride) g_cnt[t] = 0;
    for (int t = i; t < 512; t += stride) g_bn1[t] = 0.f;
    if (i < 12) g_bn0[i] = 0.f;
}

// ---------------- BN0 statistics ----------------
__global__ void k_bn0_reduce(const float* __restrict__ h) {
    float s[5] = {0, 0, 0, 0, 0}, q[5] = {0, 0, 0, 0, 0};
    int stride = gridDim.x * blockDim.x;
    for (int r = blockIdx.x * blockDim.x + threadIdx.x; r < NN; r += stride) {
#pragma unroll
        for (int c = 0; c < 5; c++) { float v = h[r * 5 + c]; s[c] += v; q[c] += v * v; }
    }
#pragma unroll
    for (int off = 16; off; off >>= 1) {
#pragma unroll
        for (int c = 0; c < 5; c++) {
            s[c] += __shfl_xor_sync(0xffffffffu, s[c], off);
            q[c] += __shfl_xor_sync(0xffffffffu, q[c], off);
        }
    }
    if ((threadIdx.x & 31) == 0) {
#pragma unroll
        for (int c = 0; c < 5; c++) {
            atomicAdd(&g_bn0[c], s[c]);
            atomicAdd(&g_bn0[5 + c], q[c]);
        }
    }
}

// ---------------- W prep: transpose to [n][k] bf16 hi/lo ----------------
__global__ void k_prepw(const float* __restrict__ w0, const float* __restrict__ w1,
                        const float* __restrict__ w2, const float* __restrict__ w3) {
    int idx = blockIdx.x * blockDim.x + threadIdx.x;   // 0..65535
    if (idx >= 1024 * 64) return;
    int q = idx >> 10;          // k quad: k = 4q..4q+3
    int j = idx & 1023;         // global n
    int g = j >> 8, jj = j & 255;
    const float* Wg = (g == 0) ? w0 : (g == 1) ? w1 : (g == 2) ? w2 : w3;
    float v0 = Wg[(4 * q + 0) * 256 + jj];
    float v1 = Wg[(4 * q + 1) * 256 + jj];
    float v2 = Wg[(4 * q + 2) * 256 + jj];
    float v3 = Wg[(4 * q + 3) * 256 + jj];
    uint32_t l0, l1;
    uint32_t h0 = split2(v0, v1, l0);
    uint32_t h1 = split2(v2, v3, l1);
    size_t o = (size_t)j * 256 + 4 * q;
    *(uint2*)&g_wt_hi[o] = make_uint2(h0, h1);
    *(uint2*)&g_wt_lo[o] = make_uint2(l0, l1);
}

// ---------------- BN0 apply + conv1 linears ----------------
__global__ void k_lin5(const float* __restrict__ h,
                       const float* __restrict__ bn_g, const float* __restrict__ bn_b,
                       const float* __restrict__ Wl, const float* __restrict__ bl,
                       const float* __restrict__ Wr, const float* __restrict__ br) {
    __shared__ float sWl[5 * 256], sWr[5 * 256];
    __shared__ float sc[5], sh[5];
    int tid = threadIdx.x;
    for (int i = tid; i < 5 * 256; i += blockDim.x) { sWl[i] = Wl[i]; sWr[i] = Wr[i]; }
    if (tid < 5) {
        float mean = g_bn0[tid] * (1.f / NN);
        float var  = g_bn0[5 + tid] * (1.f / NN) - mean * mean;
        float scale = rsqrtf(var + BN_EPS) * bn_g[tid];
        sc[tid] = scale; sh[tid] = bn_b[tid] - mean * scale;
    }
    __syncthreads();
    int j = tid;
    float blj = bl[j], brj = br[j];
    int n0 = blockIdx.x * 32, n1 = min(n0 + 32, NN);
    for (int n = n0; n < n1; n++) {
        float al = blj, ar = brj;
#pragma unroll
        for (int k = 0; k < 5; k++) {
            float x = h[n * 5 + k] * sc[k] + sh[k];
            al += x * sWl[k * 256 + j];
            ar += x * sWr[k * 256 + j];
        }
        g_xl1[(long long)n * 256 + j] = al;
        g_xr1[(long long)n * 256 + j] = ar;
    }
}

// ---------------- hist + CSR scan + scatter ----------------
__global__ void k_hist(const int* __restrict__ dst) {
    int e = blockIdx.x * blockDim.x + threadIdx.x;
    if (e < NE) atomicAdd(&g_cnt[dst[e]], 1);
}

__global__ void k_scan1() {
    __shared__ int sm[1024];
    int t = threadIdx.x;
    int n = blockIdx.x * 1024 + t;
    sm[t] = (n < NN) ? g_cnt[n] : 0;
    __syncthreads();
    for (int off = 512; off; off >>= 1) {
        if (t < off) sm[t] += sm[t + off];
        __syncthreads();
    }
    if (t == 0) g_bsum[blockIdx.x] = sm[0];
}

__global__ void k_scan2(int nblocks) {
    __shared__ int sm[64];
    int t = threadIdx.x;
    int v = (t < nblocks) ? g_bsum[t] : 0;
    sm[t] = v;
    __syncthreads();
    for (int off = 1; off < 64; off <<= 1) {
        int u = (t >= off) ? sm[t - off] : 0;
        __syncthreads();
        sm[t] += u;
        __syncthreads();
    }
    g_boff[t] = sm[t] - v;
    if (t == 0) g_rowptr[NN] = NE;
}

__global__ void k_scan3() {
    __shared__ int sm[1024];
    int t = threadIdx.x;
    int n = blockIdx.x * 1024 + t;
    int v = (n < NN) ? g_cnt[n] : 0;
    sm[t] = v;
    __syncthreads();
    for (int off = 1; off < 1024; off <<= 1) {
        int u = (t >= off) ? sm[t - off] : 0;
        __syncthreads();
        sm[t] += u;
        __syncthreads();
    }
    if (n < NN) {
        int excl = g_boff[blockIdx.x] + sm[t] - v;
        g_rowptr[n] = excl;
        g_cursor[n] = excl;
    }
}

__global__ void k_scatter(const int* __restrict__ src, const int* __restrict__ dst,
                          const float* __restrict__ ew) {
    int e = blockIdx.x * blockDim.x + threadIdx.x;
    if (e < NE) {
        int p = atomicAdd(&g_cursor[dst[e]], 1);
        g_srcs[p] = src[e];
        g_ews[p]  = ew[e];
    }
}

// ---------------- conv1: warp-per-node ONLINE softmax, 2-edge unroll -------------
__global__ void k_node1(const float* __restrict__ We, const float* __restrict__ att,
                        const float* __restrict__ bias) {
    int n = (blockIdx.x * blockDim.x + threadIdx.x) >> 5;
    if (n >= NN) return;
    int lane = threadIdx.x & 31;
    int cb = lane * 8;
    int js = g_rowptr[n], je = g_rowptr[n + 1];
    const float4* pxr = (const float4*)&g_xr1[(long long)n * 256 + cb];
    float4 xrA = pxr[0], xrB = pxr[1];
    float4 weA = *(const float4*)&We[cb],  weB = *(const float4*)&We[cb + 4];
    float4 atA = *(const float4*)&att[cb], atB = *(const float4*)&att[cb + 4];
    float m = NEG_INF, den = 0.f;
    float acc[8] = {0, 0, 0, 0, 0, 0, 0, 0};
    int j = js;
    for (; j + 1 < je; j += 2) {
        int s0 = g_srcs[j], s1 = g_srcs[j + 1];
        float w0 = g_ews[j], w1 = g_ews[j + 1];
        const float4* p0_ = (const float4*)&g_xl1[(long long)s0 * 256 + cb];
        const float4* p1_ = (const float4*)&g_xl1[(long long)s1 * 256 + cb];
        float4 xa0 = p0_[0], xb0 = p0_[1];
        float4 xa1 = p1_[0], xb1 = p1_[1];
        float t0 = edge_logit(xa0, xb0, w0, xrA, xrB, weA, weB, atA, atB);
        float t1 = edge_logit(xa1, xb1, w1, xrA, xrB, weA, weB, atA, atB);
        float pa = hsum(t0), pb = hsum(t1);
        float nm = fmaxf(m, fmaxf(pa, pb));
        float sc = __expf(m - nm);
        float wa = __expf(pa - nm), wb = __expf(pb - nm);
        m = nm;
        den = den * sc + wa + wb;
        acc[0] = acc[0] * sc + wa * xa0.x + wb * xa1.x;
        acc[1] = acc[1] * sc + wa * xa0.y + wb * xa1.y;
        acc[2] = acc[2] * sc + wa * xa0.z + wb * xa1.z;
        acc[3] = acc[3] * sc + wa * xa0.w + wb * xa1.w;
        acc[4] = acc[4] * sc + wa * xb0.x + wb * xb1.x;
        acc[5] = acc[5] * sc + wa * xb0.y + wb * xb1.y;
        acc[6] = acc[6] * sc + wa * xb0.z + wb * xb1.z;
        acc[7] = acc[7] * sc + wa * xb0.w + wb * xb1.w;
    }
    if (j < je) {
        int s0 = g_srcs[j]; float w0 = g_ews[j];
        const float4* p0_ = (const float4*)&g_xl1[(long long)s0 * 256 + cb];
        float4 xa0 = p0_[0], xb0 = p0_[1];
        float t0 = edge_logit(xa0, xb0, w0, xrA, xrB, weA, weB, atA, atB);
        float pa = hsum(t0);
        float nm = fmaxf(m, pa);
        float sc = __expf(m - nm);
        float wa = __expf(pa - nm);
        m = nm;
        den = den * sc + wa;
        acc[0] = acc[0] * sc + wa * xa0.x; acc[1] = acc[1] * sc + wa * xa0.y;
        acc[2] = acc[2] * sc + wa * xa0.z; acc[3] = acc[3] * sc + wa * xa0.w;
        acc[4] = acc[4] * sc + wa * xb0.x; acc[5] = acc[5] * sc + wa * xb0.y;
        acc[6] = acc[6] * sc + wa * xb0.z; acc[7] = acc[7] * sc + wa * xb0.w;
    }
    float inv = 1.f / (den + 1e-16f);
    float4 bA = *(const float4*)&bias[cb], bB = *(const float4*)&bias[cb + 4];
    float4* po = (float4*)&g_agg1[(long long)n * 256 + cb];
    po[0] = make_float4(acc[0] * inv + bA.x, acc[1] * inv + bA.y,
                        acc[2] * inv + bA.z, acc[3] * inv + bA.w);
    po[1] = make_float4(acc[4] * inv + bB.x, acc[5] * inv + bB.y,
                        acc[6] * inv + bB.z, acc[7] * inv + bB.w);
}

// ---------------- BN1 statistics ----------------
__global__ void k_bn1_reduce() {
    int c = threadIdx.x;
    float s = 0.f, q = 0.f;
    for (int r = blockIdx.x; r < NN; r += gridDim.x) {
        float v = g_agg1[(long long)r * 256 + c];
        s += v; q += v * v;
    }
    atomicAdd(&g_bn1[c], s);
    atomicAdd(&g_bn1[256 + c], q);
}

// ---------------- A prep: BN (from raw sums) + ReLU, bf16 hi/lo split ------------
__global__ void k_prepa(const float* __restrict__ bg, const float* __restrict__ bb_) {
    int idx = blockIdx.x * blockDim.x + threadIdx.x;   // quad index
    if (idx >= NBLK * 128 * 64) return;
    int r = idx >> 6;
    int q4 = (idx & 63) * 4;
    uint32_t h0 = 0, h1 = 0, l0 = 0, l1 = 0;
    if (r < NN) {
        float4 s4 = *(const float4*)&g_bn1[q4];
        float4 q4v = *(const float4*)&g_bn1[256 + q4];
        float4 gg = *(const float4*)&bg[q4];
        float4 bv = *(const float4*)&bb_[q4];
        float m0 = s4.x * (1.f / NN), m1 = s4.y * (1.f / NN);
        float m2 = s4.z * (1.f / NN), m3 = s4.w * (1.f / NN);
        float A0 = rsqrtf(q4v.x * (1.f / NN) - m0 * m0 + BN_EPS) * gg.x;
        float A1 = rsqrtf(q4v.y * (1.f / NN) - m1 * m1 + BN_EPS) * gg.y;
        float A2 = rsqrtf(q4v.z * (1.f / NN) - m2 * m2 + BN_EPS) * gg.z;
        float A3 = rsqrtf(q4v.w * (1.f / NN) - m3 * m3 + BN_EPS) * gg.w;
        float C0 = bv.x - m0 * A0, C1 = bv.y - m1 * A1;
        float C2 = bv.z - m2 * A2, C3 = bv.w - m3 * A3;
        float4 x = *(const float4*)&g_agg1[(size_t)r * 256 + q4];
        float v0 = fmaxf(x.x * A0 + C0, 0.f);
        float v1 = fmaxf(x.y * A1 + C1, 0.f);
        float v2 = fmaxf(x.z * A2 + C2, 0.f);
        float v3 = fmaxf(x.w * A3 + C3, 0.f);
        h0 = split2(v0, v1, l0);
        h1 = split2(v2, v3, l1);
    }
    size_t o = (size_t)r * 256 + q4;
    *(uint2*)&g_a_hi[o] = make_uint2(h0, h1);
    *(uint2*)&g_a_lo[o] = make_uint2(l0, l1);
}

// ---------------- mma.sync GEMM with 2-stage cp.async pipeline -------------------
#define RS 40
#define PLN (128 * RS * 2)             // 10240 B per plane
__global__ void __launch_bounds__(256) k_gemm_mma(
        const float* __restrict__ b0, const float* __restrict__ b1,
        const float* __restrict__ b2, const float* __restrict__ b3,
        float* __restrict__ Cout) {
    extern __shared__ __align__(16) char dsm[];
    uint32_t sb = s2u(dsm);
    int tid = threadIdx.x;
    int wid = tid >> 5, lane = tid & 31;
    int bx = blockIdx.x;              // 0..7 -> grp*2 + half
    int by = blockIdx.y;
    int grp = bx >> 1, half = bx & 1;
    const float* bb = (grp == 0) ? b0 : (grp == 1) ? b1 : (grp == 2) ? b2 : b3;
    int warp_m = wid & 1;             // 2 x 64 rows
    int warp_n = wid >> 1;            // 4 x 32 cols

    const unsigned short* gAh = g_a_hi + (size_t)by * 128 * 256;
    const unsigned short* gAl = g_a_lo + (size_t)by * 128 * 256;
    const unsigned short* gBh = g_wt_hi + (size_t)bx * 128 * 256;
    const unsigned short* gBl = g_wt_lo + (size_t)bx * 128 * 256;

    int arow = 64 * warp_m + (lane & 15);
    int akb  = (lane >> 4) << 3;
    int brow = 32 * warp_n + (lane & 7) + ((lane >> 4) << 3);
    int bkb  = ((lane >> 3) & 1) << 3;
    int grow0 = tid >> 2, gq0 = (tid & 3) * 8;
    int grow1 = (tid + 256) >> 2, gq1 = ((tid + 256) & 3) * 8;

    float acc[4][4][4];
#pragma unroll
    for (int mi = 0; mi < 4; mi++)
#pragma unroll
        for (int ni = 0; ni < 4; ni++)
#pragma unroll
            for (int r = 0; r < 4; r++) acc[mi][ni][r] = 0.f;

#define ISSUE(stage, cc) do { \
        int k0_ = (cc) * 32; \
        uint32_t base_ = sb + (stage) * 4 * PLN; \
        uint32_t d0_ = base_ + (uint32_t)(grow0 * RS + gq0) * 2; \
        uint32_t d1_ = base_ + (uint32_t)(grow1 * RS + gq1) * 2; \
        size_t s0_ = (size_t)grow0 * 256 + k0_ + gq0; \
        size_t s1_ = (size_t)grow1 * 256 + k0_ + gq1; \
        CP16(d0_,           gAh + s0_); CP16(d1_,           gAh + s1_); \
        CP16(d0_ + PLN,     gAl + s0_); CP16(d1_ + PLN,     gAl + s1_); \
        CP16(d0_ + 2 * PLN, gBh + s0_); CP16(d1_ + 2 * PLN, gBh + s1_); \
        CP16(d0_ + 3 * PLN, gBl + s0_); CP16(d1_ + 3 * PLN, gBl + s1_); \
        asm volatile("cp.async.commit_group;" ::: "memory"); \
    } while (0)

    ISSUE(0, 0);
    for (int c = 0; c < 8; c++) {
        if (c + 1 < 8) {
            ISSUE((c + 1) & 1, c + 1);
            asm volatile("cp.async.wait_group 1;" ::: "memory");
        } else {
            asm volatile("cp.async.wait_group 0;" ::: "memory");
        }
        __syncthreads();
        uint32_t aAh = sb + (c & 1) * 4 * PLN;
        uint32_t aAl = aAh + PLN, aBh = aAh + 2 * PLN, aBl = aAh + 3 * PLN;
#pragma unroll
        for (int ks = 0; ks < 2; ks++) {
            int kk = ks * 16;
            uint32_t ah[4][4], al[4][4];
#pragma unroll
            for (int mi = 0; mi < 4; mi++) {
                uint32_t ad = aAh + (uint32_t)(((arow + 16 * mi) * RS + kk + akb) * 2);
                LDSM4(ah[mi], ad);
            }
            uint32_t bh[4][2];
#pragma unroll
            for (int nb = 0; nb < 2; nb++) {
                uint32_t r4[4];
                uint32_t ad = aBh + (uint32_t)(((brow + 16 * nb) * RS + kk + bkb) * 2);
                LDSM4(r4, ad);
                bh[2 * nb][0] = r4[0]; bh[2 * nb][1] = r4[1];
                bh[2 * nb + 1][0] = r4[2]; bh[2 * nb + 1][1] = r4[3];
            }
#pragma unroll
            for (int mi = 0; mi < 4; mi++)
#pragma unroll
                for (int ni = 0; ni < 4; ni++) MMA(acc[mi][ni], ah[mi], bh[ni]);
            uint32_t bl_[4][2];
#pragma unroll
            for (int nb = 0; nb < 2; nb++) {
                uint32_t r4[4];
                uint32_t ad = aBl + (uint32_t)(((brow + 16 * nb) * RS + kk + bkb) * 2);
                LDSM4(r4, ad);
                bl_[2 * nb][0] = r4[0]; bl_[2 * nb][1] = r4[1];
                bl_[2 * nb + 1][0] = r4[2]; bl_[2 * nb + 1][1] = r4[3];
            }
#pragma unroll
            for (int mi = 0; mi < 4; mi++)
#pragma unroll
                for (int ni = 0; ni < 4; ni++) MMA(acc[mi][ni], ah[mi], bl_[ni]);
#pragma unroll
            for (int mi = 0; mi < 4; mi++) {
                uint32_t ad = aAl + (uint32_t)(((arow + 16 * mi) * RS + kk + akb) * 2);
                LDSM4(al[mi], ad);
            }
#pragma unroll
            for (int mi = 0; mi < 4; mi++)
#pragma unroll
                for (int ni = 0; ni < 4; ni++) MMA(acc[mi][ni], al[mi], bh[ni]);
        }
        __syncthreads();
    }

    float* outp = Cout + (size_t)grp * NN * 256;
    int rbase = by * 128 + 64 * warp_m + (lane >> 2);
    int cfrag = (lane & 3) * 2;
#pragma unroll
    for (int ni = 0; ni < 4; ni++) {
        int col = 32 * warp_n + 8 * ni + cfrag;
        float bx0 = bb[half * 128 + col], bx1 = bb[half * 128 + col + 1];
#pragma unroll
        for (int mi = 0; mi < 4; mi++) {
            int r0 = rbase + 16 * mi;
            if (r0 < NN)
                *(float2*)&outp[(size_t)r0 * 256 + half * 128 + col] =
                    make_float2(acc[mi][ni][0] + bx0, acc[mi][ni][1] + bx1);
            if (r0 + 8 < NN)
                *(float2*)&outp[(size_t)(r0 + 8) * 256 + half * 128 + col] =
                    make_float2(acc[mi][ni][2] + bx0, acc[mi][ni][3] + bx1);
        }
    }
}

// ---------------- mu/ls conv: ONLINE softmax, 2-edge unroll, head-mean -----------
__global__ void k_node2h(const float* __restrict__ xl, const float* __restrict__ xr,
                         const float* __restrict__ We, const float* __restrict__ att,
                         const float* __restrict__ bias, float* __restrict__ out) {
    int n = (blockIdx.x * blockDim.x + threadIdx.x) >> 5;
    if (n >= NN) return;
    int lane = threadIdx.x & 31;
    int cb = lane * 8;
    int js = g_rowptr[n], je = g_rowptr[n + 1];
    const float4* pxr = (const float4*)&xr[(long long)n * 256 + cb];
    float4 xrA = pxr[0], xrB = pxr[1];
    float4 weA = *(const float4*)&We[cb],  weB = *(const float4*)&We[cb + 4];
    float4 atA = *(const float4*)&att[cb], atB = *(const float4*)&att[cb + 4];
    float m = NEG_INF, den = 0.f;
    float acc[8] = {0, 0, 0, 0, 0, 0, 0, 0};
    int j = js;
    for (; j + 1 < je; j += 2) {
        int s0 = g_srcs[j], s1 = g_srcs[j + 1];
        float w0 = g_ews[j], w1 = g_ews[j + 1];
        const float4* p0_ = (const float4*)&xl[(long long)s0 * 256 + cb];
        const float4* p1_ = (const float4*)&xl[(long long)s1 * 256 + cb];
        float4 xa0 = p0_[0], xb0 = p0_[1];
        float4 xa1 = p1_[0], xb1 = p1_[1];
        float t0 = edge_logit(xa0, xb0, w0, xrA, xrB, weA, weB, atA, atB);
        float t1 = edge_logit(xa1, xb1, w1, xrA, xrB, weA, weB, atA, atB);
        float pa = hsum(t0), pb = hsum(t1);
        float nm = fmaxf(m, fmaxf(pa, pb));
        float sc = __expf(m - nm);
        float wa = __expf(pa - nm), wb = __expf(pb - nm);
        m = nm;
        den = den * sc + wa + wb;
        acc[0] = acc[0] * sc + wa * xa0.x + wb * xa1.x;
        acc[1] = acc[1] * sc + wa * xa0.y + wb * xa1.y;
        acc[2] = acc[2] * sc + wa * xa0.z + wb * xa1.z;
        acc[3] = acc[3] * sc + wa * xa0.w + wb * xa1.w;
        acc[4] = acc[4] * sc + wa * xb0.x + wb * xb1.x;
        acc[5] = acc[5] * sc + wa * xb0.y + wb * xb1.y;
        acc[6] = acc[6] * sc + wa * xb0.z + wb * xb1.z;
        acc[7] = acc[7] * sc + wa * xb0.w + wb * xb1.w;
    }
    if (j < je) {
        int s0 = g_srcs[j]; float w0 = g_ews[j];
        const float4* p0_ = (const float4*)&xl[(long long)s0 * 256 + cb];
        float4 xa0 = p0_[0], xb0 = p0_[1];
        float t0 = edge_logit(xa0, xb0, w0, xrA, xrB, weA, weB, atA, atB);
        float pa = hsum(t0);
        float nm = fmaxf(m, pa);
        float sc = __expf(m - nm);
        float wa = __expf(pa - nm);
        m = nm;
        den = den * sc + wa;
        acc[0] = acc[0] * sc + wa * xa0.x; acc[1] = acc[1] * sc + wa * xa0.y;
        acc[2] = acc[2] * sc + wa * xa0.z; acc[3] = acc[3] * sc + wa * xa0.w;
        acc[4] = acc[4] * sc + wa * xb0.x; acc[5] = acc[5] * sc + wa * xb0.y;
        acc[6] = acc[6] * sc + wa * xb0.z; acc[7] = acc[7] * sc + wa * xb0.w;
    }
    float inv = 1.f / (den + 1e-16f);
    float r8[8];
#pragma unroll
    for (int k = 0; k < 8; k++) {
        float mine = acc[k] * inv;
        float peer = __shfl_xor_sync(0xffffffffu, mine, 16);
        r8[k] = 0.5f * (mine + peer);
    }
    if (lane < 16) {
        float4 bA = *(const float4*)&bias[cb], bB = *(const float4*)&bias[cb + 4];
        float4* po = (float4*)&out[(long long)n * 128 + cb];
        po[0] = make_float4(r8[0] + bA.x, r8[1] + bA.y, r8[2] + bA.z, r8[3] + bA.w);
        po[1] = make_float4(r8[4] + bB.x, r8[5] + bB.y, r8[6] + bB.z, r8[7] + bB.w);
    }
}

// ---------------- launch ----------------
extern "C" void kernel_launch(void* const* d_in, const int* in_sizes, int n_in,
                              void* d_out, int out_size) {
    const float* h       = (const float*)d_in[0];
    const int*   ei      = (const int*)d_in[1];
    const float* ew      = (const float*)d_in[2];
    const float* bn0_g   = (const float*)d_in[3];
    const float* bn0_b   = (const float*)d_in[4];
    const float* bn1_g   = (const float*)d_in[5];
    const float* bn1_b   = (const float*)d_in[6];
    const float* c1_Wl   = (const float*)d_in[7];
    const float* c1_bl   = (const float*)d_in[8];
    const float* c1_Wr   = (const float*)d_in[9];
    const float* c1_br   = (const float*)d_in[10];
    const float* c1_We   = (const float*)d_in[11];
    const float* c1_att  = (const float*)d_in[12];
    const float* c1_bias = (const float*)d_in[13];
    const float* mu_Wl   = (const float*)d_in[14];
    const float* mu_bl   = (const float*)d_in[15];
    const float* mu_Wr   = (const float*)d_in[16];
    const float* mu_br   = (const float*)d_in[17];
    const float* mu_We   = (const float*)d_in[18];
    const float* mu_att  = (const float*)d_in[19];
    const float* mu_bias = (const float*)d_in[20];
    const float* ls_Wl   = (const float*)d_in[21];
    const float* ls_bl   = (const float*)d_in[22];
    const float* ls_Wr   = (const float*)d_in[23];
    const float* ls_br   = (const float*)d_in[24];
    const float* ls_We   = (const float*)d_in[25];
    const float* ls_att  = (const float*)d_in[26];
    const float* ls_bias = (const float*)d_in[27];
    float* out = (float*)d_out;

    const int* src = ei;
    const int* dst = ei + NE;

    float* x4;
    cudaGetSymbolAddress((void**)&x4, g_x4);

    const int TB = 256;
    int eb = (NE + TB - 1) / TB;
    int nodeWarpBlocks = (NN * 32 + TB - 1) / TB;
    int scanBlocks = (NN + 1023) / 1024;   // 49
    const int GEMM_SMEM = 8 * PLN;         // 81920 B

    cudaFuncSetAttribute(k_gemm_mma, cudaFuncAttributeMaxDynamicSharedMemorySize, GEMM_SMEM);

    k_init<<<128, TB>>>();                                       // 1
    k_bn0_reduce<<<64, TB>>>(h);                                 // 2
    k_prepw<<<(1024 * 64 + TB - 1) / TB, TB>>>(mu_Wl, mu_Wr, ls_Wl, ls_Wr);  // 3
    k_lin5<<<(NN + 31) / 32, TB>>>(h, bn0_g, bn0_b,              // 4 (ncu slot)
                                   c1_Wl, c1_bl, c1_Wr, c1_br);
    k_hist<<<eb, TB>>>(dst);                                     // 5
    k_scan1<<<scanBlocks, 1024>>>();                             // 6
    k_scan2<<<1, 64>>>(scanBlocks);                              // 7
    k_scan3<<<scanBlocks, 1024>>>();                             // 8
    k_scatter<<<eb, TB>>>(src, dst, ew);                         // 9

    k_node1<<<nodeWarpBlocks, TB>>>(c1_We, c1_att, c1_bias);     // 10

    k_bn1_reduce<<<512, TB>>>();                                 // 11

    k_prepa<<<(NBLK * 128 * 64 + TB - 1) / TB, TB>>>(bn1_g, bn1_b);  // 12

    dim3 gg(8, NBLK);
    k_gemm_mma<<<gg, 256, GEMM_SMEM>>>(mu_bl, mu_br, ls_bl, ls_br, x4);  // 13

    k_node2h<<<nodeWarpBlocks, TB>>>(x4, x4 + (long long)NN * 256,          // 14: mu
                                     mu_We, mu_att, mu_bias, out);
    k_node2h<<<nodeWarpBlocks, TB>>>(x4 + 2ll * NN * 256, x4 + 3ll * NN * 256,  // 15: ls
                                     ls_We, ls_att, ls_bias,
                                     out + (long long)NN * 128);
}

// round 11
// speedup vs baseline: 2.4786x; 1.0233x over previous
#include <cuda_runtime.h>
#include <cuda_bf16.h>
#include <cstdint>

#define NN 50000
#define NE 300000
#define BN_EPS 1e-5f
#define NEG_INF __int_as_float(0xff800000)
#define NBLK 391                       // ceil(NN/128)

// ---------------- scratch (__device__ globals; zero-initialized at load) --------
__device__ float g_xl1[NN * 256];
__device__ float g_xr1[NN * 256];
__device__ float g_x4 [NN * 1024];   // 4 blocks [NN,256]: mu_xl | mu_xr | ls_xl | ls_xr
__device__ float g_agg1[NN * 256];   // conv1 out (+bias), pre-BN
__device__ int   g_cnt [NN];         // re-zeroed by k_scan3 each launch
__device__ int   g_rowptr[NN + 1];
__device__ int   g_cursor[NN];
__device__ int   g_srcs[NE];
__device__ float g_ews [NE];
__device__ int   g_bsum[64];
__device__ int   g_boff[64];
__device__ float g_bn0[12];          // re-zeroed by k_node1 block 0
__device__ float g_bn1[512];         // re-zeroed by k_node1 block 0
// bf16 hi/lo operand planes for the mma.sync GEMM
__device__ unsigned short g_a_hi[NBLK * 128 * 256];   // relu(bn(x1)) hi
__device__ unsigned short g_a_lo[NBLK * 128 * 256];   // residual lo
__device__ unsigned short g_wt_hi[1024 * 256];        // W^T [n][k] hi
__device__ unsigned short g_wt_lo[1024 * 256];

// ---------------- generic helpers ----------------
__device__ __forceinline__ float hsum(float v) {   // 16-lane half-warp butterfly
#pragma unroll
    for (int o = 8; o; o >>= 1) v += __shfl_xor_sync(0xffffffffu, v, o);
    return v;
}
__device__ __forceinline__ uint32_t s2u(const void* p) {
    uint32_t a;
    asm("{ .reg .u64 t; cvta.to.shared.u64 t, %1; cvt.u32.u64 %0, t; }" : "=r"(a) : "l"(p));
    return a;
}
// pack two floats to bf16x2 hi, produce bf16x2 lo residual
__device__ __forceinline__ uint32_t split2(float a, float b, uint32_t& lo) {
    __nv_bfloat16 ha = __float2bfloat16_rn(a), hb = __float2bfloat16_rn(b);
    float ra = a - __bfloat162float(ha), rb = b - __bfloat162float(hb);
    lo = (uint32_t)__bfloat16_as_ushort(__float2bfloat16_rn(ra)) |
         ((uint32_t)__bfloat16_as_ushort(__float2bfloat16_rn(rb)) << 16);
    return (uint32_t)__bfloat16_as_ushort(ha) |
           ((uint32_t)__bfloat16_as_ushort(hb) << 16);
}

// per-edge logit over this lane's 8 channels (inline fn: macro-hygiene-safe)
__device__ __forceinline__ float edge_logit(
        const float4& xa, const float4& xb, float ew,
        const float4& xrA, const float4& xrB,
        const float4& weA, const float4& weB,
        const float4& atA, const float4& atB) {
    float t = 0.f, v;
    v = xa.x + xrA.x + ew * weA.x; v = v > 0.f ? v : 0.2f * v; t += v * atA.x;
    v = xa.y + xrA.y + ew * weA.y; v = v > 0.f ? v : 0.2f * v; t += v * atA.y;
    v = xa.z + xrA.z + ew * weA.z; v = v > 0.f ? v : 0.2f * v; t += v * atA.z;
    v = xa.w + xrA.w + ew * weA.w; v = v > 0.f ? v : 0.2f * v; t += v * atA.w;
    v = xb.x + xrB.x + ew * weB.x; v = v > 0.f ? v : 0.2f * v; t += v * atB.x;
    v = xb.y + xrB.y + ew * weB.y; v = v > 0.f ? v : 0.2f * v; t += v * atB.y;
    v = xb.z + xrB.z + ew * weB.z; v = v > 0.f ? v : 0.2f * v; t += v * atB.z;
    v = xb.w + xrB.w + ew * weB.w; v = v > 0.f ? v : 0.2f * v; t += v * atB.w;
    return t;
}

#define LDSM4(r, a) \
    asm volatile("ldmatrix.sync.aligned.m8n8.x4.shared.b16 {%0,%1,%2,%3}, [%4];" \
        : "=r"((r)[0]), "=r"((r)[1]), "=r"((r)[2]), "=r"((r)[3]) : "r"(a))
#define MMA(c, a, b) \
    asm volatile("mma.sync.aligned.m16n8k16.row.col.f32.bf16.bf16.f32 " \
        "{%0,%1,%2,%3},{%4,%5,%6,%7},{%8,%9},{%0,%1,%2,%3};" \
        : "+f"((c)[0]), "+f"((c)[1]), "+f"((c)[2]), "+f"((c)[3]) \
        : "r"((a)[0]), "r"((a)[1]), "r"((a)[2]), "r"((a)[3]), "r"((b)[0]), "r"((b)[1]))
#define CP16(saddr, gptr) \
    asm volatile("cp.async.ca.shared.global [%0], [%1], 16;" :: "r"(saddr), "l"(gptr) : "memory")

// ---------------- BN0 statistics ----------------
__global__ void k_bn0_reduce(const float* __restrict__ h) {
    float s[5] = {0, 0, 0, 0, 0}, q[5] = {0, 0, 0, 0, 0};
    int stride = gridDim.x * blockDim.x;
    for (int r = blockIdx.x * blockDim.x + threadIdx.x; r < NN; r += stride) {
#pragma unroll
        for (int c = 0; c < 5; c++) { float v = h[r * 5 + c]; s[c] += v; q[c] += v * v; }
    }
#pragma unroll
    for (int off = 16; off; off >>= 1) {
#pragma unroll
        for (int c = 0; c < 5; c++) {
            s[c] += __shfl_xor_sync(0xffffffffu, s[c], off);
            q[c] += __shfl_xor_sync(0xffffffffu, q[c], off);
        }
    }
    if ((threadIdx.x & 31) == 0) {
#pragma unroll
        for (int c = 0; c < 5; c++) {
            atomicAdd(&g_bn0[c], s[c]);
            atomicAdd(&g_bn0[5 + c], q[c]);
        }
    }
}

// ---------------- W prep: transpose to [n][k] bf16 hi/lo ----------------
__global__ void k_prepw(const float* __restrict__ w0, const float* __restrict__ w1,
                        const float* __restrict__ w2, const float* __restrict__ w3) {
    int idx = blockIdx.x * blockDim.x + threadIdx.x;   // 0..65535
    if (idx >= 1024 * 64) return;
    int q = idx >> 10;          // k quad: k = 4q..4q+3
    int j = idx & 1023;         // global n
    int g = j >> 8, jj = j & 255;
    const float* Wg = (g == 0) ? w0 : (g == 1) ? w1 : (g == 2) ? w2 : w3;
    float v0 = Wg[(4 * q + 0) * 256 + jj];
    float v1 = Wg[(4 * q + 1) * 256 + jj];
    float v2 = Wg[(4 * q + 2) * 256 + jj];
    float v3 = Wg[(4 * q + 3) * 256 + jj];
    uint32_t l0, l1;
    uint32_t h0 = split2(v0, v1, l0);
    uint32_t h1 = split2(v2, v3, l1);
    size_t o = (size_t)j * 256 + 4 * q;
    *(uint2*)&g_wt_hi[o] = make_uint2(h0, h1);
    *(uint2*)&g_wt_lo[o] = make_uint2(l0, l1);
}

// ---------------- BN0 apply + conv1 linears (2-node ILP unroll) ------------------
__global__ void k_lin5(const float* __restrict__ h,
                       const float* __restrict__ bn_g, const float* __restrict__ bn_b,
                       const float* __restrict__ Wl, const float* __restrict__ bl,
                       const float* __restrict__ Wr, const float* __restrict__ br) {
    __shared__ float sWl[5 * 256], sWr[5 * 256];
    __shared__ float sc[5], sh[5];
    int tid = threadIdx.x;
    for (int i = tid; i < 5 * 256; i += blockDim.x) { sWl[i] = Wl[i]; sWr[i] = Wr[i]; }
    if (tid < 5) {
        float mean = g_bn0[tid] * (1.f / NN);
        float var  = g_bn0[5 + tid] * (1.f / NN) - mean * mean;
        float scale = rsqrtf(var + BN_EPS) * bn_g[tid];
        sc[tid] = scale; sh[tid] = bn_b[tid] - mean * scale;
    }
    __syncthreads();
    int j = tid;
    float blj = bl[j], brj = br[j];
    int n0 = blockIdx.x * 32, n1 = min(n0 + 32, NN);
    int n = n0;
    for (; n + 1 < n1; n += 2) {
        float al0 = blj, ar0 = brj, al1 = blj, ar1 = brj;
#pragma unroll
        for (int k = 0; k < 5; k++) {
            float x0 = h[n * 5 + k] * sc[k] + sh[k];
            float x1 = h[(n + 1) * 5 + k] * sc[k] + sh[k];
            float wl_ = sWl[k * 256 + j], wr_ = sWr[k * 256 + j];
            al0 += x0 * wl_; ar0 += x0 * wr_;
            al1 += x1 * wl_; ar1 += x1 * wr_;
        }
        g_xl1[(long long)n * 256 + j] = al0;
        g_xr1[(long long)n * 256 + j] = ar0;
        g_xl1[(long long)(n + 1) * 256 + j] = al1;
        g_xr1[(long long)(n + 1) * 256 + j] = ar1;
    }
    if (n < n1) {
        float al = blj, ar = brj;
#pragma unroll
        for (int k = 0; k < 5; k++) {
            float x = h[n * 5 + k] * sc[k] + sh[k];
            al += x * sWl[k * 256 + j];
            ar += x * sWr[k * 256 + j];
        }
        g_xl1[(long long)n * 256 + j] = al;
        g_xr1[(long long)n * 256 + j] = ar;
    }
}

// ---------------- hist + CSR scan + scatter ----------------
__global__ void k_hist(const int* __restrict__ dst) {
    int e = blockIdx.x * blockDim.x + threadIdx.x;
    if (e < NE) atomicAdd(&g_cnt[dst[e]], 1);
}

__global__ void k_scan1() {
    __shared__ int sm[1024];
    int t = threadIdx.x;
    int n = blockIdx.x * 1024 + t;
    sm[t] = (n < NN) ? g_cnt[n] : 0;
    __syncthreads();
    for (int off = 512; off; off >>= 1) {
        if (t < off) sm[t] += sm[t + off];
        __syncthreads();
    }
    if (t == 0) g_bsum[blockIdx.x] = sm[0];
}

__global__ void k_scan2(int nblocks) {
    __shared__ int sm[64];
    int t = threadIdx.x;
    int v = (t < nblocks) ? g_bsum[t] : 0;
    sm[t] = v;
    __syncthreads();
    for (int off = 1; off < 64; off <<= 1) {
        int u = (t >= off) ? sm[t - off] : 0;
        __syncthreads();
        sm[t] += u;
        __syncthreads();
    }
    g_boff[t] = sm[t] - v;
    if (t == 0) g_rowptr[NN] = NE;
}

__global__ void k_scan3() {
    __shared__ int sm[1024];
    int t = threadIdx.x;
    int n = blockIdx.x * 1024 + t;
    int v = (n < NN) ? g_cnt[n] : 0;
    sm[t] = v;
    __syncthreads();
    for (int off = 1; off < 1024; off <<= 1) {
        int u = (t >= off) ? sm[t - off] : 0;
        __syncthreads();
        sm[t] += u;
        __syncthreads();
    }
    if (n < NN) {
        int excl = g_boff[blockIdx.x] + sm[t] - v;
        g_rowptr[n] = excl;
        g_cursor[n] = excl;
        g_cnt[n] = 0;            // self-zero for next graph replay
    }
}

__global__ void k_scatter(const int* __restrict__ src, const int* __restrict__ dst,
                          const float* __restrict__ ew) {
    int e = blockIdx.x * blockDim.x + threadIdx.x;
    if (e < NE) {
        int p = atomicAdd(&g_cursor[dst[e]], 1);
        g_srcs[p] = src[e];
        g_ews[p]  = ew[e];
    }
}

// ---------------- conv1: warp-per-node ONLINE softmax, 2-edge unroll -------------
__global__ void k_node1(const float* __restrict__ We, const float* __restrict__ att,
                        const float* __restrict__ bias) {
    // self-zero BN accumulators for next replay (consumers already ran this launch)
    if (blockIdx.x == 0) {
        int t = threadIdx.x;
        g_bn1[t] = 0.f; g_bn1[256 + t] = 0.f;
        if (t < 12) g_bn0[t] = 0.f;
    }
    int n = (blockIdx.x * blockDim.x + threadIdx.x) >> 5;
    if (n >= NN) return;
    int lane = threadIdx.x & 31;
    int cb = lane * 8;
    int js = g_rowptr[n], je = g_rowptr[n + 1];
    const float4* pxr = (const float4*)&g_xr1[(long long)n * 256 + cb];
    float4 xrA = pxr[0], xrB = pxr[1];
    float4 weA = *(const float4*)&We[cb],  weB = *(const float4*)&We[cb + 4];
    float4 atA = *(const float4*)&att[cb], atB = *(const float4*)&att[cb + 4];
    float m = NEG_INF, den = 0.f;
    float acc[8] = {0, 0, 0, 0, 0, 0, 0, 0};
    int j = js;
    for (; j + 1 < je; j += 2) {
        int s0 = g_srcs[j], s1 = g_srcs[j + 1];
        float w0 = g_ews[j], w1 = g_ews[j + 1];
        const float4* p0_ = (const float4*)&g_xl1[(long long)s0 * 256 + cb];
        const float4* p1_ = (const float4*)&g_xl1[(long long)s1 * 256 + cb];
        float4 xa0 = p0_[0], xb0 = p0_[1];
        float4 xa1 = p1_[0], xb1 = p1_[1];
        float t0 = edge_logit(xa0, xb0, w0, xrA, xrB, weA, weB, atA, atB);
        float t1 = edge_logit(xa1, xb1, w1, xrA, xrB, weA, weB, atA, atB);
        float pa = hsum(t0), pb = hsum(t1);
        float nm = fmaxf(m, fmaxf(pa, pb));
        float sc = __expf(m - nm);
        float wa = __expf(pa - nm), wb = __expf(pb - nm);
        m = nm;
        den = den * sc + wa + wb;
        acc[0] = acc[0] * sc + wa * xa0.x + wb * xa1.x;
        acc[1] = acc[1] * sc + wa * xa0.y + wb * xa1.y;
        acc[2] = acc[2] * sc + wa * xa0.z + wb * xa1.z;
        acc[3] = acc[3] * sc + wa * xa0.w + wb * xa1.w;
        acc[4] = acc[4] * sc + wa * xb0.x + wb * xb1.x;
        acc[5] = acc[5] * sc + wa * xb0.y + wb * xb1.y;
        acc[6] = acc[6] * sc + wa * xb0.z + wb * xb1.z;
        acc[7] = acc[7] * sc + wa * xb0.w + wb * xb1.w;
    }
    if (j < je) {
        int s0 = g_srcs[j]; float w0 = g_ews[j];
        const float4* p0_ = (const float4*)&g_xl1[(long long)s0 * 256 + cb];
        float4 xa0 = p0_[0], xb0 = p0_[1];
        float t0 = edge_logit(xa0, xb0, w0, xrA, xrB, weA, weB, atA, atB);
        float pa = hsum(t0);
        float nm = fmaxf(m, pa);
        float sc = __expf(m - nm);
        float wa = __expf(pa - nm);
        m = nm;
        den = den * sc + wa;
        acc[0] = acc[0] * sc + wa * xa0.x; acc[1] = acc[1] * sc + wa * xa0.y;
        acc[2] = acc[2] * sc + wa * xa0.z; acc[3] = acc[3] * sc + wa * xa0.w;
        acc[4] = acc[4] * sc + wa * xb0.x; acc[5] = acc[5] * sc + wa * xb0.y;
        acc[6] = acc[6] * sc + wa * xb0.z; acc[7] = acc[7] * sc + wa * xb0.w;
    }
    float inv = 1.f / (den + 1e-16f);
    float4 bA = *(const float4*)&bias[cb], bB = *(const float4*)&bias[cb + 4];
    float4* po = (float4*)&g_agg1[(long long)n * 256 + cb];
    po[0] = make_float4(acc[0] * inv + bA.x, acc[1] * inv + bA.y,
                        acc[2] * inv + bA.z, acc[3] * inv + bA.w);
    po[1] = make_float4(acc[4] * inv + bB.x, acc[5] * inv + bB.y,
                        acc[6] * inv + bB.z, acc[7] * inv + bB.w);
}

// ---------------- BN1 statistics ----------------
__global__ void k_bn1_reduce() {
    int c = threadIdx.x;
    float s = 0.f, q = 0.f;
    for (int r = blockIdx.x; r < NN; r += gridDim.x) {
        float v = g_agg1[(long long)r * 256 + c];
        s += v; q += v * v;
    }
    atomicAdd(&g_bn1[c], s);
    atomicAdd(&g_bn1[256 + c], q);
}

// ---------------- A prep: BN (from raw sums) + ReLU, bf16 hi/lo split ------------
__global__ void k_prepa(const float* __restrict__ bg, const float* __restrict__ bb_) {
    int idx = blockIdx.x * blockDim.x + threadIdx.x;   // quad index
    if (idx >= NBLK * 128 * 64) return;
    int r = idx >> 6;
    int q4 = (idx & 63) * 4;
    uint32_t h0 = 0, h1 = 0, l0 = 0, l1 = 0;
    if (r < NN) {
        float4 s4 = *(const float4*)&g_bn1[q4];
        float4 q4v = *(const float4*)&g_bn1[256 + q4];
        float4 gg = *(const float4*)&bg[q4];
        float4 bv = *(const float4*)&bb_[q4];
        float m0 = s4.x * (1.f / NN), m1 = s4.y * (1.f / NN);
        float m2 = s4.z * (1.f / NN), m3 = s4.w * (1.f / NN);
        float A0 = rsqrtf(q4v.x * (1.f / NN) - m0 * m0 + BN_EPS) * gg.x;
        float A1 = rsqrtf(q4v.y * (1.f / NN) - m1 * m1 + BN_EPS) * gg.y;
        float A2 = rsqrtf(q4v.z * (1.f / NN) - m2 * m2 + BN_EPS) * gg.z;
        float A3 = rsqrtf(q4v.w * (1.f / NN) - m3 * m3 + BN_EPS) * gg.w;
        float C0 = bv.x - m0 * A0, C1 = bv.y - m1 * A1;
        float C2 = bv.z - m2 * A2, C3 = bv.w - m3 * A3;
        float4 x = *(const float4*)&g_agg1[(size_t)r * 256 + q4];
        float v0 = fmaxf(x.x * A0 + C0, 0.f);
        float v1 = fmaxf(x.y * A1 + C1, 0.f);
        float v2 = fmaxf(x.z * A2 + C2, 0.f);
        float v3 = fmaxf(x.w * A3 + C3, 0.f);
        h0 = split2(v0, v1, l0);
        h1 = split2(v2, v3, l1);
    }
    size_t o = (size_t)r * 256 + q4;
    *(uint2*)&g_a_hi[o] = make_uint2(h0, h1);
    *(uint2*)&g_a_lo[o] = make_uint2(l0, l1);
}

// ---------------- mma.sync GEMM with 2-stage cp.async pipeline -------------------
#define RS 40
#define PLN (128 * RS * 2)             // 10240 B per plane
__global__ void __launch_bounds__(256) k_gemm_mma(
        const float* __restrict__ b0, const float* __restrict__ b1,
        const float* __restrict__ b2, const float* __restrict__ b3,
        float* __restrict__ Cout) {
    extern __shared__ __align__(16) char dsm[];
    uint32_t sb = s2u(dsm);
    int tid = threadIdx.x;
    int wid = tid >> 5, lane = tid & 31;
    int bx = blockIdx.x;              // 0..7 -> grp*2 + half
    int by = blockIdx.y;
    int grp = bx >> 1, half = bx & 1;
    const float* bb = (grp == 0) ? b0 : (grp == 1) ? b1 : (grp == 2) ? b2 : b3;
    int warp_m = wid & 1;             // 2 x 64 rows
    int warp_n = wid >> 1;            // 4 x 32 cols

    const unsigned short* gAh = g_a_hi + (size_t)by * 128 * 256;
    const unsigned short* gAl = g_a_lo + (size_t)by * 128 * 256;
    const unsigned short* gBh = g_wt_hi + (size_t)bx * 128 * 256;
    const unsigned short* gBl = g_wt_lo + (size_t)bx * 128 * 256;

    int arow = 64 * warp_m + (lane & 15);
    int akb  = (lane >> 4) << 3;
    int brow = 32 * warp_n + (lane & 7) + ((lane >> 4) << 3);
    int bkb  = ((lane >> 3) & 1) << 3;
    int grow0 = tid >> 2, gq0 = (tid & 3) * 8;
    int grow1 = (tid + 256) >> 2, gq1 = ((tid + 256) & 3) * 8;

    float acc[4][4][4];
#pragma unroll
    for (int mi = 0; mi < 4; mi++)
#pragma unroll
        for (int ni = 0; ni < 4; ni++)
#pragma unroll
            for (int r = 0; r < 4; r++) acc[mi][ni][r] = 0.f;

#define ISSUE(stage, cc) do { \
        int k0_ = (cc) * 32; \
        uint32_t base_ = sb + (stage) * 4 * PLN; \
        uint32_t d0_ = base_ + (uint32_t)(grow0 * RS + gq0) * 2; \
        uint32_t d1_ = base_ + (uint32_t)(grow1 * RS + gq1) * 2; \
        size_t s0_ = (size_t)grow0 * 256 + k0_ + gq0; \
        size_t s1_ = (size_t)grow1 * 256 + k0_ + gq1; \
        CP16(d0_,           gAh + s0_); CP16(d1_,           gAh + s1_); \
        CP16(d0_ + PLN,     gAl + s0_); CP16(d1_ + PLN,     gAl + s1_); \
        CP16(d0_ + 2 * PLN, gBh + s0_); CP16(d1_ + 2 * PLN, gBh + s1_); \
        CP16(d0_ + 3 * PLN, gBl + s0_); CP16(d1_ + 3 * PLN, gBl + s1_); \
        asm volatile("cp.async.commit_group;" ::: "memory"); \
    } while (0)

    ISSUE(0, 0);
    for (int c = 0; c < 8; c++) {
        if (c + 1 < 8) {
            ISSUE((c + 1) & 1, c + 1);
            asm volatile("cp.async.wait_group 1;" ::: "memory");
        } else {
            asm volatile("cp.async.wait_group 0;" ::: "memory");
        }
        __syncthreads();
        uint32_t aAh = sb + (c & 1) * 4 * PLN;
        uint32_t aAl = aAh + PLN, aBh = aAh + 2 * PLN, aBl = aAh + 3 * PLN;
#pragma unroll
        for (int ks = 0; ks < 2; ks++) {
            int kk = ks * 16;
            uint32_t ah[4][4], al[4][4];
#pragma unroll
            for (int mi = 0; mi < 4; mi++) {
                uint32_t ad = aAh + (uint32_t)(((arow + 16 * mi) * RS + kk + akb) * 2);
                LDSM4(ah[mi], ad);
            }
            uint32_t bh[4][2];
#pragma unroll
            for (int nb = 0; nb < 2; nb++) {
                uint32_t r4[4];
                uint32_t ad = aBh + (uint32_t)(((brow + 16 * nb) * RS + kk + bkb) * 2);
                LDSM4(r4, ad);
                bh[2 * nb][0] = r4[0]; bh[2 * nb][1] = r4[1];
                bh[2 * nb + 1][0] = r4[2]; bh[2 * nb + 1][1] = r4[3];
            }
#pragma unroll
            for (int mi = 0; mi < 4; mi++)
#pragma unroll
                for (int ni = 0; ni < 4; ni++) MMA(acc[mi][ni], ah[mi], bh[ni]);
            uint32_t bl_[4][2];
#pragma unroll
            for (int nb = 0; nb < 2; nb++) {
                uint32_t r4[4];
                uint32_t ad = aBl + (uint32_t)(((brow + 16 * nb) * RS + kk + bkb) * 2);
                LDSM4(r4, ad);
                bl_[2 * nb][0] = r4[0]; bl_[2 * nb][1] = r4[1];
                bl_[2 * nb + 1][0] = r4[2]; bl_[2 * nb + 1][1] = r4[3];
            }
#pragma unroll
            for (int mi = 0; mi < 4; mi++)
#pragma unroll
                for (int ni = 0; ni < 4; ni++) MMA(acc[mi][ni], ah[mi], bl_[ni]);
#pragma unroll
            for (int mi = 0; mi < 4; mi++) {
                uint32_t ad = aAl + (uint32_t)(((arow + 16 * mi) * RS + kk + akb) * 2);
                LDSM4(al[mi], ad);
            }
#pragma unroll
            for (int mi = 0; mi < 4; mi++)
#pragma unroll
                for (int ni = 0; ni < 4; ni++) MMA(acc[mi][ni], al[mi], bh[ni]);
        }
        __syncthreads();
    }

    float* outp = Cout + (size_t)grp * NN * 256;
    int rbase = by * 128 + 64 * warp_m + (lane >> 2);
    int cfrag = (lane & 3) * 2;
#pragma unroll
    for (int ni = 0; ni < 4; ni++) {
        int col = 32 * warp_n + 8 * ni + cfrag;
        float bx0 = bb[half * 128 + col], bx1 = bb[half * 128 + col + 1];
#pragma unroll
        for (int mi = 0; mi < 4; mi++) {
            int r0 = rbase + 16 * mi;
            if (r0 < NN)
                *(float2*)&outp[(size_t)r0 * 256 + half * 128 + col] =
                    make_float2(acc[mi][ni][0] + bx0, acc[mi][ni][1] + bx1);
            if (r0 + 8 < NN)
                *(float2*)&outp[(size_t)(r0 + 8) * 256 + half * 128 + col] =
                    make_float2(acc[mi][ni][2] + bx0, acc[mi][ni][3] + bx1);
        }
    }
}

// ---------------- mu/ls conv: ONLINE softmax, 2-edge unroll, head-mean -----------
__global__ void k_node2h(const float* __restrict__ xl, const float* __restrict__ xr,
                         const float* __restrict__ We, const float* __restrict__ att,
                         const float* __restrict__ bias, float* __restrict__ out) {
    int n = (blockIdx.x * blockDim.x + threadIdx.x) >> 5;
    if (n >= NN) return;
    int lane = threadIdx.x & 31;
    int cb = lane * 8;
    int js = g_rowptr[n], je = g_rowptr[n + 1];
    const float4* pxr = (const float4*)&xr[(long long)n * 256 + cb];
    float4 xrA = pxr[0], xrB = pxr[1];
    float4 weA = *(const float4*)&We[cb],  weB = *(const float4*)&We[cb + 4];
    float4 atA = *(const float4*)&att[cb], atB = *(const float4*)&att[cb + 4];
    float m = NEG_INF, den = 0.f;
    float acc[8] = {0, 0, 0, 0, 0, 0, 0, 0};
    int j = js;
    for (; j + 1 < je; j += 2) {
        int s0 = g_srcs[j], s1 = g_srcs[j + 1];
        float w0 = g_ews[j], w1 = g_ews[j + 1];
        const float4* p0_ = (const float4*)&xl[(long long)s0 * 256 + cb];
        const float4* p1_ = (const float4*)&xl[(long long)s1 * 256 + cb];
        float4 xa0 = p0_[0], xb0 = p0_[1];
        float4 xa1 = p1_[0], xb1 = p1_[1];
        float t0 = edge_logit(xa0, xb0, w0, xrA, xrB, weA, weB, atA, atB);
        float t1 = edge_logit(xa1, xb1, w1, xrA, xrB, weA, weB, atA, atB);
        float pa = hsum(t0), pb = hsum(t1);
        float nm = fmaxf(m, fmaxf(pa, pb));
        float sc = __expf(m - nm);
        float wa = __expf(pa - nm), wb = __expf(pb - nm);
        m = nm;
        den = den * sc + wa + wb;
        acc[0] = acc[0] * sc + wa * xa0.x + wb * xa1.x;
        acc[1] = acc[1] * sc + wa * xa0.y + wb * xa1.y;
        acc[2] = acc[2] * sc + wa * xa0.z + wb * xa1.z;
        acc[3] = acc[3] * sc + wa * xa0.w + wb * xa1.w;
        acc[4] = acc[4] * sc + wa * xb0.x + wb * xb1.x;
        acc[5] = acc[5] * sc + wa * xb0.y + wb * xb1.y;
        acc[6] = acc[6] * sc + wa * xb0.z + wb * xb1.z;
        acc[7] = acc[7] * sc + wa * xb0.w + wb * xb1.w;
    }
    if (j < je) {
        int s0 = g_srcs[j]; float w0 = g_ews[j];
        const float4* p0_ = (const float4*)&xl[(long long)s0 * 256 + cb];
        float4 xa0 = p0_[0], xb0 = p0_[1];
        float t0 = edge_logit(xa0, xb0, w0, xrA, xrB, weA, weB, atA, atB);
        float pa = hsum(t0);
        float nm = fmaxf(m, pa);
        float sc = __expf(m - nm);
        float wa = __expf(pa - nm);
        m = nm;
        den = den * sc + wa;
        acc[0] = acc[0] * sc + wa * xa0.x; acc[1] = acc[1] * sc + wa * xa0.y;
        acc[2] = acc[2] * sc + wa * xa0.z; acc[3] = acc[3] * sc + wa * xa0.w;
        acc[4] = acc[4] * sc + wa * xb0.x; acc[5] = acc[5] * sc + wa * xb0.y;
        acc[6] = acc[6] * sc + wa * xb0.z; acc[7] = acc[7] * sc + wa * xb0.w;
    }
    float inv = 1.f / (den + 1e-16f);
    float r8[8];
#pragma unroll
    for (int k = 0; k < 8; k++) {
        float mine = acc[k] * inv;
        float peer = __shfl_xor_sync(0xffffffffu, mine, 16);
        r8[k] = 0.5f * (mine + peer);
    }
    if (lane < 16) {
        float4 bA = *(const float4*)&bias[cb], bB = *(const float4*)&bias[cb + 4];
        float4* po = (float4*)&out[(long long)n * 128 + cb];
        po[0] = make_float4(r8[0] + bA.x, r8[1] + bA.y, r8[2] + bA.z, r8[3] + bA.w);
        po[1] = make_float4(r8[4] + bB.x, r8[5] + bB.y, r8[6] + bB.z, r8[7] + bB.w);
    }
}

// ---------------- launch ----------------
extern "C" void kernel_launch(void* const* d_in, const int* in_sizes, int n_in,
                              void* d_out, int out_size) {
    const float* h       = (const float*)d_in[0];
    const int*   ei      = (const int*)d_in[1];
    const float* ew      = (const float*)d_in[2];
    const float* bn0_g   = (const float*)d_in[3];
    const float* bn0_b   = (const float*)d_in[4];
    const float* bn1_g   = (const float*)d_in[5];
    const float* bn1_b   = (const float*)d_in[6];
    const float* c1_Wl   = (const float*)d_in[7];
    const float* c1_bl   = (const float*)d_in[8];
    const float* c1_Wr   = (const float*)d_in[9];
    const float* c1_br   = (const float*)d_in[10];
    const float* c1_We   = (const float*)d_in[11];
    const float* c1_att  = (const float*)d_in[12];
    const float* c1_bias = (const float*)d_in[13];
    const float* mu_Wl   = (const float*)d_in[14];
    const float* mu_bl   = (const float*)d_in[15];
    const float* mu_Wr   = (const float*)d_in[16];
    const float* mu_br   = (const float*)d_in[17];
    const float* mu_We   = (const float*)d_in[18];
    const float* mu_att  = (const float*)d_in[19];
    const float* mu_bias = (const float*)d_in[20];
    const float* ls_Wl   = (const float*)d_in[21];
    const float* ls_bl   = (const float*)d_in[22];
    const float* ls_Wr   = (const float*)d_in[23];
    const float* ls_br   = (const float*)d_in[24];
    const float* ls_We   = (const float*)d_in[25];
    const float* ls_att  = (const float*)d_in[26];
    const float* ls_bias = (const float*)d_in[27];
    float* out = (float*)d_out;

    const int* src = ei;
    const int* dst = ei + NE;

    float* x4;
    cudaGetSymbolAddress((void**)&x4, g_x4);

    const int TB = 256;
    int eb = (NE + TB - 1) / TB;
    int nodeWarpBlocks = (NN * 32 + TB - 1) / TB;
    int scanBlocks = (NN + 1023) / 1024;   // 49
    const int GEMM_SMEM = 8 * PLN;         // 81920 B

    cudaFuncSetAttribute(k_gemm_mma, cudaFuncAttributeMaxDynamicSharedMemorySize, GEMM_SMEM);

    // fork: side stream runs the CSR chain concurrently with prepw+bn0+lin5
    cudaStream_t s2;
    cudaStreamCreateWithFlags(&s2, cudaStreamNonBlocking);
    cudaEvent_t ef, ej;
    cudaEventCreateWithFlags(&ef, cudaEventDisableTiming);
    cudaEventCreateWithFlags(&ej, cudaEventDisableTiming);

    cudaEventRecord(ef, 0);
    cudaStreamWaitEvent(s2, ef, 0);

    // side stream: CSR build
    k_hist<<<eb, TB, 0, s2>>>(dst);
    k_scan1<<<scanBlocks, 1024, 0, s2>>>();
    k_scan2<<<1, 64, 0, s2>>>(scanBlocks);
    k_scan3<<<scanBlocks, 1024, 0, s2>>>();
    k_scatter<<<eb, TB, 0, s2>>>(src, dst, ew);
    cudaEventRecord(ej, s2);

    // main stream: weight prep + BN0 + conv1 linears
    k_prepw<<<(1024 * 64 + TB - 1) / TB, TB>>>(mu_Wl, mu_Wr, ls_Wl, ls_Wr);
    k_bn0_reduce<<<64, TB>>>(h);
    k_lin5<<<(NN + 31) / 32, TB>>>(h, bn0_g, bn0_b, c1_Wl, c1_bl, c1_Wr, c1_br);

    // join
    cudaStreamWaitEvent(0, ej, 0);

    k_node1<<<nodeWarpBlocks, TB>>>(c1_We, c1_att, c1_bias);

    k_bn1_reduce<<<512, TB>>>();

    k_prepa<<<(NBLK * 128 * 64 + TB - 1) / TB, TB>>>(bn1_g, bn1_b);

    dim3 gg(8, NBLK);
    k_gemm_mma<<<gg, 256, GEMM_SMEM>>>(mu_bl, mu_br, ls_bl, ls_br, x4);

    k_node2h<<<nodeWarpBlocks, TB>>>(x4, x4 + (long long)NN * 256,
                                     mu_We, mu_att, mu_bias, out);
    k_node2h<<<nodeWarpBlocks, TB>>>(x4 + 2ll * NN * 256, x4 + 3ll * NN * 256,
                                     ls_We, ls_att, ls_bias,
                                     out + (long long)NN * 128);
}